// round 1
// baseline (speedup 1.0000x reference)
#include <cuda_runtime.h>
#include <math.h>

// ---------------- problem constants (all static) ----------------
constexpr int B_    = 8;
constexpr int H0    = 56;
constexpr int W0    = 56;
constexpr int N0    = H0 * W0;        // 3136
constexpr int DIM   = 256;
constexpr int HEADS = 8;
constexpr int HD    = 32;
constexpr int LOCAL = 9;
constexpr int PW    = 7;
constexpr int PLEN  = 49;
constexpr int LTAB  = 4096;
constexpr int MROWS = B_ * N0;        // 25088
constexpr float NEGV = -1e9f;

// ---------------- scratch (device globals; no allocs) ----------------
__device__ float g_qs[B_*HEADS*N0*HD];   // q_s           (b,h,n,d)
__device__ float g_qn[B_*HEADS*N0*HD];   // raw q -> q_norm
__device__ float g_k [B_*HEADS*N0*HD];   // raw k -> k_norm
__device__ float g_v [B_*HEADS*N0*HD];   // v_loc
__device__ float g_xs[B_*N0*DIM];        // gelu(x@sr_w+sr_b)
__device__ float g_xp[B_*PLEN*DIM];      // pooled + LN
__device__ float g_kp[B_*HEADS*PLEN*HD]; // k_pool (normalized)
__device__ float g_vp[B_*HEADS*PLEN*HD]; // v_pool
__device__ float g_tab[LTAB*HEADS];      // cpb table
__device__ float g_xo[B_*N0*DIM];        // x_local + x_pool  (b,n, h*32+d)

// ---------------- SGEMM 128x64x16, 256 threads, 8x4/thread ----------------
// MODE 0: A = x, B = [q_w | kv_w | sr_w], scatter epilogue
// MODE 1: A = g_xo, B = proj_w, out = d_out (+proj_b)
template<int MODE>
__global__ __launch_bounds__(256)
void gemm_kernel(const float* __restrict__ A,
                 const float* __restrict__ Wq, const float* __restrict__ Wkv,
                 const float* __restrict__ Wsr,
                 const float* __restrict__ bq, const float* __restrict__ bkv,
                 const float* __restrict__ bsr,
                 float* __restrict__ Out)
{
    constexpr int BM = 128, BN = 64, BK = 16, TM = 8, TN = 4;
    __shared__ float As[BK][BM];
    __shared__ float Bs[BK][BN];

    const float* Aptr = (MODE == 0) ? A : g_xo;

    int tid  = threadIdx.x;
    int m0   = blockIdx.x * BM;
    int col0 = blockIdx.y * BN;

    const float* Bsrc; int ldb, cb;
    if (MODE == 0) {
        if (col0 < 256)      { Bsrc = Wq;  ldb = 256; cb = col0;       }
        else if (col0 < 768) { Bsrc = Wkv; ldb = 512; cb = col0 - 256; }
        else                 { Bsrc = Wsr; ldb = 256; cb = col0 - 768; }
    } else                   { Bsrc = Wq;  ldb = 256; cb = col0;       }

    int arow = tid >> 2;           // 0..63
    int acol = (tid & 3) * 4;      // 0,4,8,12
    int brow = tid >> 4;           // 0..15
    int bcol = (tid & 15) * 4;

    int ty = tid >> 4;             // 0..15 -> rows
    int tx = tid & 15;             // 0..15 -> cols

    float acc[TM][TN];
#pragma unroll
    for (int i = 0; i < TM; i++)
#pragma unroll
        for (int j = 0; j < TN; j++) acc[i][j] = 0.f;

    for (int k0 = 0; k0 < DIM; k0 += BK) {
#pragma unroll
        for (int rr = 0; rr < 2; rr++) {
            int r = arow + rr * 64;
            float4 a4 = *reinterpret_cast<const float4*>(&Aptr[(size_t)(m0 + r) * DIM + k0 + acol]);
            As[acol + 0][r] = a4.x; As[acol + 1][r] = a4.y;
            As[acol + 2][r] = a4.z; As[acol + 3][r] = a4.w;
        }
        float4 b4 = *reinterpret_cast<const float4*>(&Bsrc[(size_t)(k0 + brow) * ldb + cb + bcol]);
        *reinterpret_cast<float4*>(&Bs[brow][bcol]) = b4;
        __syncthreads();
#pragma unroll
        for (int k = 0; k < BK; k++) {
            float ra[TM], rb[TN];
#pragma unroll
            for (int i = 0; i < TM; i++) ra[i] = As[k][ty * TM + i];
#pragma unroll
            for (int j = 0; j < TN; j++) rb[j] = Bs[k][tx * TN + j];
#pragma unroll
            for (int i = 0; i < TM; i++)
#pragma unroll
                for (int j = 0; j < TN; j++) acc[i][j] += ra[i] * rb[j];
        }
        __syncthreads();
    }

#pragma unroll
    for (int i = 0; i < TM; i++) {
        int r = m0 + ty * TM + i;
        int b = r / N0, n = r % N0;
#pragma unroll
        for (int j = 0; j < TN; j++) {
            int c = col0 + tx * TN + j;
            float v = acc[i][j];
            if (MODE == 0) {
                if (c < 256) {
                    v += bq[c];
                    g_qn[(((size_t)(b * HEADS + (c >> 5))) * N0 + n) * HD + (c & 31)] = v;
                } else if (c < 768) {
                    int cc = c - 256;
                    v += bkv[cc];
                    if (cc < 256)
                        g_k[(((size_t)(b * HEADS + (cc >> 5))) * N0 + n) * HD + (cc & 31)] = v;
                    else {
                        int c2 = cc - 256;
                        g_v[(((size_t)(b * HEADS + (c2 >> 5))) * N0 + n) * HD + (c2 & 31)] = v;
                    }
                } else {
                    int cc = c - 768;
                    v += bsr[cc];
                    float gl = 0.5f * v * (1.f + erff(v * 0.70710678118654752f));
                    g_xs[((size_t)(b * N0 + n)) * DIM + cc] = gl;
                }
            } else {
                Out[(size_t)r * DIM + c] = v + bq[c];
            }
        }
    }
}

// ---------------- normalize q (-> q_norm, q_s) and k, warp per row ----------------
__global__ void norm_kernel(const float* __restrict__ qe,
                            const float* __restrict__ temp,
                            const float* __restrict__ sls)
{
    int gw   = (blockIdx.x * blockDim.x + threadIdx.x) >> 5;
    int lane = threadIdx.x & 31;
    const int total = B_ * HEADS * N0;
    bool isq = gw < total;
    int idx  = isq ? gw : gw - total;
    if (idx >= total) return;

    float* buf = isq ? g_qn : g_k;
    float v = buf[(size_t)idx * HD + lane];
    float ss = v * v;
#pragma unroll
    for (int o = 16; o; o >>= 1) ss += __shfl_xor_sync(0xffffffffu, ss, o);
    float d  = fmaxf(sqrtf(ss), 1e-12f);
    float vn = v / d;
    buf[(size_t)idx * HD + lane] = vn;
    if (isq) {
        int h = (idx / N0) % HEADS;
        float sp = log1pf(expf(temp[h]));
        g_qs[(size_t)idx * HD + lane] = (vn + qe[h * HD + lane]) * sp * sls[0];
    }
}

// ---------------- 8x8 avg pool + layernorm, block per (b, p) ----------------
__global__ void pool_ln_kernel(const float* __restrict__ gamma,
                               const float* __restrict__ beta)
{
    __shared__ float red[256];
    int bp = blockIdx.x;
    int b = bp / PLEN, p = bp % PLEN;
    int pi = p / PW, pj = p % PW;
    int c = threadIdx.x;

    float s = 0.f;
#pragma unroll
    for (int r = 0; r < 8; r++)
#pragma unroll
        for (int col = 0; col < 8; col++) {
            int n = (pi * 8 + r) * W0 + (pj * 8 + col);
            s += g_xs[((size_t)(b * N0 + n)) * DIM + c];
        }
    s *= (1.f / 64.f);

    red[c] = s; __syncthreads();
    for (int o = 128; o > 0; o >>= 1) { if (c < o) red[c] += red[c + o]; __syncthreads(); }
    float mean = red[0] * (1.f / 256.f);
    __syncthreads();
    float dv = s - mean;
    red[c] = dv * dv; __syncthreads();
    for (int o = 128; o > 0; o >>= 1) { if (c < o) red[c] += red[c + o]; __syncthreads(); }
    float var = red[0] * (1.f / 256.f);
    g_xp[(size_t)bp * DIM + c] = dv * rsqrtf(var + 1e-5f) * gamma[c] + beta[c];
}

// ---------------- kvp: xp(392x256) @ kv_w(256x512), k_pool normalized ----------------
__global__ void kvp_kernel(const float* __restrict__ kv_w,
                           const float* __restrict__ kv_b)
{
    __shared__ float xr[DIM];
    int bp = blockIdx.x;
    int tid = threadIdx.x, lane = tid & 31, wp = tid >> 5; // wp == head for k cols
    xr[tid] = g_xp[(size_t)bp * DIM + tid];
    __syncthreads();

    float ak = kv_b[tid], av = kv_b[tid + 256];
    for (int kk = 0; kk < DIM; kk++) {
        float xv = xr[kk];
        ak += xv * kv_w[(size_t)kk * 512 + tid];
        av += xv * kv_w[(size_t)kk * 512 + 256 + tid];
    }
    float ss = ak * ak;
#pragma unroll
    for (int o = 16; o; o >>= 1) ss += __shfl_xor_sync(0xffffffffu, ss, o);
    float kn = ak / fmaxf(sqrtf(ss), 1e-12f);

    int b = bp / PLEN, p = bp % PLEN;
    g_kp[(((size_t)(b * HEADS + wp)) * PLEN + p) * HD + lane] = kn;
    g_vp[(((size_t)(b * HEADS + wp)) * PLEN + p) * HD + lane] = av;
}

// ---------------- cpb MLP: tab[t,h], warp per table row ----------------
__global__ void cpb_kernel(const float* __restrict__ rct,
                           const float* __restrict__ w1, const float* __restrict__ b1,
                           const float* __restrict__ w2, const float* __restrict__ b2)
{
    int gw = (blockIdx.x * blockDim.x + threadIdx.x) >> 5;
    int lane = threadIdx.x & 31;
    if (gw >= LTAB) return;
    float r0 = rct[gw * 2], r1 = rct[gw * 2 + 1];
    float acc[HEADS];
#pragma unroll
    for (int h = 0; h < HEADS; h++) acc[h] = 0.f;
    for (int j = lane; j < 512; j += 32) {
        float hv = fmaxf(r0 * w1[j] + r1 * w1[512 + j] + b1[j], 0.f);
#pragma unroll
        for (int h = 0; h < HEADS; h++) acc[h] += hv * w2[j * HEADS + h];
    }
#pragma unroll
    for (int h = 0; h < HEADS; h++)
#pragma unroll
        for (int o = 16; o; o >>= 1) acc[h] += __shfl_xor_sync(0xffffffffu, acc[h], o);
    if (lane == 0) {
#pragma unroll
        for (int h = 0; h < HEADS; h++) g_tab[gw * HEADS + h] = acc[h] + b2[h];
    }
}

// ---------------- fused attention: warp per pixel ----------------
__global__ __launch_bounds__(256)
void attn_kernel(const int* __restrict__ rpi,
                 const float* __restrict__ rpb_local,
                 const float* __restrict__ ltok,
                 const float* __restrict__ lbias)
{
    __shared__ float kp_sh[PLEN * 33];
    __shared__ float vp_sh[PLEN * 33];
    __shared__ float lt_sh[HD * LOCAL];    // [d*9 + l]
    __shared__ float rpb_sh[LOCAL], lb_sh[LOCAL];
    __shared__ float kw_sh[8][LOCAL * 33];
    __shared__ float vw_sh[8][LOCAL * 33];

    int bh = blockIdx.x;
    int b = bh / HEADS, h = bh % HEADS;
    int tid = threadIdx.x, warp = tid >> 5, lane = tid & 31;

    const float* kpsrc = g_kp + (size_t)bh * PLEN * HD;
    const float* vpsrc = g_vp + (size_t)bh * PLEN * HD;
    for (int i = tid; i < PLEN * HD; i += 256) {
        int m = i >> 5, d = i & 31;
        kp_sh[m * 33 + d] = kpsrc[i];
        vp_sh[m * 33 + d] = vpsrc[i];
    }
    for (int i = tid; i < HD * LOCAL; i += 256) lt_sh[i] = ltok[h * HD * LOCAL + i];
    if (tid < LOCAL) { rpb_sh[tid] = rpb_local[h * LOCAL + tid]; lb_sh[tid] = lbias[h * LOCAL + tid]; }
    __syncthreads();

    const float* qs_base = g_qs + (size_t)bh * N0 * HD;
    const float* qn_base = g_qn + (size_t)bh * N0 * HD;
    const float* k_base  = g_k  + (size_t)bh * N0 * HD;
    const float* v_base  = g_v  + (size_t)bh * N0 * HD;

    int li  = (lane < LOCAL) ? lane : 0;
    int mi1 = (lane < 17) ? lane + 32 : 0;

    for (int it = 0; it < 14; it++) {
        int n = blockIdx.y * 112 + warp * 14 + it;
        int pi = n / W0, pj = n % W0;
        float qs = qs_base[(size_t)n * HD + lane];
        float qn = qn_base[(size_t)n * HD + lane];

        unsigned vm = 0;
#pragma unroll
        for (int l = 0; l < LOCAL; l++) {
            int di = l / 3 - 1, dj = l % 3 - 1;
            int ii = pi + di, jj = pj + dj;
            bool ok = (ii >= 0 && ii < H0 && jj >= 0 && jj < W0);
            int nn = ok ? ii * W0 + jj : 0;
            kw_sh[warp][l * 33 + lane] = k_base[(size_t)nn * HD + lane];
            vw_sh[warp][l * 33 + lane] = ok ? v_base[(size_t)nn * HD + lane] : 0.f;
            if (ok) vm |= (1u << l);
        }
        __syncwarp();

        float pb0 = g_tab[rpi[n * PLEN + lane] * HEADS + h];
        float pb1 = (lane < 17) ? g_tab[rpi[n * PLEN + 32 + lane] * HEADS + h] : 0.f;

        float s9 = 0.f, sp0 = 0.f, sp1 = 0.f, tl = 0.f;
#pragma unroll
        for (int d = 0; d < HD; d++) {
            float qd  = __shfl_sync(0xffffffffu, qs, d);
            float qnd = __shfl_sync(0xffffffffu, qn, d);
            s9  += qd  * kw_sh[warp][li * 33 + d];
            sp0 += qd  * kp_sh[lane * 33 + d];
            sp1 += qd  * kp_sh[mi1 * 33 + d];
            tl  += qnd * lt_sh[d * LOCAL + li];
        }

        s9  = (lane < LOCAL && ((vm >> lane) & 1)) ? (s9 + rpb_sh[lane]) : NEGV;
        sp0 += pb0;
        sp1 = (lane < 17) ? (sp1 + pb1) : NEGV;

        float mx = fmaxf(s9, fmaxf(sp0, sp1));
#pragma unroll
        for (int o = 16; o; o >>= 1) mx = fmaxf(mx, __shfl_xor_sync(0xffffffffu, mx, o));
        float e9 = expf(s9 - mx), e0 = expf(sp0 - mx), e1 = expf(sp1 - mx);
        float sum = e9 + e0 + e1;
#pragma unroll
        for (int o = 16; o; o >>= 1) sum += __shfl_xor_sync(0xffffffffu, sum, o);
        float inv = 1.f / sum;

        float a9 = (lane < LOCAL) ? (e9 * inv + tl + lb_sh[lane]) : 0.f;
        float a0 = e0 * inv;
        float a1 = e1 * inv;   // lanes >= 17: e1 == 0

        float out = 0.f;
#pragma unroll
        for (int l = 0; l < LOCAL; l++)
            out += __shfl_sync(0xffffffffu, a9, l) * vw_sh[warp][l * 33 + lane];
#pragma unroll
        for (int m = 0; m < 32; m++)
            out += __shfl_sync(0xffffffffu, a0, m) * vp_sh[m * 33 + lane];
#pragma unroll
        for (int m = 0; m < 17; m++)
            out += __shfl_sync(0xffffffffu, a1, m) * vp_sh[(m + 32) * 33 + lane];

        g_xo[((size_t)(b * N0 + n)) * DIM + h * HD + lane] = out;
        __syncwarp();
    }
}

// ---------------- launch ----------------
extern "C" void kernel_launch(void* const* d_in, const int* in_sizes, int n_in,
                              void* d_out, int out_size)
{
    const float* x      = (const float*)d_in[0];
    const float* sls    = (const float*)d_in[1];
    const float* rct    = (const float*)d_in[2];
    const float* q_w    = (const float*)d_in[3];
    const float* q_b    = (const float*)d_in[4];
    const float* qe     = (const float*)d_in[5];
    const float* temp   = (const float*)d_in[6];
    const float* kv_w   = (const float*)d_in[7];
    const float* kv_b   = (const float*)d_in[8];
    const float* sr_w   = (const float*)d_in[9];
    const float* sr_b   = (const float*)d_in[10];
    const float* norm_g = (const float*)d_in[11];
    const float* norm_b = (const float*)d_in[12];
    const float* fc1_w  = (const float*)d_in[13];
    const float* fc1_b  = (const float*)d_in[14];
    const float* fc2_w  = (const float*)d_in[15];
    const float* fc2_b  = (const float*)d_in[16];
    const float* rpb    = (const float*)d_in[17];
    const float* lt     = (const float*)d_in[18];
    const float* lb     = (const float*)d_in[19];
    const float* proj_w = (const float*)d_in[20];
    const float* proj_b = (const float*)d_in[21];
    const int*   rpi    = (const int*)d_in[22];
    float* out = (float*)d_out;

    // 1) fused x @ [q_w | kv_w | sr_w] with scatter/gelu epilogue
    dim3 g1(MROWS / 128, 1024 / 64);
    gemm_kernel<0><<<g1, 256>>>(x, q_w, kv_w, sr_w, q_b, kv_b, sr_b, nullptr);

    // 2) l2-normalize q (-> q_norm, q_s) and k
    int warps = 2 * B_ * HEADS * N0;
    norm_kernel<<<warps / 8, 256>>>(qe, temp, sls);

    // 3) pool + layernorm
    pool_ln_kernel<<<B_ * PLEN, 256>>>(norm_g, norm_b);

    // 4) kvp mini-GEMM (k_pool normalized in-epilogue)
    kvp_kernel<<<B_ * PLEN, 256>>>(kv_w, kv_b);

    // 5) cpb table MLP
    cpb_kernel<<<LTAB / 8, 256>>>(rct, fc1_w, fc1_b, fc2_w, fc2_b);

    // 6) fused attention
    attn_kernel<<<dim3(B_ * HEADS, 28), 256>>>(rpi, rpb, lt, lb);

    // 7) proj GEMM -> d_out
    dim3 g7(MROWS / 128, 256 / 64);
    gemm_kernel<1><<<g7, 256>>>(nullptr, proj_w, nullptr, nullptr, proj_b, nullptr, nullptr, out);
}

// round 2
// speedup vs baseline: 1.0843x; 1.0843x over previous
#include <cuda_runtime.h>
#include <cuda_bf16.h>
#include <math.h>
#include <stdint.h>

// ---------------- problem constants (all static) ----------------
constexpr int B_    = 8;
constexpr int H0    = 56;
constexpr int W0    = 56;
constexpr int N0    = H0 * W0;        // 3136
constexpr int DIM   = 256;
constexpr int HEADS = 8;
constexpr int HD    = 32;
constexpr int LOCAL = 9;
constexpr int PW    = 7;
constexpr int PLEN  = 49;
constexpr int LTAB  = 4096;
constexpr int MROWS = B_ * N0;        // 25088
constexpr float NEGV = -1e9f;

// ---------------- scratch (device globals; no allocs) ----------------
__device__ float g_qs[B_*HEADS*N0*HD];   // q_s           (b,h,n,d)
__device__ float g_qn[B_*HEADS*N0*HD];   // raw q -> q_norm
__device__ float g_k [B_*HEADS*N0*HD];   // raw k -> k_norm
__device__ float g_v [B_*HEADS*N0*HD];   // v_loc
__device__ float g_xs[B_*N0*DIM];        // gelu(x@sr_w+sr_b)
__device__ float g_xp[B_*PLEN*DIM];      // pooled + LN
__device__ float g_kp[B_*HEADS*PLEN*HD]; // k_pool (normalized)
__device__ float g_vp[B_*HEADS*PLEN*HD]; // v_pool
__device__ float g_tab[LTAB*HEADS];      // cpb table
__device__ float g_xo[B_*N0*DIM];        // x_local + x_pool  (b,n, h*32+d)

// ---------------- bf16 split helpers ----------------
__device__ __forceinline__ uint32_t pack_bf2(__nv_bfloat16 x, __nv_bfloat16 y) {
    __nv_bfloat162 t; t.x = x; t.y = y;
    return *reinterpret_cast<uint32_t*>(&t);
}
__device__ __forceinline__ void split2(float x, float y, uint32_t& hi, uint32_t& lo) {
    __nv_bfloat16 xh = __float2bfloat16_rn(x);
    __nv_bfloat16 yh = __float2bfloat16_rn(y);
    float xr = x - __bfloat162float(xh);
    float yr = y - __bfloat162float(yh);
    hi = pack_bf2(xh, yh);
    lo = pack_bf2(__float2bfloat16_rn(xr), __float2bfloat16_rn(yr));
}

#define MMA16816(d, a0,a1,a2,a3, b0,b1) \
    asm volatile("mma.sync.aligned.m16n8k16.row.col.f32.bf16.bf16.f32 " \
        "{%0,%1,%2,%3},{%4,%5,%6,%7},{%8,%9},{%0,%1,%2,%3};" \
        : "+f"(d[0]), "+f"(d[1]), "+f"(d[2]), "+f"(d[3]) \
        : "r"(a0), "r"(a1), "r"(a2), "r"(a3), "r"(b0), "r"(b1))

// ---------------- epilogue scatter for the fused GEMM ----------------
__device__ __forceinline__ void store_epi0(int r, int c, float v,
                                           const float* __restrict__ bq,
                                           const float* __restrict__ bkv,
                                           const float* __restrict__ bsr)
{
    int b = r / N0, n = r % N0;
    if (c < 256) {
        v += bq[c];
        g_qn[(((size_t)(b * HEADS + (c >> 5))) * N0 + n) * HD + (c & 31)] = v;
    } else if (c < 768) {
        int cc = c - 256;
        v += bkv[cc];
        if (cc < 256)
            g_k[(((size_t)(b * HEADS + (cc >> 5))) * N0 + n) * HD + (cc & 31)] = v;
        else {
            int c2 = cc - 256;
            g_v[(((size_t)(b * HEADS + (c2 >> 5))) * N0 + n) * HD + (c2 & 31)] = v;
        }
    } else {
        int cc = c - 768;
        v += bsr[cc];
        float gl = 0.5f * v * (1.f + erff(v * 0.70710678118654752f));
        g_xs[((size_t)(b * N0 + n)) * DIM + cc] = gl;
    }
}

// ---------------- bf16x3 tensor-core GEMM, 128x128x32 tiles ----------------
// MODE 0: A = x [25088,256], B = [q_w | kv_w | sr_w] (1024 cols), scatter epilogue
// MODE 1: A = g_xo,          B = proj_w (256 cols), out = d_out (+proj_b)
template<int MODE>
__global__ __launch_bounds__(256)
void gemm_bf3_kernel(const float* __restrict__ A,
                     const float* __restrict__ Wq, const float* __restrict__ Wkv,
                     const float* __restrict__ Wsr,
                     const float* __restrict__ bq, const float* __restrict__ bkv,
                     const float* __restrict__ bsr,
                     float* __restrict__ Out)
{
    constexpr int LDU = 20;              // u32 row stride (conflict-free)
    __shared__ uint32_t AsH[128][LDU];
    __shared__ uint32_t AsL[128][LDU];
    __shared__ uint32_t BsH[128][LDU];
    __shared__ uint32_t BsL[128][LDU];

    const float* Aptr = (MODE == 0) ? A : g_xo;

    int tid  = threadIdx.x;
    int lane = tid & 31;
    int warp = tid >> 5;
    int wm   = warp >> 2;                // 0..1  (64-row strips)
    int wn   = warp & 3;                 // 0..3  (32-col strips)

    int m0   = blockIdx.x * 128;
    int col0 = blockIdx.y * 128;

    const float* Bsrc; int ldb, cb;
    if (MODE == 0) {
        if (col0 < 256)      { Bsrc = Wq;  ldb = 256; cb = col0;       }
        else if (col0 < 768) { Bsrc = Wkv; ldb = 512; cb = col0 - 256; }
        else                 { Bsrc = Wsr; ldb = 256; cb = col0 - 768; }
    } else                   { Bsrc = Wq;  ldb = 256; cb = col0;       }

    float acc[4][4][4];
#pragma unroll
    for (int i = 0; i < 4; i++)
#pragma unroll
        for (int j = 0; j < 4; j++)
#pragma unroll
            for (int e = 0; e < 4; e++) acc[i][j][e] = 0.f;

    int arow = tid >> 1;                 // 0..127
    int acg  = (tid & 1) * 16;           // col group 0 / 16

    for (int k0 = 0; k0 < DIM; k0 += 32) {
        // --- load A tile [128 x 32] fp32 -> split bf16 pairs ---
#pragma unroll
        for (int j = 0; j < 4; j++) {
            int c = acg + j * 4;
            float4 a4 = *reinterpret_cast<const float4*>(&Aptr[(size_t)(m0 + arow) * DIM + k0 + c]);
            uint32_t h0, l0, h1, l1;
            split2(a4.x, a4.y, h0, l0);
            split2(a4.z, a4.w, h1, l1);
            AsH[arow][(c >> 1) + 0] = h0; AsL[arow][(c >> 1) + 0] = l0;
            AsH[arow][(c >> 1) + 1] = h1; AsL[arow][(c >> 1) + 1] = l1;
        }
        // --- load B tile [32 x 128] -> [n][k] split bf16 pairs ---
#pragma unroll
        for (int i = 0; i < 8; i++) {
            int p  = tid + i * 256;      // 0..2047
            int n  = p & 127;
            int k2 = p >> 7;             // 0..15
            float f0 = Bsrc[(size_t)(k0 + 2 * k2 + 0) * ldb + cb + n];
            float f1 = Bsrc[(size_t)(k0 + 2 * k2 + 1) * ldb + cb + n];
            uint32_t h, l;
            split2(f0, f1, h, l);
            BsH[n][k2] = h; BsL[n][k2] = l;
        }
        __syncthreads();

#pragma unroll
        for (int s = 0; s < 2; s++) {
            int ci = 8 * s + (lane & 3);
            uint32_t aH[4][4], aL[4][4], bH[4][2], bL[4][2];
#pragma unroll
            for (int mt = 0; mt < 4; mt++) {
                int mr = wm * 64 + mt * 16 + (lane >> 2);
                aH[mt][0] = AsH[mr][ci];     aH[mt][1] = AsH[mr + 8][ci];
                aH[mt][2] = AsH[mr][ci + 4]; aH[mt][3] = AsH[mr + 8][ci + 4];
                aL[mt][0] = AsL[mr][ci];     aL[mt][1] = AsL[mr + 8][ci];
                aL[mt][2] = AsL[mr][ci + 4]; aL[mt][3] = AsL[mr + 8][ci + 4];
            }
#pragma unroll
            for (int nt = 0; nt < 4; nt++) {
                int nr = wn * 32 + nt * 8 + (lane >> 2);
                bH[nt][0] = BsH[nr][ci]; bH[nt][1] = BsH[nr][ci + 4];
                bL[nt][0] = BsL[nr][ci]; bL[nt][1] = BsL[nr][ci + 4];
            }
#pragma unroll
            for (int mt = 0; mt < 4; mt++)
#pragma unroll
                for (int nt = 0; nt < 4; nt++) {
                    MMA16816(acc[mt][nt], aH[mt][0], aH[mt][1], aH[mt][2], aH[mt][3],
                             bH[nt][0], bH[nt][1]);
                    MMA16816(acc[mt][nt], aH[mt][0], aH[mt][1], aH[mt][2], aH[mt][3],
                             bL[nt][0], bL[nt][1]);
                    MMA16816(acc[mt][nt], aL[mt][0], aL[mt][1], aL[mt][2], aL[mt][3],
                             bH[nt][0], bH[nt][1]);
                }
        }
        __syncthreads();
    }

    // --- epilogue ---
#pragma unroll
    for (int mt = 0; mt < 4; mt++) {
        int r0 = m0 + wm * 64 + mt * 16 + (lane >> 2);
#pragma unroll
        for (int nt = 0; nt < 4; nt++) {
            int c0 = col0 + wn * 32 + nt * 8 + (lane & 3) * 2;
            if (MODE == 0) {
                store_epi0(r0,     c0,     acc[mt][nt][0], bq, bkv, bsr);
                store_epi0(r0,     c0 + 1, acc[mt][nt][1], bq, bkv, bsr);
                store_epi0(r0 + 8, c0,     acc[mt][nt][2], bq, bkv, bsr);
                store_epi0(r0 + 8, c0 + 1, acc[mt][nt][3], bq, bkv, bsr);
            } else {
                Out[(size_t)r0 * DIM + c0]           = acc[mt][nt][0] + bq[c0];
                Out[(size_t)r0 * DIM + c0 + 1]       = acc[mt][nt][1] + bq[c0 + 1];
                Out[(size_t)(r0 + 8) * DIM + c0]     = acc[mt][nt][2] + bq[c0];
                Out[(size_t)(r0 + 8) * DIM + c0 + 1] = acc[mt][nt][3] + bq[c0 + 1];
            }
        }
    }
}

// ---------------- normalize q (-> q_norm, q_s) and k, warp per row ----------------
__global__ void norm_kernel(const float* __restrict__ qe,
                            const float* __restrict__ temp,
                            const float* __restrict__ sls)
{
    int gw   = (blockIdx.x * blockDim.x + threadIdx.x) >> 5;
    int lane = threadIdx.x & 31;
    const int total = B_ * HEADS * N0;
    bool isq = gw < total;
    int idx  = isq ? gw : gw - total;
    if (idx >= total) return;

    float* buf = isq ? g_qn : g_k;
    float v = buf[(size_t)idx * HD + lane];
    float ss = v * v;
#pragma unroll
    for (int o = 16; o; o >>= 1) ss += __shfl_xor_sync(0xffffffffu, ss, o);
    float d  = fmaxf(sqrtf(ss), 1e-12f);
    float vn = v / d;
    buf[(size_t)idx * HD + lane] = vn;
    if (isq) {
        int h = (idx / N0) % HEADS;
        float sp = log1pf(expf(temp[h]));
        g_qs[(size_t)idx * HD + lane] = (vn + qe[h * HD + lane]) * sp * sls[0];
    }
}

// ---------------- 8x8 avg pool + layernorm, block per (b, p) ----------------
__global__ void pool_ln_kernel(const float* __restrict__ gamma,
                               const float* __restrict__ beta)
{
    __shared__ float red[256];
    int bp = blockIdx.x;
    int b = bp / PLEN, p = bp % PLEN;
    int pi = p / PW, pj = p % PW;
    int c = threadIdx.x;

    float s = 0.f;
#pragma unroll
    for (int r = 0; r < 8; r++)
#pragma unroll
        for (int col = 0; col < 8; col++) {
            int n = (pi * 8 + r) * W0 + (pj * 8 + col);
            s += g_xs[((size_t)(b * N0 + n)) * DIM + c];
        }
    s *= (1.f / 64.f);

    red[c] = s; __syncthreads();
    for (int o = 128; o > 0; o >>= 1) { if (c < o) red[c] += red[c + o]; __syncthreads(); }
    float mean = red[0] * (1.f / 256.f);
    __syncthreads();
    float dv = s - mean;
    red[c] = dv * dv; __syncthreads();
    for (int o = 128; o > 0; o >>= 1) { if (c < o) red[c] += red[c + o]; __syncthreads(); }
    float var = red[0] * (1.f / 256.f);
    g_xp[(size_t)bp * DIM + c] = dv * rsqrtf(var + 1e-5f) * gamma[c] + beta[c];
}

// ---------------- kvp: xp(392x256) @ kv_w(256x512), 8 rows per block ----------------
__global__ __launch_bounds__(256)
void kvp_kernel(const float* __restrict__ kv_w,
                const float* __restrict__ kv_b)
{
    __shared__ float xr[8][DIM];
    int bp0 = blockIdx.x * 8;
    int tid = threadIdx.x, lane = tid & 31, wp = tid >> 5; // wp == head for k cols

#pragma unroll
    for (int i = 0; i < 8; i++)
        xr[i][tid] = g_xp[(size_t)(bp0 + i) * DIM + tid];
    __syncthreads();

    float ak[8], av[8];
    float bk = kv_b[tid], bv = kv_b[tid + 256];
#pragma unroll
    for (int i = 0; i < 8; i++) { ak[i] = bk; av[i] = bv; }

    for (int kk = 0; kk < DIM; kk++) {
        float w0 = kv_w[(size_t)kk * 512 + tid];
        float w1 = kv_w[(size_t)kk * 512 + 256 + tid];
#pragma unroll
        for (int i = 0; i < 8; i++) {
            float xv = xr[i][kk];
            ak[i] = fmaf(xv, w0, ak[i]);
            av[i] = fmaf(xv, w1, av[i]);
        }
    }

#pragma unroll
    for (int i = 0; i < 8; i++) {
        float ss = ak[i] * ak[i];
#pragma unroll
        for (int o = 16; o; o >>= 1) ss += __shfl_xor_sync(0xffffffffu, ss, o);
        float kn = ak[i] / fmaxf(sqrtf(ss), 1e-12f);
        int bp = bp0 + i;
        int b = bp / PLEN, p = bp % PLEN;
        g_kp[(((size_t)(b * HEADS + wp)) * PLEN + p) * HD + lane] = kn;
        g_vp[(((size_t)(b * HEADS + wp)) * PLEN + p) * HD + lane] = av[i];
    }
}

// ---------------- cpb MLP: tab[t,h], warp per table row ----------------
__global__ void cpb_kernel(const float* __restrict__ rct,
                           const float* __restrict__ w1, const float* __restrict__ b1,
                           const float* __restrict__ w2, const float* __restrict__ b2)
{
    int gw = (blockIdx.x * blockDim.x + threadIdx.x) >> 5;
    int lane = threadIdx.x & 31;
    if (gw >= LTAB) return;
    float r0 = rct[gw * 2], r1 = rct[gw * 2 + 1];
    float acc[HEADS];
#pragma unroll
    for (int h = 0; h < HEADS; h++) acc[h] = 0.f;
    for (int j = lane; j < 512; j += 32) {
        float hv = fmaxf(r0 * w1[j] + r1 * w1[512 + j] + b1[j], 0.f);
#pragma unroll
        for (int h = 0; h < HEADS; h++) acc[h] += hv * w2[j * HEADS + h];
    }
#pragma unroll
    for (int h = 0; h < HEADS; h++)
#pragma unroll
        for (int o = 16; o; o >>= 1) acc[h] += __shfl_xor_sync(0xffffffffu, acc[h], o);
    if (lane == 0) {
#pragma unroll
        for (int h = 0; h < HEADS; h++) g_tab[gw * HEADS + h] = acc[h] + b2[h];
    }
}

// ---------------- fused attention: warp per pixel ----------------
__global__ __launch_bounds__(256)
void attn_kernel(const int* __restrict__ rpi,
                 const float* __restrict__ rpb_local,
                 const float* __restrict__ ltok,
                 const float* __restrict__ lbias)
{
    __shared__ float kp_sh[PLEN * 33];
    __shared__ float vp_sh[PLEN * 33];
    __shared__ float lt_sh[HD * LOCAL];    // [d*9 + l]
    __shared__ float rpb_sh[LOCAL], lb_sh[LOCAL];
    __shared__ float kw_sh[8][LOCAL * 33];
    __shared__ float vw_sh[8][LOCAL * 33];

    int bh = blockIdx.x;
    int b = bh / HEADS, h = bh % HEADS;
    int tid = threadIdx.x, warp = tid >> 5, lane = tid & 31;

    const float* kpsrc = g_kp + (size_t)bh * PLEN * HD;
    const float* vpsrc = g_vp + (size_t)bh * PLEN * HD;
    for (int i = tid; i < PLEN * HD; i += 256) {
        int m = i >> 5, d = i & 31;
        kp_sh[m * 33 + d] = kpsrc[i];
        vp_sh[m * 33 + d] = vpsrc[i];
    }
    for (int i = tid; i < HD * LOCAL; i += 256) lt_sh[i] = ltok[h * HD * LOCAL + i];
    if (tid < LOCAL) { rpb_sh[tid] = rpb_local[h * LOCAL + tid]; lb_sh[tid] = lbias[h * LOCAL + tid]; }
    __syncthreads();

    const float* qs_base = g_qs + (size_t)bh * N0 * HD;
    const float* qn_base = g_qn + (size_t)bh * N0 * HD;
    const float* k_base  = g_k  + (size_t)bh * N0 * HD;
    const float* v_base  = g_v  + (size_t)bh * N0 * HD;

    int li  = (lane < LOCAL) ? lane : 0;
    int mi1 = (lane < 17) ? lane + 32 : 0;

    for (int it = 0; it < 14; it++) {
        int n = blockIdx.y * 112 + warp * 14 + it;
        int pi = n / W0, pj = n % W0;
        float qs = qs_base[(size_t)n * HD + lane];
        float qn = qn_base[(size_t)n * HD + lane];

        unsigned vm = 0;
#pragma unroll
        for (int l = 0; l < LOCAL; l++) {
            int di = l / 3 - 1, dj = l % 3 - 1;
            int ii = pi + di, jj = pj + dj;
            bool ok = (ii >= 0 && ii < H0 && jj >= 0 && jj < W0);
            int nn = ok ? ii * W0 + jj : 0;
            kw_sh[warp][l * 33 + lane] = k_base[(size_t)nn * HD + lane];
            vw_sh[warp][l * 33 + lane] = ok ? v_base[(size_t)nn * HD + lane] : 0.f;
            if (ok) vm |= (1u << l);
        }
        __syncwarp();

        float pb0 = g_tab[rpi[n * PLEN + lane] * HEADS + h];
        float pb1 = (lane < 17) ? g_tab[rpi[n * PLEN + 32 + lane] * HEADS + h] : 0.f;

        float s9 = 0.f, sp0 = 0.f, sp1 = 0.f, tl = 0.f;
#pragma unroll
        for (int d = 0; d < HD; d++) {
            float qd  = __shfl_sync(0xffffffffu, qs, d);
            float qnd = __shfl_sync(0xffffffffu, qn, d);
            s9  += qd  * kw_sh[warp][li * 33 + d];
            sp0 += qd  * kp_sh[lane * 33 + d];
            sp1 += qd  * kp_sh[mi1 * 33 + d];
            tl  += qnd * lt_sh[d * LOCAL + li];
        }

        s9  = (lane < LOCAL && ((vm >> lane) & 1)) ? (s9 + rpb_sh[lane]) : NEGV;
        sp0 += pb0;
        sp1 = (lane < 17) ? (sp1 + pb1) : NEGV;

        float mx = fmaxf(s9, fmaxf(sp0, sp1));
#pragma unroll
        for (int o = 16; o; o >>= 1) mx = fmaxf(mx, __shfl_xor_sync(0xffffffffu, mx, o));
        float e9 = expf(s9 - mx), e0 = expf(sp0 - mx), e1 = expf(sp1 - mx);
        float sum = e9 + e0 + e1;
#pragma unroll
        for (int o = 16; o; o >>= 1) sum += __shfl_xor_sync(0xffffffffu, sum, o);
        float inv = 1.f / sum;

        float a9 = (lane < LOCAL) ? (e9 * inv + tl + lb_sh[lane]) : 0.f;
        float a0 = e0 * inv;
        float a1 = e1 * inv;   // lanes >= 17: e1 == 0

        float out = 0.f;
#pragma unroll
        for (int l = 0; l < LOCAL; l++)
            out += __shfl_sync(0xffffffffu, a9, l) * vw_sh[warp][l * 33 + lane];
#pragma unroll
        for (int m = 0; m < 32; m++)
            out += __shfl_sync(0xffffffffu, a0, m) * vp_sh[m * 33 + lane];
#pragma unroll
        for (int m = 0; m < 17; m++)
            out += __shfl_sync(0xffffffffu, a1, m) * vp_sh[(m + 32) * 33 + lane];

        g_xo[((size_t)(b * N0 + n)) * DIM + h * HD + lane] = out;
        __syncwarp();
    }
}

// ---------------- launch ----------------
extern "C" void kernel_launch(void* const* d_in, const int* in_sizes, int n_in,
                              void* d_out, int out_size)
{
    const float* x      = (const float*)d_in[0];
    const float* sls    = (const float*)d_in[1];
    const float* rct    = (const float*)d_in[2];
    const float* q_w    = (const float*)d_in[3];
    const float* q_b    = (const float*)d_in[4];
    const float* qe     = (const float*)d_in[5];
    const float* temp   = (const float*)d_in[6];
    const float* kv_w   = (const float*)d_in[7];
    const float* kv_b   = (const float*)d_in[8];
    const float* sr_w   = (const float*)d_in[9];
    const float* sr_b   = (const float*)d_in[10];
    const float* norm_g = (const float*)d_in[11];
    const float* norm_b = (const float*)d_in[12];
    const float* fc1_w  = (const float*)d_in[13];
    const float* fc1_b  = (const float*)d_in[14];
    const float* fc2_w  = (const float*)d_in[15];
    const float* fc2_b  = (const float*)d_in[16];
    const float* rpb    = (const float*)d_in[17];
    const float* lt     = (const float*)d_in[18];
    const float* lb     = (const float*)d_in[19];
    const float* proj_w = (const float*)d_in[20];
    const float* proj_b = (const float*)d_in[21];
    const int*   rpi    = (const int*)d_in[22];
    float* out = (float*)d_out;

    // 1) fused x @ [q_w | kv_w | sr_w] (bf16x3 tensor cores), scatter epilogue
    dim3 g1(MROWS / 128, 1024 / 128);
    gemm_bf3_kernel<0><<<g1, 256>>>(x, q_w, kv_w, sr_w, q_b, kv_b, sr_b, nullptr);

    // 2) l2-normalize q (-> q_norm, q_s) and k
    int warps = 2 * B_ * HEADS * N0;
    norm_kernel<<<warps / 8, 256>>>(qe, temp, sls);

    // 3) pool + layernorm
    pool_ln_kernel<<<B_ * PLEN, 256>>>(norm_g, norm_b);

    // 4) kvp mini-GEMM, 8 rows per block (k_pool normalized in-epilogue)
    kvp_kernel<<<B_ * PLEN / 8, 256>>>(kv_w, kv_b);

    // 5) cpb table MLP
    cpb_kernel<<<LTAB / 8, 256>>>(rct, fc1_w, fc1_b, fc2_w, fc2_b);

    // 6) fused attention
    attn_kernel<<<dim3(B_ * HEADS, 28), 256>>>(rpi, rpb, lt, lb);

    // 7) proj GEMM (bf16x3 tensor cores) -> d_out
    dim3 g7(MROWS / 128, 256 / 128);
    gemm_bf3_kernel<1><<<g7, 256>>>(nullptr, proj_w, nullptr, nullptr, proj_b, nullptr, nullptr, out);
}

// round 3
// speedup vs baseline: 1.2944x; 1.1937x over previous
#include <cuda_runtime.h>
#include <cuda_bf16.h>
#include <math.h>
#include <stdint.h>

// ---------------- problem constants (all static) ----------------
constexpr int B_    = 8;
constexpr int H0    = 56;
constexpr int W0    = 56;
constexpr int N0    = H0 * W0;        // 3136
constexpr int DIM   = 256;
constexpr int HEADS = 8;
constexpr int HD    = 32;
constexpr int LOCAL = 9;
constexpr int PW    = 7;
constexpr int PLEN  = 49;
constexpr int LTAB  = 4096;
constexpr int MROWS = B_ * N0;        // 25088
constexpr float NEGV = -1e9f;

// ---------------- scratch (device globals; no allocs) ----------------
__device__ float g_qs[B_*HEADS*N0*HD];   // q_s           (b,h,n,d)
__device__ float g_qn[B_*HEADS*N0*HD];   // q_norm
__device__ float g_k [B_*HEADS*N0*HD];   // k_norm
__device__ float g_v [B_*HEADS*N0*HD];   // v_loc
__device__ float g_xs[B_*N0*DIM];        // gelu(x@sr_w+sr_b)
__device__ float g_xp[B_*PLEN*DIM];      // pooled + LN
__device__ float g_kp[B_*HEADS*PLEN*HD]; // k_pool (normalized)
__device__ float g_vp[B_*HEADS*PLEN*HD]; // v_pool
__device__ float g_tab[LTAB*HEADS];      // cpb table

// packed bf16 hi/lo operands (u32 = 2 bf16 along k)
__device__ uint32_t g_xH [MROWS*128];    // x        [row][k2]
__device__ uint32_t g_xL [MROWS*128];
__device__ uint32_t g_xoH[MROWS*128];    // attn out [row][k2]
__device__ uint32_t g_xoL[MROWS*128];
__device__ uint32_t g_wH [1280*128];     // fused W  [col][k2]: q|k|v|sr|proj
__device__ uint32_t g_wL [1280*128];

// ---------------- bf16 split helpers ----------------
__device__ __forceinline__ uint32_t pack_bf2(__nv_bfloat16 x, __nv_bfloat16 y) {
    __nv_bfloat162 t; t.x = x; t.y = y;
    return *reinterpret_cast<uint32_t*>(&t);
}
__device__ __forceinline__ void split2(float x, float y, uint32_t& hi, uint32_t& lo) {
    __nv_bfloat16 xh = __float2bfloat16_rn(x);
    __nv_bfloat16 yh = __float2bfloat16_rn(y);
    float xr = x - __bfloat162float(xh);
    float yr = y - __bfloat162float(yh);
    hi = pack_bf2(xh, yh);
    lo = pack_bf2(__float2bfloat16_rn(xr), __float2bfloat16_rn(yr));
}

#define MMA16816(d, a0,a1,a2,a3, b0,b1) \
    asm volatile("mma.sync.aligned.m16n8k16.row.col.f32.bf16.bf16.f32 " \
        "{%0,%1,%2,%3},{%4,%5,%6,%7},{%8,%9},{%0,%1,%2,%3};" \
        : "+f"(d[0]), "+f"(d[1]), "+f"(d[2]), "+f"(d[3]) \
        : "r"(a0), "r"(a1), "r"(a2), "r"(a3), "r"(b0), "r"(b1))

// ---------------- operand conversion kernels ----------------
__global__ __launch_bounds__(256)
void convert_x_kernel(const float* __restrict__ x)
{
    int i = blockIdx.x * 256 + threadIdx.x;          // one float4
    float4 v = reinterpret_cast<const float4*>(x)[i];
    uint32_t h0, l0, h1, l1;
    split2(v.x, v.y, h0, l0);
    split2(v.z, v.w, h1, l1);
    g_xH[i * 2] = h0; g_xH[i * 2 + 1] = h1;
    g_xL[i * 2] = l0; g_xL[i * 2 + 1] = l1;
}

__global__ __launch_bounds__(256)
void convert_w_kernel(const float* __restrict__ q_w, const float* __restrict__ kv_w,
                      const float* __restrict__ sr_w, const float* __restrict__ proj_w)
{
    int idx = blockIdx.x * 256 + threadIdx.x;        // 1280*128
    int c = idx >> 7, k2 = idx & 127;
    float f0, f1;
    if (c < 256)       { f0 = q_w [(2*k2)   * 256 + c];        f1 = q_w [(2*k2+1) * 256 + c];        }
    else if (c < 768)  { f0 = kv_w[(2*k2)   * 512 + c - 256];  f1 = kv_w[(2*k2+1) * 512 + c - 256];  }
    else if (c < 1024) { f0 = sr_w[(2*k2)   * 256 + c - 768];  f1 = sr_w[(2*k2+1) * 256 + c - 768];  }
    else               { f0 = proj_w[(2*k2) * 256 + c - 1024]; f1 = proj_w[(2*k2+1) * 256 + c - 1024]; }
    uint32_t h, l;
    split2(f0, f1, h, l);
    g_wH[idx] = h; g_wL[idx] = l;
}

// ---------------- bf16x3 tensor-core GEMM, 128x128x32 tiles ----------------
// MODE 0: A = g_xH/L, B cols [0,1024): fused epilogue (q/k norm, gelu, scatter)
// MODE 1: A = g_xoH/L, B cols [1024,1280): out = d_out (+proj_b)
template<int MODE>
__global__ __launch_bounds__(256)
void gemm_mma_kernel(const float* __restrict__ bq, const float* __restrict__ bkv,
                     const float* __restrict__ bsr,
                     const float* __restrict__ qe, const float* __restrict__ temp,
                     const float* __restrict__ sls,
                     float* __restrict__ Out)
{
    constexpr int LDU = 20;
    __shared__ uint32_t AsH[128][LDU];
    __shared__ uint32_t AsL[128][LDU];
    __shared__ uint32_t BsH[128][LDU];
    __shared__ uint32_t BsL[128][LDU];

    const uint32_t* AH = MODE ? g_xoH : g_xH;
    const uint32_t* AL = MODE ? g_xoL : g_xL;

    int tid  = threadIdx.x;
    int lane = tid & 31;
    int warp = tid >> 5;
    int wm   = warp >> 2;
    int wn   = warp & 3;

    int m0    = blockIdx.x * 128;
    int col0  = blockIdx.y * 128;                 // logical output col
    int bcol0 = col0 + (MODE ? 1024 : 0);         // col in fused weight buffer

    int lrow = tid >> 1;                          // 0..127
    int loff = (tid & 1) * 8;                     // 0 / 8

    float acc[4][4][4];
#pragma unroll
    for (int i = 0; i < 4; i++)
#pragma unroll
        for (int j = 0; j < 4; j++)
#pragma unroll
            for (int e = 0; e < 4; e++) acc[i][j][e] = 0.f;

    const uint32_t* aHp = &AH [(size_t)(m0 + lrow)    * 128 + loff];
    const uint32_t* aLp = &AL [(size_t)(m0 + lrow)    * 128 + loff];
    const uint32_t* bHp = &g_wH[(size_t)(bcol0 + lrow) * 128 + loff];
    const uint32_t* bLp = &g_wL[(size_t)(bcol0 + lrow) * 128 + loff];

    uint4 rAH[2], rAL[2], rBH[2], rBL[2];
    // preload k-step 0
#pragma unroll
    for (int u = 0; u < 2; u++) {
        rAH[u] = *reinterpret_cast<const uint4*>(aHp + u * 4);
        rAL[u] = *reinterpret_cast<const uint4*>(aLp + u * 4);
        rBH[u] = *reinterpret_cast<const uint4*>(bHp + u * 4);
        rBL[u] = *reinterpret_cast<const uint4*>(bLp + u * 4);
    }
#pragma unroll
    for (int u = 0; u < 2; u++) {
        *reinterpret_cast<uint4*>(&AsH[lrow][loff + u * 4]) = rAH[u];
        *reinterpret_cast<uint4*>(&AsL[lrow][loff + u * 4]) = rAL[u];
        *reinterpret_cast<uint4*>(&BsH[lrow][loff + u * 4]) = rBH[u];
        *reinterpret_cast<uint4*>(&BsL[lrow][loff + u * 4]) = rBL[u];
    }
    __syncthreads();

    for (int it = 0; it < 8; it++) {
        if (it < 7) {
            int kk2 = (it + 1) * 16;
#pragma unroll
            for (int u = 0; u < 2; u++) {
                rAH[u] = *reinterpret_cast<const uint4*>(aHp + kk2 + u * 4);
                rAL[u] = *reinterpret_cast<const uint4*>(aLp + kk2 + u * 4);
                rBH[u] = *reinterpret_cast<const uint4*>(bHp + kk2 + u * 4);
                rBL[u] = *reinterpret_cast<const uint4*>(bLp + kk2 + u * 4);
            }
        }
#pragma unroll
        for (int s = 0; s < 2; s++) {
            int ci = 8 * s + (lane & 3);
            uint32_t aH[4][4], aL[4][4], bH[4][2], bL[4][2];
#pragma unroll
            for (int mt = 0; mt < 4; mt++) {
                int mr = wm * 64 + mt * 16 + (lane >> 2);
                aH[mt][0] = AsH[mr][ci];     aH[mt][1] = AsH[mr + 8][ci];
                aH[mt][2] = AsH[mr][ci + 4]; aH[mt][3] = AsH[mr + 8][ci + 4];
                aL[mt][0] = AsL[mr][ci];     aL[mt][1] = AsL[mr + 8][ci];
                aL[mt][2] = AsL[mr][ci + 4]; aL[mt][3] = AsL[mr + 8][ci + 4];
            }
#pragma unroll
            for (int nt = 0; nt < 4; nt++) {
                int nr = wn * 32 + nt * 8 + (lane >> 2);
                bH[nt][0] = BsH[nr][ci]; bH[nt][1] = BsH[nr][ci + 4];
                bL[nt][0] = BsL[nr][ci]; bL[nt][1] = BsL[nr][ci + 4];
            }
#pragma unroll
            for (int mt = 0; mt < 4; mt++)
#pragma unroll
                for (int nt = 0; nt < 4; nt++) {
                    MMA16816(acc[mt][nt], aH[mt][0], aH[mt][1], aH[mt][2], aH[mt][3],
                             bH[nt][0], bH[nt][1]);
                    MMA16816(acc[mt][nt], aH[mt][0], aH[mt][1], aH[mt][2], aH[mt][3],
                             bL[nt][0], bL[nt][1]);
                    MMA16816(acc[mt][nt], aL[mt][0], aL[mt][1], aL[mt][2], aL[mt][3],
                             bH[nt][0], bH[nt][1]);
                }
        }
        __syncthreads();
        if (it < 7) {
#pragma unroll
            for (int u = 0; u < 2; u++) {
                *reinterpret_cast<uint4*>(&AsH[lrow][loff + u * 4]) = rAH[u];
                *reinterpret_cast<uint4*>(&AsL[lrow][loff + u * 4]) = rAL[u];
                *reinterpret_cast<uint4*>(&BsH[lrow][loff + u * 4]) = rBH[u];
                *reinterpret_cast<uint4*>(&BsL[lrow][loff + u * 4]) = rBL[u];
            }
            __syncthreads();
        }
    }

    // ---------------- epilogue ----------------
    if (MODE == 1) {
#pragma unroll
        for (int mt = 0; mt < 4; mt++) {
            int r0 = m0 + wm * 64 + mt * 16 + (lane >> 2);
#pragma unroll
            for (int nt = 0; nt < 4; nt++) {
                int c0 = col0 + wn * 32 + nt * 8 + (lane & 3) * 2;
                Out[(size_t)r0 * DIM + c0]           = acc[mt][nt][0] + bq[c0];
                Out[(size_t)r0 * DIM + c0 + 1]       = acc[mt][nt][1] + bq[c0 + 1];
                Out[(size_t)(r0 + 8) * DIM + c0]     = acc[mt][nt][2] + bq[c0];
                Out[(size_t)(r0 + 8) * DIM + c0 + 1] = acc[mt][nt][3] + bq[c0 + 1];
            }
        }
        return;
    }

    // MODE 0: this warp's 32-col strip is one "unit" of the fused output.
    int strip = (col0 + wn * 32) >> 5;   // 0..31
    // add bias first
#pragma unroll
    for (int mt = 0; mt < 4; mt++)
#pragma unroll
        for (int nt = 0; nt < 4; nt++) {
            int c = col0 + wn * 32 + nt * 8 + (lane & 3) * 2;
            float b0, b1;
            if (c < 256)      { b0 = bq[c];        b1 = bq[c + 1];        }
            else if (c < 768) { b0 = bkv[c - 256]; b1 = bkv[c - 255];     }
            else              { b0 = bsr[c - 768]; b1 = bsr[c - 767];     }
            acc[mt][nt][0] += b0; acc[mt][nt][1] += b1;
            acc[mt][nt][2] += b0; acc[mt][nt][3] += b1;
        }

    if (strip < 16) {
        // q (strip 0..7) or k (strip 8..15): L2-normalize over the 32-col head
        int h = strip & 7;
        bool isq = strip < 8;
        float spsls = 0.f;
        if (isq) spsls = log1pf(expf(temp[h])) * sls[0];
#pragma unroll
        for (int mt = 0; mt < 4; mt++) {
            float ss0 = 0.f, ss1 = 0.f;
#pragma unroll
            for (int nt = 0; nt < 4; nt++) {
                ss0 += acc[mt][nt][0] * acc[mt][nt][0] + acc[mt][nt][1] * acc[mt][nt][1];
                ss1 += acc[mt][nt][2] * acc[mt][nt][2] + acc[mt][nt][3] * acc[mt][nt][3];
            }
            ss0 += __shfl_xor_sync(0xffffffffu, ss0, 1);
            ss0 += __shfl_xor_sync(0xffffffffu, ss0, 2);
            ss1 += __shfl_xor_sync(0xffffffffu, ss1, 1);
            ss1 += __shfl_xor_sync(0xffffffffu, ss1, 2);
            float inv0 = 1.f / fmaxf(sqrtf(ss0), 1e-12f);
            float inv1 = 1.f / fmaxf(sqrtf(ss1), 1e-12f);
            int r0 = m0 + wm * 64 + mt * 16 + (lane >> 2);
            int b0i = r0 / N0, n0i = r0 % N0;
            int b1i = (r0 + 8) / N0, n1i = (r0 + 8) % N0;
            size_t base0 = (((size_t)(b0i * HEADS + h)) * N0 + n0i) * HD;
            size_t base1 = (((size_t)(b1i * HEADS + h)) * N0 + n1i) * HD;
#pragma unroll
            for (int nt = 0; nt < 4; nt++) {
                int d0 = (wn * 32 + nt * 8 + (lane & 3) * 2) & 31;
#pragma unroll
                for (int p = 0; p < 2; p++) {
                    int d = d0 + p;
                    float v0 = acc[mt][nt][p]     * inv0;
                    float v1 = acc[mt][nt][2 + p] * inv1;
                    if (isq) {
                        float e = qe[h * HD + d];
                        g_qn[base0 + d] = v0;
                        g_qn[base1 + d] = v1;
                        g_qs[base0 + d] = (v0 + e) * spsls;
                        g_qs[base1 + d] = (v1 + e) * spsls;
                    } else {
                        g_k[base0 + d] = v0;
                        g_k[base1 + d] = v1;
                    }
                }
            }
        }
    } else if (strip < 24) {
        // v: plain scatter
        int h = strip & 7;
#pragma unroll
        for (int mt = 0; mt < 4; mt++) {
            int r0 = m0 + wm * 64 + mt * 16 + (lane >> 2);
#pragma unroll
            for (int e = 0; e < 2; e++) {
                int r = r0 + e * 8;
                int b = r / N0, n = r % N0;
                size_t base = (((size_t)(b * HEADS + h)) * N0 + n) * HD;
#pragma unroll
                for (int nt = 0; nt < 4; nt++) {
                    int d = (wn * 32 + nt * 8 + (lane & 3) * 2) & 31;
                    base[(float*)nullptr];  // (never executed) placeholder removed below
                }
            }
        }
        // (rewritten without placeholder)
#pragma unroll
        for (int mt = 0; mt < 4; mt++) {
            int r0 = m0 + wm * 64 + mt * 16 + (lane >> 2);
            int ba = r0 / N0, na = r0 % N0;
            int bb = (r0 + 8) / N0, nb = (r0 + 8) % N0;
            size_t base0 = (((size_t)(ba * HEADS + h)) * N0 + na) * HD;
            size_t base1 = (((size_t)(bb * HEADS + h)) * N0 + nb) * HD;
#pragma unroll
            for (int nt = 0; nt < 4; nt++) {
                int d = (wn * 32 + nt * 8 + (lane & 3) * 2) & 31;
                g_v[base0 + d]     = acc[mt][nt][0];
                g_v[base0 + d + 1] = acc[mt][nt][1];
                g_v[base1 + d]     = acc[mt][nt][2];
                g_v[base1 + d + 1] = acc[mt][nt][3];
            }
        }
    } else {
        // sr: gelu -> g_xs
#pragma unroll
        for (int mt = 0; mt < 4; mt++) {
            int r0 = m0 + wm * 64 + mt * 16 + (lane >> 2);
            int ba = r0 / N0, na = r0 % N0;
            int bb = (r0 + 8) / N0, nb = (r0 + 8) % N0;
#pragma unroll
            for (int nt = 0; nt < 4; nt++) {
                int cc = (wn * 32 + nt * 8 + (lane & 3) * 2) + col0 - 768;
#pragma unroll
                for (int p = 0; p < 2; p++) {
                    float v0 = acc[mt][nt][p];
                    float v1 = acc[mt][nt][2 + p];
                    g_xs[((size_t)(ba * N0 + na)) * DIM + cc + p] =
                        0.5f * v0 * (1.f + erff(v0 * 0.70710678118654752f));
                    g_xs[((size_t)(bb * N0 + nb)) * DIM + cc + p] =
                        0.5f * v1 * (1.f + erff(v1 * 0.70710678118654752f));
                }
            }
        }
    }
}

// ---------------- 8x8 avg pool + layernorm, block per (b, p) ----------------
__global__ void pool_ln_kernel(const float* __restrict__ gamma,
                               const float* __restrict__ beta)
{
    __shared__ float red[256];
    int bp = blockIdx.x;
    int b = bp / PLEN, p = bp % PLEN;
    int pi = p / PW, pj = p % PW;
    int c = threadIdx.x;

    float s = 0.f;
#pragma unroll
    for (int r = 0; r < 8; r++)
#pragma unroll
        for (int col = 0; col < 8; col++) {
            int n = (pi * 8 + r) * W0 + (pj * 8 + col);
            s += g_xs[((size_t)(b * N0 + n)) * DIM + c];
        }
    s *= (1.f / 64.f);

    red[c] = s; __syncthreads();
    for (int o = 128; o > 0; o >>= 1) { if (c < o) red[c] += red[c + o]; __syncthreads(); }
    float mean = red[0] * (1.f / 256.f);
    __syncthreads();
    float dv = s - mean;
    red[c] = dv * dv; __syncthreads();
    for (int o = 128; o > 0; o >>= 1) { if (c < o) red[c] += red[c + o]; __syncthreads(); }
    float var = red[0] * (1.f / 256.f);
    g_xp[(size_t)bp * DIM + c] = dv * rsqrtf(var + 1e-5f) * gamma[c] + beta[c];
}

// ---------------- kvp: xp(392x256) @ kv_w(256x512) ----------------
// grid (98, 2): 4 rows per block; y=0 -> k cols (normalized), y=1 -> v cols
__global__ __launch_bounds__(256)
void kvp_kernel(const float* __restrict__ kv_w,
                const float* __restrict__ kv_b)
{
    __shared__ float xr[4][DIM];
    int bp0 = blockIdx.x * 4;
    int half = blockIdx.y;
    int tid = threadIdx.x, lane = tid & 31, wp = tid >> 5;

#pragma unroll
    for (int i = 0; i < 4; i++)
        xr[i][tid] = g_xp[(size_t)(bp0 + i) * DIM + tid];
    __syncthreads();

    int yoff = half * 256;
    float bb = kv_b[yoff + tid];
    float acc[4];
#pragma unroll
    for (int i = 0; i < 4; i++) acc[i] = bb;

#pragma unroll 8
    for (int kk = 0; kk < DIM; kk++) {
        float w = kv_w[(size_t)kk * 512 + yoff + tid];
#pragma unroll
        for (int i = 0; i < 4; i++) acc[i] = fmaf(xr[i][kk], w, acc[i]);
    }

#pragma unroll
    for (int i = 0; i < 4; i++) {
        int bp = bp0 + i;
        int b = bp / PLEN, p = bp % PLEN;
        size_t dst = (((size_t)(b * HEADS + wp)) * PLEN + p) * HD + lane;
        if (half == 0) {
            float ss = acc[i] * acc[i];
#pragma unroll
            for (int o = 16; o; o >>= 1) ss += __shfl_xor_sync(0xffffffffu, ss, o);
            g_kp[dst] = acc[i] / fmaxf(sqrtf(ss), 1e-12f);
        } else {
            g_vp[dst] = acc[i];
        }
    }
}

// ---------------- cpb MLP: tab[t,h], warp per table row ----------------
__global__ void cpb_kernel(const float* __restrict__ rct,
                           const float* __restrict__ w1, const float* __restrict__ b1,
                           const float* __restrict__ w2, const float* __restrict__ b2)
{
    int gw = (blockIdx.x * blockDim.x + threadIdx.x) >> 5;
    int lane = threadIdx.x & 31;
    if (gw >= LTAB) return;
    float r0 = rct[gw * 2], r1 = rct[gw * 2 + 1];
    float acc[HEADS];
#pragma unroll
    for (int h = 0; h < HEADS; h++) acc[h] = 0.f;
    for (int j = lane; j < 512; j += 32) {
        float hv = fmaxf(r0 * w1[j] + r1 * w1[512 + j] + b1[j], 0.f);
#pragma unroll
        for (int h = 0; h < HEADS; h++) acc[h] += hv * w2[j * HEADS + h];
    }
#pragma unroll
    for (int h = 0; h < HEADS; h++)
#pragma unroll
        for (int o = 16; o; o >>= 1) acc[h] += __shfl_xor_sync(0xffffffffu, acc[h], o);
    if (lane == 0) {
#pragma unroll
        for (int h = 0; h < HEADS; h++) g_tab[gw * HEADS + h] = acc[h] + b2[h];
    }
}

// ---------------- fused attention: warp per pixel ----------------
__global__ __launch_bounds__(256)
void attn_kernel(const int* __restrict__ rpi,
                 const float* __restrict__ rpb_local,
                 const float* __restrict__ ltok,
                 const float* __restrict__ lbias)
{
    __shared__ float kp_sh[PLEN * 33];
    __shared__ float vp_sh[PLEN * 33];
    __shared__ float lt_sh[HD * LOCAL];
    __shared__ float rpb_sh[LOCAL], lb_sh[LOCAL];
    __shared__ float kw_sh[8][LOCAL * 33];
    __shared__ float vw_sh[8][LOCAL * 33];

    int bh = blockIdx.x;
    int b = bh / HEADS, h = bh % HEADS;
    int tid = threadIdx.x, warp = tid >> 5, lane = tid & 31;

    const float* kpsrc = g_kp + (size_t)bh * PLEN * HD;
    const float* vpsrc = g_vp + (size_t)bh * PLEN * HD;
    for (int i = tid; i < PLEN * HD; i += 256) {
        int m = i >> 5, d = i & 31;
        kp_sh[m * 33 + d] = kpsrc[i];
        vp_sh[m * 33 + d] = vpsrc[i];
    }
    for (int i = tid; i < HD * LOCAL; i += 256) lt_sh[i] = ltok[h * HD * LOCAL + i];
    if (tid < LOCAL) { rpb_sh[tid] = rpb_local[h * LOCAL + tid]; lb_sh[tid] = lbias[h * LOCAL + tid]; }
    __syncthreads();

    const float* qs_base = g_qs + (size_t)bh * N0 * HD;
    const float* qn_base = g_qn + (size_t)bh * N0 * HD;
    const float* k_base  = g_k  + (size_t)bh * N0 * HD;
    const float* v_base  = g_v  + (size_t)bh * N0 * HD;

    int li  = (lane < LOCAL) ? lane : 0;
    int mi1 = (lane < 17) ? lane + 32 : 0;

    for (int it = 0; it < 14; it++) {
        int n = blockIdx.y * 112 + warp * 14 + it;
        int pi = n / W0, pj = n % W0;
        float qs = qs_base[(size_t)n * HD + lane];
        float qn = qn_base[(size_t)n * HD + lane];

        unsigned vm = 0;
#pragma unroll
        for (int l = 0; l < LOCAL; l++) {
            int di = l / 3 - 1, dj = l % 3 - 1;
            int ii = pi + di, jj = pj + dj;
            bool ok = (ii >= 0 && ii < H0 && jj >= 0 && jj < W0);
            int nn = ok ? ii * W0 + jj : 0;
            kw_sh[warp][l * 33 + lane] = k_base[(size_t)nn * HD + lane];
            vw_sh[warp][l * 33 + lane] = ok ? v_base[(size_t)nn * HD + lane] : 0.f;
            if (ok) vm |= (1u << l);
        }
        __syncwarp();

        float pb0 = g_tab[rpi[n * PLEN + lane] * HEADS + h];
        float pb1 = (lane < 17) ? g_tab[rpi[n * PLEN + 32 + lane] * HEADS + h] : 0.f;

        float s9 = 0.f, sp0 = 0.f, sp1 = 0.f, tl = 0.f;
#pragma unroll
        for (int d = 0; d < HD; d++) {
            float qd  = __shfl_sync(0xffffffffu, qs, d);
            float qnd = __shfl_sync(0xffffffffu, qn, d);
            s9  += qd  * kw_sh[warp][li * 33 + d];
            sp0 += qd  * kp_sh[lane * 33 + d];
            sp1 += qd  * kp_sh[mi1 * 33 + d];
            tl  += qnd * lt_sh[d * LOCAL + li];
        }

        s9  = (lane < LOCAL && ((vm >> lane) & 1)) ? (s9 + rpb_sh[lane]) : NEGV;
        sp0 += pb0;
        sp1 = (lane < 17) ? (sp1 + pb1) : NEGV;

        float mx = fmaxf(s9, fmaxf(sp0, sp1));
#pragma unroll
        for (int o = 16; o; o >>= 1) mx = fmaxf(mx, __shfl_xor_sync(0xffffffffu, mx, o));
        float e9 = expf(s9 - mx), e0 = expf(sp0 - mx), e1 = expf(sp1 - mx);
        float sum = e9 + e0 + e1;
#pragma unroll
        for (int o = 16; o; o >>= 1) sum += __shfl_xor_sync(0xffffffffu, sum, o);
        float inv = 1.f / sum;

        float a9 = (lane < LOCAL) ? (e9 * inv + tl + lb_sh[lane]) : 0.f;
        float a0 = e0 * inv;
        float a1 = e1 * inv;

        float out = 0.f;
#pragma unroll
        for (int l = 0; l < LOCAL; l++)
            out += __shfl_sync(0xffffffffu, a9, l) * vw_sh[warp][l * 33 + lane];
#pragma unroll
        for (int m = 0; m < 32; m++)
            out += __shfl_sync(0xffffffffu, a0, m) * vp_sh[m * 33 + lane];
#pragma unroll
        for (int m = 0; m < 17; m++)
            out += __shfl_sync(0xffffffffu, a1, m) * vp_sh[(m + 32) * 33 + lane];

        // write split bf16 directly (proj GEMM A operand)
        float nbv = __shfl_down_sync(0xffffffffu, out, 1);
        if ((lane & 1) == 0) {
            uint32_t hi, lo;
            split2(out, nbv, hi, lo);
            size_t base = ((size_t)(b * N0 + n)) * 128 + h * 16 + (lane >> 1);
            g_xoH[base] = hi;
            g_xoL[base] = lo;
        }
        __syncwarp();
    }
}

// ---------------- launch ----------------
extern "C" void kernel_launch(void* const* d_in, const int* in_sizes, int n_in,
                              void* d_out, int out_size)
{
    const float* x      = (const float*)d_in[0];
    const float* sls    = (const float*)d_in[1];
    const float* rct    = (const float*)d_in[2];
    const float* q_w    = (const float*)d_in[3];
    const float* q_b    = (const float*)d_in[4];
    const float* qe     = (const float*)d_in[5];
    const float* temp   = (const float*)d_in[6];
    const float* kv_w   = (const float*)d_in[7];
    const float* kv_b   = (const float*)d_in[8];
    const float* sr_w   = (const float*)d_in[9];
    const float* sr_b   = (const float*)d_in[10];
    const float* norm_g = (const float*)d_in[11];
    const float* norm_b = (const float*)d_in[12];
    const float* fc1_w  = (const float*)d_in[13];
    const float* fc1_b  = (const float*)d_in[14];
    const float* fc2_w  = (const float*)d_in[15];
    const float* fc2_b  = (const float*)d_in[16];
    const float* rpb    = (const float*)d_in[17];
    const float* lt     = (const float*)d_in[18];
    const float* lb     = (const float*)d_in[19];
    const float* proj_w = (const float*)d_in[20];
    const float* proj_b = (const float*)d_in[21];
    const int*   rpi    = (const int*)d_in[22];
    float* out = (float*)d_out;

    // 0) operand conversion (bf16 hi/lo splits)
    convert_x_kernel<<<MROWS * DIM / 4 / 256, 256>>>(x);
    convert_w_kernel<<<1280 * 128 / 256, 256>>>(q_w, kv_w, sr_w, proj_w);

    // 1) fused GEMM1 with q/k-norm + gelu epilogue
    dim3 g1(MROWS / 128, 1024 / 128);
    gemm_mma_kernel<0><<<g1, 256>>>(q_b, kv_b, sr_b, qe, temp, sls, nullptr);

    // 2) pool + layernorm
    pool_ln_kernel<<<B_ * PLEN, 256>>>(norm_g, norm_b);

    // 3) kvp mini-GEMM
    kvp_kernel<<<dim3(B_ * PLEN / 4, 2), 256>>>(kv_w, kv_b);

    // 4) cpb table MLP
    cpb_kernel<<<LTAB / 8, 256>>>(rct, fc1_w, fc1_b, fc2_w, fc2_b);

    // 5) fused attention (writes split bf16 output)
    attn_kernel<<<dim3(B_ * HEADS, 28), 256>>>(rpi, rpb, lt, lb);

    // 6) proj GEMM -> d_out
    dim3 g7(MROWS / 128, 256 / 128);
    gemm_mma_kernel<1><<<g7, 256>>>(proj_b, nullptr, nullptr, nullptr, nullptr, nullptr, out);
}

// round 4
// speedup vs baseline: 1.3958x; 1.0783x over previous
#include <cuda_runtime.h>
#include <cuda_bf16.h>
#include <math.h>
#include <stdint.h>

// ---------------- problem constants (all static) ----------------
constexpr int B_    = 8;
constexpr int H0    = 56;
constexpr int W0    = 56;
constexpr int N0    = H0 * W0;        // 3136
constexpr int DIM   = 256;
constexpr int HEADS = 8;
constexpr int HD    = 32;
constexpr int LOCAL = 9;
constexpr int PW    = 7;
constexpr int PLEN  = 49;
constexpr int LTAB  = 4096;
constexpr int MROWS = B_ * N0;        // 25088
constexpr float NEGV = -1e9f;

// ---------------- scratch (device globals; no allocs) ----------------
__device__ float g_qs[B_*HEADS*N0*HD];   // q_s           (b,h,n,d)
__device__ float g_qn[B_*HEADS*N0*HD];   // q_norm
__device__ float g_k [B_*HEADS*N0*HD];   // k_norm
__device__ float g_v [B_*HEADS*N0*HD];   // v_loc
__device__ float g_xs[B_*N0*DIM];        // gelu(x@sr_w+sr_b)
__device__ float g_xp[B_*PLEN*DIM];      // pooled + LN
__device__ float g_kp[B_*HEADS*PLEN*HD]; // k_pool (normalized)
__device__ float g_vp[B_*HEADS*PLEN*HD]; // v_pool
__device__ float g_tab[LTAB*HEADS];      // cpb table

// packed bf16 hi/lo operands (u32 = 2 bf16 along k)
__device__ uint32_t g_xH [MROWS*128];
__device__ uint32_t g_xL [MROWS*128];
__device__ uint32_t g_xoH[MROWS*128];
__device__ uint32_t g_xoL[MROWS*128];
__device__ uint32_t g_wH [1280*128];     // fused W [col][k2]: q|k|v|sr|proj
__device__ uint32_t g_wL [1280*128];

// ---------------- bf16 split helpers ----------------
__device__ __forceinline__ uint32_t pack_bf2(__nv_bfloat16 x, __nv_bfloat16 y) {
    __nv_bfloat162 t; t.x = x; t.y = y;
    return *reinterpret_cast<uint32_t*>(&t);
}
__device__ __forceinline__ void split2(float x, float y, uint32_t& hi, uint32_t& lo) {
    __nv_bfloat16 xh = __float2bfloat16_rn(x);
    __nv_bfloat16 yh = __float2bfloat16_rn(y);
    float xr = x - __bfloat162float(xh);
    float yr = y - __bfloat162float(yh);
    hi = pack_bf2(xh, yh);
    lo = pack_bf2(__float2bfloat16_rn(xr), __float2bfloat16_rn(yr));
}

#define MMA16816(d, a0,a1,a2,a3, b0,b1) \
    asm volatile("mma.sync.aligned.m16n8k16.row.col.f32.bf16.bf16.f32 " \
        "{%0,%1,%2,%3},{%4,%5,%6,%7},{%8,%9},{%0,%1,%2,%3};" \
        : "+f"(d[0]), "+f"(d[1]), "+f"(d[2]), "+f"(d[3]) \
        : "r"(a0), "r"(a1), "r"(a2), "r"(a3), "r"(b0), "r"(b1))

// ---------------- operand conversion kernels ----------------
__global__ __launch_bounds__(256)
void convert_x_kernel(const float* __restrict__ x)
{
    int i = blockIdx.x * 256 + threadIdx.x;
    float4 v = reinterpret_cast<const float4*>(x)[i];
    uint32_t h0, l0, h1, l1;
    split2(v.x, v.y, h0, l0);
    split2(v.z, v.w, h1, l1);
    g_xH[i * 2] = h0; g_xH[i * 2 + 1] = h1;
    g_xL[i * 2] = l0; g_xL[i * 2 + 1] = l1;
}

__global__ __launch_bounds__(256)
void convert_w_kernel(const float* __restrict__ q_w, const float* __restrict__ kv_w,
                      const float* __restrict__ sr_w, const float* __restrict__ proj_w)
{
    int idx = blockIdx.x * 256 + threadIdx.x;        // 1280*128
    int c = idx >> 7, k2 = idx & 127;
    float f0, f1;
    if (c < 256)       { f0 = q_w [(2*k2)   * 256 + c];        f1 = q_w [(2*k2+1) * 256 + c];        }
    else if (c < 768)  { f0 = kv_w[(2*k2)   * 512 + c - 256];  f1 = kv_w[(2*k2+1) * 512 + c - 256];  }
    else if (c < 1024) { f0 = sr_w[(2*k2)   * 256 + c - 768];  f1 = sr_w[(2*k2+1) * 256 + c - 768];  }
    else               { f0 = proj_w[(2*k2) * 256 + c - 1024]; f1 = proj_w[(2*k2+1) * 256 + c - 1024]; }
    uint32_t h, l;
    split2(f0, f1, h, l);
    g_wH[idx] = h; g_wL[idx] = l;
}

// ---------------- bf16x3 tensor-core GEMM, 128x128x32 tiles ----------------
template<int MODE>
__global__ __launch_bounds__(256)
void gemm_mma_kernel(const float* __restrict__ bq, const float* __restrict__ bkv,
                     const float* __restrict__ bsr,
                     const float* __restrict__ qe, const float* __restrict__ temp,
                     const float* __restrict__ sls,
                     float* __restrict__ Out)
{
    constexpr int LDU = 20;
    __shared__ uint32_t AsH[128][LDU];
    __shared__ uint32_t AsL[128][LDU];
    __shared__ uint32_t BsH[128][LDU];
    __shared__ uint32_t BsL[128][LDU];

    const uint32_t* AH = MODE ? g_xoH : g_xH;
    const uint32_t* AL = MODE ? g_xoL : g_xL;

    int tid  = threadIdx.x;
    int lane = tid & 31;
    int warp = tid >> 5;
    int wm   = warp >> 2;
    int wn   = warp & 3;

    int m0    = blockIdx.x * 128;
    int col0  = blockIdx.y * 128;
    int bcol0 = col0 + (MODE ? 1024 : 0);

    int lrow = tid >> 1;
    int loff = (tid & 1) * 8;

    float acc[4][4][4];
#pragma unroll
    for (int i = 0; i < 4; i++)
#pragma unroll
        for (int j = 0; j < 4; j++)
#pragma unroll
            for (int e = 0; e < 4; e++) acc[i][j][e] = 0.f;

    const uint32_t* aHp = &AH [(size_t)(m0 + lrow)    * 128 + loff];
    const uint32_t* aLp = &AL [(size_t)(m0 + lrow)    * 128 + loff];
    const uint32_t* bHp = &g_wH[(size_t)(bcol0 + lrow) * 128 + loff];
    const uint32_t* bLp = &g_wL[(size_t)(bcol0 + lrow) * 128 + loff];

    uint4 rAH[2], rAL[2], rBH[2], rBL[2];
#pragma unroll
    for (int u = 0; u < 2; u++) {
        rAH[u] = *reinterpret_cast<const uint4*>(aHp + u * 4);
        rAL[u] = *reinterpret_cast<const uint4*>(aLp + u * 4);
        rBH[u] = *reinterpret_cast<const uint4*>(bHp + u * 4);
        rBL[u] = *reinterpret_cast<const uint4*>(bLp + u * 4);
    }
#pragma unroll
    for (int u = 0; u < 2; u++) {
        *reinterpret_cast<uint4*>(&AsH[lrow][loff + u * 4]) = rAH[u];
        *reinterpret_cast<uint4*>(&AsL[lrow][loff + u * 4]) = rAL[u];
        *reinterpret_cast<uint4*>(&BsH[lrow][loff + u * 4]) = rBH[u];
        *reinterpret_cast<uint4*>(&BsL[lrow][loff + u * 4]) = rBL[u];
    }
    __syncthreads();

    for (int it = 0; it < 8; it++) {
        if (it < 7) {
            int kk2 = (it + 1) * 16;
#pragma unroll
            for (int u = 0; u < 2; u++) {
                rAH[u] = *reinterpret_cast<const uint4*>(aHp + kk2 + u * 4);
                rAL[u] = *reinterpret_cast<const uint4*>(aLp + kk2 + u * 4);
                rBH[u] = *reinterpret_cast<const uint4*>(bHp + kk2 + u * 4);
                rBL[u] = *reinterpret_cast<const uint4*>(bLp + kk2 + u * 4);
            }
        }
#pragma unroll
        for (int s = 0; s < 2; s++) {
            int ci = 8 * s + (lane & 3);
            uint32_t aH[4][4], aL[4][4], bH[4][2], bL[4][2];
#pragma unroll
            for (int mt = 0; mt < 4; mt++) {
                int mr = wm * 64 + mt * 16 + (lane >> 2);
                aH[mt][0] = AsH[mr][ci];     aH[mt][1] = AsH[mr + 8][ci];
                aH[mt][2] = AsH[mr][ci + 4]; aH[mt][3] = AsH[mr + 8][ci + 4];
                aL[mt][0] = AsL[mr][ci];     aL[mt][1] = AsL[mr + 8][ci];
                aL[mt][2] = AsL[mr][ci + 4]; aL[mt][3] = AsL[mr + 8][ci + 4];
            }
#pragma unroll
            for (int nt = 0; nt < 4; nt++) {
                int nr = wn * 32 + nt * 8 + (lane >> 2);
                bH[nt][0] = BsH[nr][ci]; bH[nt][1] = BsH[nr][ci + 4];
                bL[nt][0] = BsL[nr][ci]; bL[nt][1] = BsL[nr][ci + 4];
            }
#pragma unroll
            for (int mt = 0; mt < 4; mt++)
#pragma unroll
                for (int nt = 0; nt < 4; nt++) {
                    MMA16816(acc[mt][nt], aH[mt][0], aH[mt][1], aH[mt][2], aH[mt][3],
                             bH[nt][0], bH[nt][1]);
                    MMA16816(acc[mt][nt], aH[mt][0], aH[mt][1], aH[mt][2], aH[mt][3],
                             bL[nt][0], bL[nt][1]);
                    MMA16816(acc[mt][nt], aL[mt][0], aL[mt][1], aL[mt][2], aL[mt][3],
                             bH[nt][0], bH[nt][1]);
                }
        }
        __syncthreads();
        if (it < 7) {
#pragma unroll
            for (int u = 0; u < 2; u++) {
                *reinterpret_cast<uint4*>(&AsH[lrow][loff + u * 4]) = rAH[u];
                *reinterpret_cast<uint4*>(&AsL[lrow][loff + u * 4]) = rAL[u];
                *reinterpret_cast<uint4*>(&BsH[lrow][loff + u * 4]) = rBH[u];
                *reinterpret_cast<uint4*>(&BsL[lrow][loff + u * 4]) = rBL[u];
            }
            __syncthreads();
        }
    }

    // ---------------- epilogue ----------------
    if (MODE == 1) {
#pragma unroll
        for (int mt = 0; mt < 4; mt++) {
            int r0 = m0 + wm * 64 + mt * 16 + (lane >> 2);
#pragma unroll
            for (int nt = 0; nt < 4; nt++) {
                int c0 = col0 + wn * 32 + nt * 8 + (lane & 3) * 2;
                Out[(size_t)r0 * DIM + c0]           = acc[mt][nt][0] + bq[c0];
                Out[(size_t)r0 * DIM + c0 + 1]       = acc[mt][nt][1] + bq[c0 + 1];
                Out[(size_t)(r0 + 8) * DIM + c0]     = acc[mt][nt][2] + bq[c0];
                Out[(size_t)(r0 + 8) * DIM + c0 + 1] = acc[mt][nt][3] + bq[c0 + 1];
            }
        }
        return;
    }

    int strip = (col0 + wn * 32) >> 5;
#pragma unroll
    for (int mt = 0; mt < 4; mt++)
#pragma unroll
        for (int nt = 0; nt < 4; nt++) {
            int c = col0 + wn * 32 + nt * 8 + (lane & 3) * 2;
            float b0, b1;
            if (c < 256)      { b0 = bq[c];        b1 = bq[c + 1];    }
            else if (c < 768) { b0 = bkv[c - 256]; b1 = bkv[c - 255]; }
            else              { b0 = bsr[c - 768]; b1 = bsr[c - 767]; }
            acc[mt][nt][0] += b0; acc[mt][nt][1] += b1;
            acc[mt][nt][2] += b0; acc[mt][nt][3] += b1;
        }

    if (strip < 16) {
        int h = strip & 7;
        bool isq = strip < 8;
        float spsls = 0.f;
        if (isq) spsls = log1pf(expf(temp[h])) * sls[0];
#pragma unroll
        for (int mt = 0; mt < 4; mt++) {
            float ss0 = 0.f, ss1 = 0.f;
#pragma unroll
            for (int nt = 0; nt < 4; nt++) {
                ss0 += acc[mt][nt][0] * acc[mt][nt][0] + acc[mt][nt][1] * acc[mt][nt][1];
                ss1 += acc[mt][nt][2] * acc[mt][nt][2] + acc[mt][nt][3] * acc[mt][nt][3];
            }
            ss0 += __shfl_xor_sync(0xffffffffu, ss0, 1);
            ss0 += __shfl_xor_sync(0xffffffffu, ss0, 2);
            ss1 += __shfl_xor_sync(0xffffffffu, ss1, 1);
            ss1 += __shfl_xor_sync(0xffffffffu, ss1, 2);
            float inv0 = 1.f / fmaxf(sqrtf(ss0), 1e-12f);
            float inv1 = 1.f / fmaxf(sqrtf(ss1), 1e-12f);
            int r0 = m0 + wm * 64 + mt * 16 + (lane >> 2);
            int b0i = r0 / N0, n0i = r0 % N0;
            int b1i = (r0 + 8) / N0, n1i = (r0 + 8) % N0;
            size_t base0 = (((size_t)(b0i * HEADS + h)) * N0 + n0i) * HD;
            size_t base1 = (((size_t)(b1i * HEADS + h)) * N0 + n1i) * HD;
#pragma unroll
            for (int nt = 0; nt < 4; nt++) {
                int d0 = (wn * 32 + nt * 8 + (lane & 3) * 2) & 31;
#pragma unroll
                for (int p = 0; p < 2; p++) {
                    int d = d0 + p;
                    float v0 = acc[mt][nt][p]     * inv0;
                    float v1 = acc[mt][nt][2 + p] * inv1;
                    if (isq) {
                        float e = qe[h * HD + d];
                        g_qn[base0 + d] = v0;
                        g_qn[base1 + d] = v1;
                        g_qs[base0 + d] = (v0 + e) * spsls;
                        g_qs[base1 + d] = (v1 + e) * spsls;
                    } else {
                        g_k[base0 + d] = v0;
                        g_k[base1 + d] = v1;
                    }
                }
            }
        }
    } else if (strip < 24) {
        int h = strip & 7;
#pragma unroll
        for (int mt = 0; mt < 4; mt++) {
            int r0 = m0 + wm * 64 + mt * 16 + (lane >> 2);
            int ba = r0 / N0, na = r0 % N0;
            int bb = (r0 + 8) / N0, nb = (r0 + 8) % N0;
            size_t base0 = (((size_t)(ba * HEADS + h)) * N0 + na) * HD;
            size_t base1 = (((size_t)(bb * HEADS + h)) * N0 + nb) * HD;
#pragma unroll
            for (int nt = 0; nt < 4; nt++) {
                int d = (wn * 32 + nt * 8 + (lane & 3) * 2) & 31;
                g_v[base0 + d]     = acc[mt][nt][0];
                g_v[base0 + d + 1] = acc[mt][nt][1];
                g_v[base1 + d]     = acc[mt][nt][2];
                g_v[base1 + d + 1] = acc[mt][nt][3];
            }
        }
    } else {
#pragma unroll
        for (int mt = 0; mt < 4; mt++) {
            int r0 = m0 + wm * 64 + mt * 16 + (lane >> 2);
            int ba = r0 / N0, na = r0 % N0;
            int bb = (r0 + 8) / N0, nb = (r0 + 8) % N0;
#pragma unroll
            for (int nt = 0; nt < 4; nt++) {
                int cc = (wn * 32 + nt * 8 + (lane & 3) * 2) + col0 - 768;
#pragma unroll
                for (int p = 0; p < 2; p++) {
                    float v0 = acc[mt][nt][p];
                    float v1 = acc[mt][nt][2 + p];
                    g_xs[((size_t)(ba * N0 + na)) * DIM + cc + p] =
                        0.5f * v0 * (1.f + erff(v0 * 0.70710678118654752f));
                    g_xs[((size_t)(bb * N0 + nb)) * DIM + cc + p] =
                        0.5f * v1 * (1.f + erff(v1 * 0.70710678118654752f));
                }
            }
        }
    }
}

// ---------------- 8x8 avg pool + layernorm ----------------
__global__ void pool_ln_kernel(const float* __restrict__ gamma,
                               const float* __restrict__ beta)
{
    __shared__ float red[256];
    int bp = blockIdx.x;
    int b = bp / PLEN, p = bp % PLEN;
    int pi = p / PW, pj = p % PW;
    int c = threadIdx.x;

    float s = 0.f;
#pragma unroll
    for (int r = 0; r < 8; r++)
#pragma unroll
        for (int col = 0; col < 8; col++) {
            int n = (pi * 8 + r) * W0 + (pj * 8 + col);
            s += g_xs[((size_t)(b * N0 + n)) * DIM + c];
        }
    s *= (1.f / 64.f);

    red[c] = s; __syncthreads();
    for (int o = 128; o > 0; o >>= 1) { if (c < o) red[c] += red[c + o]; __syncthreads(); }
    float mean = red[0] * (1.f / 256.f);
    __syncthreads();
    float dv = s - mean;
    red[c] = dv * dv; __syncthreads();
    for (int o = 128; o > 0; o >>= 1) { if (c < o) red[c] += red[c + o]; __syncthreads(); }
    float var = red[0] * (1.f / 256.f);
    g_xp[(size_t)bp * DIM + c] = dv * rsqrtf(var + 1e-5f) * gamma[c] + beta[c];
}

// ---------------- kvp: xp(392x256) @ kv_w(256x512) ----------------
__global__ __launch_bounds__(256)
void kvp_kernel(const float* __restrict__ kv_w,
                const float* __restrict__ kv_b)
{
    __shared__ float xr[4][DIM];
    int bp0 = blockIdx.x * 4;
    int half = blockIdx.y;
    int tid = threadIdx.x, lane = tid & 31, wp = tid >> 5;

#pragma unroll
    for (int i = 0; i < 4; i++)
        xr[i][tid] = g_xp[(size_t)(bp0 + i) * DIM + tid];
    __syncthreads();

    int yoff = half * 256;
    float bb = kv_b[yoff + tid];
    float acc[4];
#pragma unroll
    for (int i = 0; i < 4; i++) acc[i] = bb;

#pragma unroll 8
    for (int kk = 0; kk < DIM; kk++) {
        float w = kv_w[(size_t)kk * 512 + yoff + tid];
#pragma unroll
        for (int i = 0; i < 4; i++) acc[i] = fmaf(xr[i][kk], w, acc[i]);
    }

#pragma unroll
    for (int i = 0; i < 4; i++) {
        int bp = bp0 + i;
        int b = bp / PLEN, p = bp % PLEN;
        size_t dst = (((size_t)(b * HEADS + wp)) * PLEN + p) * HD + lane;
        if (half == 0) {
            float ss = acc[i] * acc[i];
#pragma unroll
            for (int o = 16; o; o >>= 1) ss += __shfl_xor_sync(0xffffffffu, ss, o);
            g_kp[dst] = acc[i] / fmaxf(sqrtf(ss), 1e-12f);
        } else {
            g_vp[dst] = acc[i];
        }
    }
}

// ---------------- cpb MLP ----------------
__global__ void cpb_kernel(const float* __restrict__ rct,
                           const float* __restrict__ w1, const float* __restrict__ b1,
                           const float* __restrict__ w2, const float* __restrict__ b2)
{
    int gw = (blockIdx.x * blockDim.x + threadIdx.x) >> 5;
    int lane = threadIdx.x & 31;
    if (gw >= LTAB) return;
    float r0 = rct[gw * 2], r1 = rct[gw * 2 + 1];
    float acc[HEADS];
#pragma unroll
    for (int h = 0; h < HEADS; h++) acc[h] = 0.f;
    for (int j = lane; j < 512; j += 32) {
        float hv = fmaxf(r0 * w1[j] + r1 * w1[512 + j] + b1[j], 0.f);
#pragma unroll
        for (int h = 0; h < HEADS; h++) acc[h] += hv * w2[j * HEADS + h];
    }
#pragma unroll
    for (int h = 0; h < HEADS; h++)
#pragma unroll
        for (int o = 16; o; o >>= 1) acc[h] += __shfl_xor_sync(0xffffffffu, acc[h], o);
    if (lane == 0) {
#pragma unroll
        for (int h = 0; h < HEADS; h++) g_tab[gw * HEADS + h] = acc[h] + b2[h];
    }
}

// ---------------- fused attention: tiled halo in smem ----------------
// block = (b,h) x 4x28-pixel tile; halo = 6x30; 8 warps x 14 pixels
constexpr int TR = 4, TC = 28, HR = 6, HC = 30;
constexpr int KST = 36;  // float stride per halo/pool row

struct AttnSmem {
    float k_halo[HR * HC * KST];
    float v_halo[HR * HC * KST];
    float kp[PLEN * KST];
    float vp[PLEN * KST];
    float lt[LOCAL * KST];       // transposed: [l][d]
    float q  [8][HD];
    float qn [8][HD];
    float a9 [8][12];
    float ap [8][52];
    float rpb[LOCAL];
    float lb [LOCAL];
};

__global__ __launch_bounds__(256)
void attn_kernel(const int* __restrict__ rpi,
                 const float* __restrict__ rpb_local,
                 const float* __restrict__ ltok,
                 const float* __restrict__ lbias)
{
    extern __shared__ char smem_raw[];
    AttnSmem& sm = *reinterpret_cast<AttnSmem*>(smem_raw);

    int bh = blockIdx.x;
    int b = bh / HEADS, h = bh % HEADS;
    int ty = blockIdx.y;
    int tr0 = (ty % 14) * TR;
    int tc0 = (ty / 14) * TC;
    int tid = threadIdx.x, warp = tid >> 5, lane = tid & 31;

    const float* k_base  = g_k  + (size_t)bh * N0 * HD;
    const float* v_base  = g_v  + (size_t)bh * N0 * HD;

    // stage halo K/V (6x30 rows, zero-filled OOB), float4 granularity
    for (int f = tid; f < HR * HC * 16; f += 256) {
        int row = f >> 4;
        int rem = f & 15;
        int mat = rem >> 3;
        int c4  = rem & 7;
        int hr = row / HC, hc = row % HC;
        int gr = tr0 - 1 + hr, gc = tc0 - 1 + hc;
        bool ok = (gr >= 0 && gr < H0 && gc >= 0 && gc < W0);
        float4 val = make_float4(0.f, 0.f, 0.f, 0.f);
        if (ok) {
            const float* src = mat ? v_base : k_base;
            val = *reinterpret_cast<const float4*>(&src[(size_t)(gr * W0 + gc) * HD + c4 * 4]);
        }
        float* dst = mat ? sm.v_halo : sm.k_halo;
        *reinterpret_cast<float4*>(&dst[row * KST + c4 * 4]) = val;
    }
    // stage pooled K/V
    {
        const float* kpsrc = g_kp + (size_t)bh * PLEN * HD;
        const float* vpsrc = g_vp + (size_t)bh * PLEN * HD;
        for (int f = tid; f < PLEN * 16; f += 256) {
            int m = f >> 4, rem = f & 15, mat = rem >> 3, c4 = rem & 7;
            const float* src = mat ? vpsrc : kpsrc;
            float4 val = *reinterpret_cast<const float4*>(&src[(size_t)m * HD + c4 * 4]);
            float* dst = mat ? sm.vp : sm.kp;
            *reinterpret_cast<float4*>(&dst[m * KST + c4 * 4]) = val;
        }
    }
    // learnable tokens transposed [l][d]
    for (int i = tid; i < HD * LOCAL; i += 256) {
        int d = i / LOCAL, l = i % LOCAL;
        sm.lt[l * KST + d] = ltok[h * HD * LOCAL + i];
    }
    if (tid < LOCAL) {
        sm.rpb[tid] = rpb_local[h * LOCAL + tid];
        sm.lb[tid]  = lbias[h * LOCAL + tid];
    }
    __syncthreads();

    const float* qs_base = g_qs + (size_t)bh * N0 * HD;
    const float* qn_base = g_qn + (size_t)bh * N0 * HD;

    int li  = (lane < LOCAL) ? lane : 0;
    int mi1 = (lane < 17) ? lane + 32 : 0;
    int ldi = li / 3 - 1, ldj = li % 3 - 1;

    for (int it = 0; it < 14; it++) {
        int p  = warp * 14 + it;
        int lr = p / TC, lc = p % TC;          // tile-local coords
        int pi = tr0 + lr, pj = tc0 + lc;
        int n  = pi * W0 + pj;

        // stage q for broadcast reads
        sm.q [warp][lane] = qs_base[(size_t)n * HD + lane];
        sm.qn[warp][lane] = qn_base[(size_t)n * HD + lane];
        __syncwarp();

        // per-lane local-key halo row (lanes 0..8 meaningful)
        int hrow = (lr + 1 + ldi) * HC + (lc + 1 + ldj);
        bool lvalid = (lane < LOCAL) &&
                      (pi + ldi >= 0) && (pi + ldi < H0) &&
                      (pj + ldj >= 0) && (pj + ldj < W0);

        float pb0 = g_tab[rpi[n * PLEN + lane] * HEADS + h];
        float pb1 = (lane < 17) ? g_tab[rpi[n * PLEN + 32 + lane] * HEADS + h] : 0.f;

        float s9 = 0.f, sp0 = 0.f, sp1 = 0.f, tl = 0.f;
        const float* krow  = &sm.k_halo[hrow * KST];
        const float* kp0r  = &sm.kp[lane * KST];
        const float* kp1r  = &sm.kp[mi1 * KST];
        const float* ltr   = &sm.lt[li * KST];
#pragma unroll
        for (int c = 0; c < 8; c++) {
            float4 q4  = *reinterpret_cast<const float4*>(&sm.q [warp][c * 4]);
            float4 qn4 = *reinterpret_cast<const float4*>(&sm.qn[warp][c * 4]);
            float4 k9  = *reinterpret_cast<const float4*>(&krow[c * 4]);
            float4 p0  = *reinterpret_cast<const float4*>(&kp0r[c * 4]);
            float4 p1  = *reinterpret_cast<const float4*>(&kp1r[c * 4]);
            float4 l4  = *reinterpret_cast<const float4*>(&ltr [c * 4]);
            s9  += q4.x * k9.x + q4.y * k9.y + q4.z * k9.z + q4.w * k9.w;
            sp0 += q4.x * p0.x + q4.y * p0.y + q4.z * p0.z + q4.w * p0.w;
            sp1 += q4.x * p1.x + q4.y * p1.y + q4.z * p1.z + q4.w * p1.w;
            tl  += qn4.x * l4.x + qn4.y * l4.y + qn4.z * l4.z + qn4.w * l4.w;
        }

        s9  = lvalid ? (s9 + sm.rpb[lane]) : NEGV;
        sp0 += pb0;
        sp1 = (lane < 17) ? (sp1 + pb1) : NEGV;

        float mx = fmaxf(s9, fmaxf(sp0, sp1));
#pragma unroll
        for (int o = 16; o; o >>= 1) mx = fmaxf(mx, __shfl_xor_sync(0xffffffffu, mx, o));
        float e9 = expf(s9 - mx), e0 = expf(sp0 - mx), e1 = expf(sp1 - mx);
        float sum = e9 + e0 + e1;
#pragma unroll
        for (int o = 16; o; o >>= 1) sum += __shfl_xor_sync(0xffffffffu, sum, o);
        float inv = 1.f / sum;

        if (lane < LOCAL) sm.a9[warp][lane] = e9 * inv + tl + sm.lb[lane];
        sm.ap[warp][lane] = e0 * inv;
        if (lane < 17) sm.ap[warp][32 + lane] = e1 * inv;
        __syncwarp();

        // output accumulation: local 9 keys from halo, 49 pooled keys
        float out = 0.f;
        int hbase = (lr + 1) * HC + (lc + 1);
#pragma unroll
        for (int l = 0; l < LOCAL; l++) {
            int di = l / 3 - 1, dj = l % 3 - 1;
            out += sm.a9[warp][l] * sm.v_halo[(hbase + di * HC + dj) * KST + lane];
        }
#pragma unroll
        for (int g = 0; g < 12; g++) {
            float4 a4 = *reinterpret_cast<const float4*>(&sm.ap[warp][g * 4]);
            out += a4.x * sm.vp[(g * 4 + 0) * KST + lane];
            out += a4.y * sm.vp[(g * 4 + 1) * KST + lane];
            out += a4.z * sm.vp[(g * 4 + 2) * KST + lane];
            out += a4.w * sm.vp[(g * 4 + 3) * KST + lane];
        }
        out += sm.ap[warp][48] * sm.vp[48 * KST + lane];

        float nbv = __shfl_down_sync(0xffffffffu, out, 1);
        if ((lane & 1) == 0) {
            uint32_t hi, lo;
            split2(out, nbv, hi, lo);
            size_t base = ((size_t)(b * N0 + n)) * 128 + h * 16 + (lane >> 1);
            g_xoH[base] = hi;
            g_xoL[base] = lo;
        }
        __syncwarp();
    }
}

// ---------------- launch ----------------
extern "C" void kernel_launch(void* const* d_in, const int* in_sizes, int n_in,
                              void* d_out, int out_size)
{
    const float* x      = (const float*)d_in[0];
    const float* sls    = (const float*)d_in[1];
    const float* rct    = (const float*)d_in[2];
    const float* q_w    = (const float*)d_in[3];
    const float* q_b    = (const float*)d_in[4];
    const float* qe     = (const float*)d_in[5];
    const float* temp   = (const float*)d_in[6];
    const float* kv_w   = (const float*)d_in[7];
    const float* kv_b   = (const float*)d_in[8];
    const float* sr_w   = (const float*)d_in[9];
    const float* sr_b   = (const float*)d_in[10];
    const float* norm_g = (const float*)d_in[11];
    const float* norm_b = (const float*)d_in[12];
    const float* fc1_w  = (const float*)d_in[13];
    const float* fc1_b  = (const float*)d_in[14];
    const float* fc2_w  = (const float*)d_in[15];
    const float* fc2_b  = (const float*)d_in[16];
    const float* rpb    = (const float*)d_in[17];
    const float* lt     = (const float*)d_in[18];
    const float* lb     = (const float*)d_in[19];
    const float* proj_w = (const float*)d_in[20];
    const float* proj_b = (const float*)d_in[21];
    const int*   rpi    = (const int*)d_in[22];
    float* out = (float*)d_out;

    static bool attr_set = false;
    if (!attr_set) {
        cudaFuncSetAttribute(attn_kernel, cudaFuncAttributeMaxDynamicSharedMemorySize,
                             (int)sizeof(AttnSmem));
        attr_set = true;
    }

    // 1) cpb table MLP (independent — placed first so gemm1 is the 4th launch)
    cpb_kernel<<<LTAB / 8, 256>>>(rct, fc1_w, fc1_b, fc2_w, fc2_b);

    // 2-3) operand conversion
    convert_x_kernel<<<MROWS * DIM / 4 / 256, 256>>>(x);
    convert_w_kernel<<<1280 * 128 / 256, 256>>>(q_w, kv_w, sr_w, proj_w);

    // 4) fused GEMM1 (profiled slot)
    dim3 g1(MROWS / 128, 1024 / 128);
    gemm_mma_kernel<0><<<g1, 256>>>(q_b, kv_b, sr_b, qe, temp, sls, nullptr);

    // 5) pool + layernorm
    pool_ln_kernel<<<B_ * PLEN, 256>>>(norm_g, norm_b);

    // 6) kvp mini-GEMM
    kvp_kernel<<<dim3(B_ * PLEN / 4, 2), 256>>>(kv_w, kv_b);

    // 7) fused attention (tiled halo)
    attn_kernel<<<dim3(B_ * HEADS, 28), 256, sizeof(AttnSmem)>>>(rpi, rpb, lt, lb);

    // 8) proj GEMM -> d_out
    dim3 g7(MROWS / 128, 256 / 128);
    gemm_mma_kernel<1><<<g7, 256>>>(proj_b, nullptr, nullptr, nullptr, nullptr, nullptr, out);
}

// round 5
// speedup vs baseline: 1.4607x; 1.0465x over previous
#include <cuda_runtime.h>
#include <cuda_bf16.h>
#include <math.h>
#include <stdint.h>

// ---------------- problem constants (all static) ----------------
constexpr int B_    = 8;
constexpr int H0    = 56;
constexpr int W0    = 56;
constexpr int N0    = H0 * W0;        // 3136
constexpr int DIM   = 256;
constexpr int HEADS = 8;
constexpr int HD    = 32;
constexpr int LOCAL = 9;
constexpr int PW    = 7;
constexpr int PLEN  = 49;
constexpr int LTAB  = 4096;
constexpr int MROWS = B_ * N0;        // 25088
constexpr float NEGV = -1e9f;

// ---------------- scratch (device globals; no allocs) ----------------
__device__ float g_qs[B_*HEADS*N0*HD];
__device__ float g_qn[B_*HEADS*N0*HD];
__device__ float g_k [B_*HEADS*N0*HD];
__device__ float g_v [B_*HEADS*N0*HD];
__device__ float g_xs[B_*N0*DIM];
__device__ float g_kp[B_*HEADS*PLEN*HD];
__device__ float g_vp[B_*HEADS*PLEN*HD];
__device__ float g_tab[LTAB*HEADS];

// packed bf16 hi/lo operands (u32 = 2 bf16 along k)
__device__ uint32_t g_xH [MROWS*128];
__device__ uint32_t g_xL [MROWS*128];
__device__ uint32_t g_xoH[MROWS*128];
__device__ uint32_t g_xoL[MROWS*128];
__device__ uint32_t g_wH [1280*128];     // fused W [col][k2]: q|k|v|sr|proj
__device__ uint32_t g_wL [1280*128];

// ---------------- helpers ----------------
__device__ __forceinline__ uint32_t pack_bf2(__nv_bfloat16 x, __nv_bfloat16 y) {
    __nv_bfloat162 t; t.x = x; t.y = y;
    return *reinterpret_cast<uint32_t*>(&t);
}
__device__ __forceinline__ void split2(float x, float y, uint32_t& hi, uint32_t& lo) {
    __nv_bfloat16 xh = __float2bfloat16_rn(x);
    __nv_bfloat16 yh = __float2bfloat16_rn(y);
    float xr = x - __bfloat162float(xh);
    float yr = y - __bfloat162float(yh);
    hi = pack_bf2(xh, yh);
    lo = pack_bf2(__float2bfloat16_rn(xr), __float2bfloat16_rn(yr));
}

#define MMA16816(d, a0,a1,a2,a3, b0,b1) \
    asm volatile("mma.sync.aligned.m16n8k16.row.col.f32.bf16.bf16.f32 " \
        "{%0,%1,%2,%3},{%4,%5,%6,%7},{%8,%9},{%0,%1,%2,%3};" \
        : "+f"(d[0]), "+f"(d[1]), "+f"(d[2]), "+f"(d[3]) \
        : "r"(a0), "r"(a1), "r"(a2), "r"(a3), "r"(b0), "r"(b1))

#define LDSM4(r, addr) \
    asm volatile("ldmatrix.sync.aligned.m8n8.x4.shared.b16 {%0,%1,%2,%3}, [%4];" \
        : "=r"((r)[0]), "=r"((r)[1]), "=r"((r)[2]), "=r"((r)[3]) : "r"(addr))

__device__ __forceinline__ void cp16(uint32_t dst, const void* src) {
    asm volatile("cp.async.cg.shared.global [%0], [%1], 16;" :: "r"(dst), "l"(src));
}

// ---------------- fused pre-kernel: convert x, convert W, cpb MLP ----------------
constexpr int NBLK_CX = MROWS * DIM / 4 / 256;   // 6272
constexpr int NBLK_CW = 1280 * 128 / 256;        // 640
constexpr int NBLK_CPB = LTAB / 8;               // 512

__global__ __launch_bounds__(256)
void pre_kernel(const float* __restrict__ x,
                const float* __restrict__ q_w, const float* __restrict__ kv_w,
                const float* __restrict__ sr_w, const float* __restrict__ proj_w,
                const float* __restrict__ rct,
                const float* __restrict__ w1, const float* __restrict__ b1,
                const float* __restrict__ w2, const float* __restrict__ b2)
{
    int blk = blockIdx.x, tid = threadIdx.x;
    if (blk < NBLK_CX) {
        int i = blk * 256 + tid;
        float4 v = reinterpret_cast<const float4*>(x)[i];
        uint32_t h0, l0, h1, l1;
        split2(v.x, v.y, h0, l0);
        split2(v.z, v.w, h1, l1);
        g_xH[i * 2] = h0; g_xH[i * 2 + 1] = h1;
        g_xL[i * 2] = l0; g_xL[i * 2 + 1] = l1;
    } else if (blk < NBLK_CX + NBLK_CW) {
        int idx = (blk - NBLK_CX) * 256 + tid;
        int c = idx >> 7, k2 = idx & 127;
        float f0, f1;
        if (c < 256)       { f0 = q_w [(2*k2)   * 256 + c];        f1 = q_w [(2*k2+1) * 256 + c];        }
        else if (c < 768)  { f0 = kv_w[(2*k2)   * 512 + c - 256];  f1 = kv_w[(2*k2+1) * 512 + c - 256];  }
        else if (c < 1024) { f0 = sr_w[(2*k2)   * 256 + c - 768];  f1 = sr_w[(2*k2+1) * 256 + c - 768];  }
        else               { f0 = proj_w[(2*k2) * 256 + c - 1024]; f1 = proj_w[(2*k2+1) * 256 + c - 1024]; }
        uint32_t h, l;
        split2(f0, f1, h, l);
        g_wH[idx] = h; g_wL[idx] = l;
    } else {
        int gw = ((blk - NBLK_CX - NBLK_CW) * 256 + tid) >> 5;
        int lane = tid & 31;
        float r0 = rct[gw * 2], r1 = rct[gw * 2 + 1];
        float acc[HEADS];
#pragma unroll
        for (int h = 0; h < HEADS; h++) acc[h] = 0.f;
        for (int j = lane; j < 512; j += 32) {
            float hv = fmaxf(r0 * w1[j] + r1 * w1[512 + j] + b1[j], 0.f);
#pragma unroll
            for (int h = 0; h < HEADS; h++) acc[h] += hv * w2[j * HEADS + h];
        }
#pragma unroll
        for (int h = 0; h < HEADS; h++)
#pragma unroll
            for (int o = 16; o; o >>= 1) acc[h] += __shfl_xor_sync(0xffffffffu, acc[h], o);
        if (lane == 0) {
#pragma unroll
            for (int h = 0; h < HEADS; h++) g_tab[gw * HEADS + h] = acc[h] + b2[h];
        }
    }
}

// ---------------- bf16x3 tensor-core GEMM: ldmatrix + cp.async double buffer ----------------
constexpr int LDU = 20;                          // u32 row stride
constexpr uint32_t SM_AL = 10240;                // byte offsets within stage
constexpr uint32_t SM_BH = 20480;
constexpr uint32_t SM_BL = 30720;
constexpr uint32_t SM_STAGE = 40960;
constexpr int GEMM_SMEM = 81920;

template<int MODE>
__global__ __launch_bounds__(256)
void gemm_mma_kernel(const float* __restrict__ bq, const float* __restrict__ bkv,
                     const float* __restrict__ bsr,
                     const float* __restrict__ qe, const float* __restrict__ temp,
                     const float* __restrict__ sls,
                     float* __restrict__ Out)
{
    extern __shared__ uint32_t sm_u[];
    uint32_t sbase = (uint32_t)__cvta_generic_to_shared(sm_u);

    const uint32_t* AH = MODE ? g_xoH : g_xH;
    const uint32_t* AL = MODE ? g_xoL : g_xL;

    int tid  = threadIdx.x;
    int lane = tid & 31;
    int warp = tid >> 5;
    int wm   = warp >> 2;
    int wn   = warp & 3;

    int m0    = blockIdx.x * 128;
    int col0  = blockIdx.y * 128;
    int bcol0 = col0 + (MODE ? 1024 : 0);

    int lrow = tid >> 1;
    int loff = (tid & 1) * 8;
    uint32_t dstb = (uint32_t)(lrow * LDU + loff) * 4;

    const uint32_t* aHp = &AH  [(size_t)(m0 + lrow)    * 128 + loff];
    const uint32_t* aLp = &AL  [(size_t)(m0 + lrow)    * 128 + loff];
    const uint32_t* bHp = &g_wH[(size_t)(bcol0 + lrow) * 128 + loff];
    const uint32_t* bLp = &g_wL[(size_t)(bcol0 + lrow) * 128 + loff];

    // ldmatrix per-warp offsets
    int aRow  = wm * 64 + (lane & 7) + ((lane >> 3) & 1) * 8;
    int aCol4 = ((lane >> 4) & 1) * 4;
    uint32_t aoff[4][2];
#pragma unroll
    for (int mt = 0; mt < 4; mt++)
#pragma unroll
        for (int s = 0; s < 2; s++)
            aoff[mt][s] = (uint32_t)(((aRow + mt * 16) * LDU) + s * 8 + aCol4) * 4;
    int bRow  = wn * 32 + (lane & 7);
    int bCol4 = ((lane >> 3) & 3) * 4;
    uint32_t boff[4];
#pragma unroll
    for (int nt = 0; nt < 4; nt++)
        boff[nt] = (uint32_t)(((bRow + nt * 8) * LDU) + bCol4) * 4;

    float acc[4][4][4];
#pragma unroll
    for (int i = 0; i < 4; i++)
#pragma unroll
        for (int j = 0; j < 4; j++)
#pragma unroll
            for (int e = 0; e < 4; e++) acc[i][j][e] = 0.f;

#define ISSUE_STAGE(it, buf) do { \
    uint32_t st_ = sbase + (uint32_t)(buf) * SM_STAGE + dstb; \
    cp16(st_,              aHp + (it) * 16); \
    cp16(st_ + 16,         aHp + (it) * 16 + 4); \
    cp16(st_ + SM_AL,      aLp + (it) * 16); \
    cp16(st_ + SM_AL + 16, aLp + (it) * 16 + 4); \
    cp16(st_ + SM_BH,      bHp + (it) * 16); \
    cp16(st_ + SM_BH + 16, bHp + (it) * 16 + 4); \
    cp16(st_ + SM_BL,      bLp + (it) * 16); \
    cp16(st_ + SM_BL + 16, bLp + (it) * 16 + 4); \
    asm volatile("cp.async.commit_group;"); \
} while (0)

    ISSUE_STAGE(0, 0);

    for (int it = 0; it < 8; it++) {
        int buf = it & 1;
        if (it < 7) {
            ISSUE_STAGE(it + 1, buf ^ 1);
            asm volatile("cp.async.wait_group 1;");
        } else {
            asm volatile("cp.async.wait_group 0;");
        }
        __syncthreads();
        {
            uint32_t st = sbase + (uint32_t)buf * SM_STAGE;
            uint32_t bHf[4][4], bLf[4][4];
#pragma unroll
            for (int nt = 0; nt < 4; nt++) {
                LDSM4(bHf[nt], st + SM_BH + boff[nt]);
                LDSM4(bLf[nt], st + SM_BL + boff[nt]);
            }
#pragma unroll
            for (int s = 0; s < 2; s++) {
                uint32_t aHf[4][4], aLf[4][4];
#pragma unroll
                for (int mt = 0; mt < 4; mt++) {
                    LDSM4(aHf[mt], st + aoff[mt][s]);
                    LDSM4(aLf[mt], st + SM_AL + aoff[mt][s]);
                }
#pragma unroll
                for (int mt = 0; mt < 4; mt++)
#pragma unroll
                    for (int nt = 0; nt < 4; nt++) {
                        MMA16816(acc[mt][nt], aHf[mt][0], aHf[mt][1], aHf[mt][2], aHf[mt][3],
                                 bHf[nt][2*s], bHf[nt][2*s+1]);
                        MMA16816(acc[mt][nt], aHf[mt][0], aHf[mt][1], aHf[mt][2], aHf[mt][3],
                                 bLf[nt][2*s], bLf[nt][2*s+1]);
                        MMA16816(acc[mt][nt], aLf[mt][0], aLf[mt][1], aLf[mt][2], aLf[mt][3],
                                 bHf[nt][2*s], bHf[nt][2*s+1]);
                    }
            }
        }
        __syncthreads();
    }
#undef ISSUE_STAGE

    // ---------------- epilogue ----------------
    if (MODE == 1) {
#pragma unroll
        for (int mt = 0; mt < 4; mt++) {
            int r0 = m0 + wm * 64 + mt * 16 + (lane >> 2);
#pragma unroll
            for (int nt = 0; nt < 4; nt++) {
                int c0 = col0 + wn * 32 + nt * 8 + (lane & 3) * 2;
                Out[(size_t)r0 * DIM + c0]           = acc[mt][nt][0] + bq[c0];
                Out[(size_t)r0 * DIM + c0 + 1]       = acc[mt][nt][1] + bq[c0 + 1];
                Out[(size_t)(r0 + 8) * DIM + c0]     = acc[mt][nt][2] + bq[c0];
                Out[(size_t)(r0 + 8) * DIM + c0 + 1] = acc[mt][nt][3] + bq[c0 + 1];
            }
        }
        return;
    }

    int strip = (col0 + wn * 32) >> 5;
#pragma unroll
    for (int mt = 0; mt < 4; mt++)
#pragma unroll
        for (int nt = 0; nt < 4; nt++) {
            int c = col0 + wn * 32 + nt * 8 + (lane & 3) * 2;
            float b0, b1;
            if (c < 256)      { b0 = bq[c];        b1 = bq[c + 1];    }
            else if (c < 768) { b0 = bkv[c - 256]; b1 = bkv[c - 255]; }
            else              { b0 = bsr[c - 768]; b1 = bsr[c - 767]; }
            acc[mt][nt][0] += b0; acc[mt][nt][1] += b1;
            acc[mt][nt][2] += b0; acc[mt][nt][3] += b1;
        }

    if (strip < 16) {
        int h = strip & 7;
        bool isq = strip < 8;
        float spsls = 0.f;
        if (isq) spsls = log1pf(expf(temp[h])) * sls[0];
#pragma unroll
        for (int mt = 0; mt < 4; mt++) {
            float ss0 = 0.f, ss1 = 0.f;
#pragma unroll
            for (int nt = 0; nt < 4; nt++) {
                ss0 += acc[mt][nt][0] * acc[mt][nt][0] + acc[mt][nt][1] * acc[mt][nt][1];
                ss1 += acc[mt][nt][2] * acc[mt][nt][2] + acc[mt][nt][3] * acc[mt][nt][3];
            }
            ss0 += __shfl_xor_sync(0xffffffffu, ss0, 1);
            ss0 += __shfl_xor_sync(0xffffffffu, ss0, 2);
            ss1 += __shfl_xor_sync(0xffffffffu, ss1, 1);
            ss1 += __shfl_xor_sync(0xffffffffu, ss1, 2);
            float inv0 = 1.f / fmaxf(sqrtf(ss0), 1e-12f);
            float inv1 = 1.f / fmaxf(sqrtf(ss1), 1e-12f);
            int r0 = m0 + wm * 64 + mt * 16 + (lane >> 2);
            int b0i = r0 / N0, n0i = r0 % N0;
            int b1i = (r0 + 8) / N0, n1i = (r0 + 8) % N0;
            size_t base0 = (((size_t)(b0i * HEADS + h)) * N0 + n0i) * HD;
            size_t base1 = (((size_t)(b1i * HEADS + h)) * N0 + n1i) * HD;
#pragma unroll
            for (int nt = 0; nt < 4; nt++) {
                int d0 = (wn * 32 + nt * 8 + (lane & 3) * 2) & 31;
#pragma unroll
                for (int p = 0; p < 2; p++) {
                    int d = d0 + p;
                    float v0 = acc[mt][nt][p]     * inv0;
                    float v1 = acc[mt][nt][2 + p] * inv1;
                    if (isq) {
                        float e = qe[h * HD + d];
                        g_qn[base0 + d] = v0;
                        g_qn[base1 + d] = v1;
                        g_qs[base0 + d] = (v0 + e) * spsls;
                        g_qs[base1 + d] = (v1 + e) * spsls;
                    } else {
                        g_k[base0 + d] = v0;
                        g_k[base1 + d] = v1;
                    }
                }
            }
        }
    } else if (strip < 24) {
        int h = strip & 7;
#pragma unroll
        for (int mt = 0; mt < 4; mt++) {
            int r0 = m0 + wm * 64 + mt * 16 + (lane >> 2);
            int ba = r0 / N0, na = r0 % N0;
            int bb = (r0 + 8) / N0, nb = (r0 + 8) % N0;
            size_t base0 = (((size_t)(ba * HEADS + h)) * N0 + na) * HD;
            size_t base1 = (((size_t)(bb * HEADS + h)) * N0 + nb) * HD;
#pragma unroll
            for (int nt = 0; nt < 4; nt++) {
                int d = (wn * 32 + nt * 8 + (lane & 3) * 2) & 31;
                g_v[base0 + d]     = acc[mt][nt][0];
                g_v[base0 + d + 1] = acc[mt][nt][1];
                g_v[base1 + d]     = acc[mt][nt][2];
                g_v[base1 + d + 1] = acc[mt][nt][3];
            }
        }
    } else {
#pragma unroll
        for (int mt = 0; mt < 4; mt++) {
            int r0 = m0 + wm * 64 + mt * 16 + (lane >> 2);
            int ba = r0 / N0, na = r0 % N0;
            int bb = (r0 + 8) / N0, nb = (r0 + 8) % N0;
#pragma unroll
            for (int nt = 0; nt < 4; nt++) {
                int cc = (wn * 32 + nt * 8 + (lane & 3) * 2) + col0 - 768;
#pragma unroll
                for (int p = 0; p < 2; p++) {
                    float v0 = acc[mt][nt][p];
                    float v1 = acc[mt][nt][2 + p];
                    g_xs[((size_t)(ba * N0 + na)) * DIM + cc + p] =
                        0.5f * v0 * (1.f + erff(v0 * 0.70710678118654752f));
                    g_xs[((size_t)(bb * N0 + nb)) * DIM + cc + p] =
                        0.5f * v1 * (1.f + erff(v1 * 0.70710678118654752f));
                }
            }
        }
    }
}

// ---------------- fused pool + LN + kvp ----------------
// grid (98, 2): 4 pooled rows per block; y=0 -> k cols (normalized), y=1 -> v cols
__global__ __launch_bounds__(256)
void poolkvp_kernel(const float* __restrict__ gamma, const float* __restrict__ beta,
                    const float* __restrict__ kv_w, const float* __restrict__ kv_b)
{
    __shared__ float xr[4][DIM];
    __shared__ float redm[4][8], redv[4][8];
    int bp0 = blockIdx.x * 4;
    int half = blockIdx.y;
    int tid = threadIdx.x, lane = tid & 31, wp = tid >> 5;

    float sv[4];
#pragma unroll
    for (int i = 0; i < 4; i++) {
        int bp = bp0 + i, b = bp / PLEN, p = bp % PLEN;
        int pi = p / PW, pj = p % PW;
        float s = 0.f;
#pragma unroll
        for (int r = 0; r < 8; r++)
#pragma unroll
            for (int c = 0; c < 8; c++)
                s += g_xs[((size_t)(b * N0 + (pi * 8 + r) * W0 + pj * 8 + c)) * DIM + tid];
        sv[i] = s * (1.f / 64.f);
    }
#pragma unroll
    for (int i = 0; i < 4; i++) {
        float m = sv[i];
#pragma unroll
        for (int o = 16; o; o >>= 1) m += __shfl_xor_sync(0xffffffffu, m, o);
        if (lane == 0) redm[i][wp] = m;
    }
    __syncthreads();
    float dv[4];
#pragma unroll
    for (int i = 0; i < 4; i++) {
        float mean = 0.f;
#pragma unroll
        for (int w = 0; w < 8; w++) mean += redm[i][w];
        mean *= (1.f / 256.f);
        dv[i] = sv[i] - mean;
        float v2 = dv[i] * dv[i];
#pragma unroll
        for (int o = 16; o; o >>= 1) v2 += __shfl_xor_sync(0xffffffffu, v2, o);
        if (lane == 0) redv[i][wp] = v2;
    }
    __syncthreads();
#pragma unroll
    for (int i = 0; i < 4; i++) {
        float var = 0.f;
#pragma unroll
        for (int w = 0; w < 8; w++) var += redv[i][w];
        var *= (1.f / 256.f);
        xr[i][tid] = dv[i] * rsqrtf(var + 1e-5f) * gamma[tid] + beta[tid];
    }
    __syncthreads();

    int yoff = half * 256;
    float bb = kv_b[yoff + tid];
    float acc[4];
#pragma unroll
    for (int i = 0; i < 4; i++) acc[i] = bb;

#pragma unroll 8
    for (int kk = 0; kk < DIM; kk++) {
        float w = kv_w[(size_t)kk * 512 + yoff + tid];
#pragma unroll
        for (int i = 0; i < 4; i++) acc[i] = fmaf(xr[i][kk], w, acc[i]);
    }

#pragma unroll
    for (int i = 0; i < 4; i++) {
        int bp = bp0 + i;
        int b = bp / PLEN, p = bp % PLEN;
        size_t dst = (((size_t)(b * HEADS + wp)) * PLEN + p) * HD + lane;
        if (half == 0) {
            float ss = acc[i] * acc[i];
#pragma unroll
            for (int o = 16; o; o >>= 1) ss += __shfl_xor_sync(0xffffffffu, ss, o);
            g_kp[dst] = acc[i] / fmaxf(sqrtf(ss), 1e-12f);
        } else {
            g_vp[dst] = acc[i];
        }
    }
}

// ---------------- fused attention: tiled halo in smem ----------------
constexpr int TR = 4, TC = 28, HR = 6, HC = 30;
constexpr int KST = 36;

struct AttnSmem {
    float k_halo[HR * HC * KST];
    float v_halo[HR * HC * KST];
    float kp[PLEN * KST];
    float vp[PLEN * KST];
    float lt[LOCAL * KST];
    float q  [8][HD];
    float qn [8][HD];
    float a9 [8][12];
    float ap [8][52];
    float rpb[LOCAL];
    float lb [LOCAL];
};

__global__ __launch_bounds__(256)
void attn_kernel(const int* __restrict__ rpi,
                 const float* __restrict__ rpb_local,
                 const float* __restrict__ ltok,
                 const float* __restrict__ lbias)
{
    extern __shared__ char smem_raw[];
    AttnSmem& sm = *reinterpret_cast<AttnSmem*>(smem_raw);

    int bh = blockIdx.x;
    int b = bh / HEADS, h = bh % HEADS;
    int ty = blockIdx.y;
    int tr0 = (ty % 14) * TR;
    int tc0 = (ty / 14) * TC;
    int tid = threadIdx.x, warp = tid >> 5, lane = tid & 31;

    const float* k_base  = g_k  + (size_t)bh * N0 * HD;
    const float* v_base  = g_v  + (size_t)bh * N0 * HD;

    for (int f = tid; f < HR * HC * 16; f += 256) {
        int row = f >> 4;
        int rem = f & 15;
        int mat = rem >> 3;
        int c4  = rem & 7;
        int hr = row / HC, hc = row % HC;
        int gr = tr0 - 1 + hr, gc = tc0 - 1 + hc;
        bool ok = (gr >= 0 && gr < H0 && gc >= 0 && gc < W0);
        float4 val = make_float4(0.f, 0.f, 0.f, 0.f);
        if (ok) {
            const float* src = mat ? v_base : k_base;
            val = *reinterpret_cast<const float4*>(&src[(size_t)(gr * W0 + gc) * HD + c4 * 4]);
        }
        float* dst = mat ? sm.v_halo : sm.k_halo;
        *reinterpret_cast<float4*>(&dst[row * KST + c4 * 4]) = val;
    }
    {
        const float* kpsrc = g_kp + (size_t)bh * PLEN * HD;
        const float* vpsrc = g_vp + (size_t)bh * PLEN * HD;
        for (int f = tid; f < PLEN * 16; f += 256) {
            int m = f >> 4, rem = f & 15, mat = rem >> 3, c4 = rem & 7;
            const float* src = mat ? vpsrc : kpsrc;
            float4 val = *reinterpret_cast<const float4*>(&src[(size_t)m * HD + c4 * 4]);
            float* dst = mat ? sm.vp : sm.kp;
            *reinterpret_cast<float4*>(&dst[m * KST + c4 * 4]) = val;
        }
    }
    for (int i = tid; i < HD * LOCAL; i += 256) {
        int d = i / LOCAL, l = i % LOCAL;
        sm.lt[l * KST + d] = ltok[h * HD * LOCAL + i];
    }
    if (tid < LOCAL) {
        sm.rpb[tid] = rpb_local[h * LOCAL + tid];
        sm.lb[tid]  = lbias[h * LOCAL + tid];
    }
    __syncthreads();

    const float* qs_base = g_qs + (size_t)bh * N0 * HD;
    const float* qn_base = g_qn + (size_t)bh * N0 * HD;

    int li  = (lane < LOCAL) ? lane : 0;
    int mi1 = (lane < 17) ? lane + 32 : 0;
    int ldi = li / 3 - 1, ldj = li % 3 - 1;

    for (int it = 0; it < 14; it++) {
        int p  = warp * 14 + it;
        int lr = p / TC, lc = p % TC;
        int pi = tr0 + lr, pj = tc0 + lc;
        int n  = pi * W0 + pj;

        sm.q [warp][lane] = qs_base[(size_t)n * HD + lane];
        sm.qn[warp][lane] = qn_base[(size_t)n * HD + lane];
        __syncwarp();

        int hrow = (lr + 1 + ldi) * HC + (lc + 1 + ldj);
        bool lvalid = (lane < LOCAL) &&
                      (pi + ldi >= 0) && (pi + ldi < H0) &&
                      (pj + ldj >= 0) && (pj + ldj < W0);

        float pb0 = g_tab[rpi[n * PLEN + lane] * HEADS + h];
        float pb1 = (lane < 17) ? g_tab[rpi[n * PLEN + 32 + lane] * HEADS + h] : 0.f;

        float s9 = 0.f, sp0 = 0.f, sp1 = 0.f, tl = 0.f;
        const float* krow  = &sm.k_halo[hrow * KST];
        const float* kp0r  = &sm.kp[lane * KST];
        const float* kp1r  = &sm.kp[mi1 * KST];
        const float* ltr   = &sm.lt[li * KST];
#pragma unroll
        for (int c = 0; c < 8; c++) {
            float4 q4  = *reinterpret_cast<const float4*>(&sm.q [warp][c * 4]);
            float4 qn4 = *reinterpret_cast<const float4*>(&sm.qn[warp][c * 4]);
            float4 k9  = *reinterpret_cast<const float4*>(&krow[c * 4]);
            float4 p0  = *reinterpret_cast<const float4*>(&kp0r[c * 4]);
            float4 p1  = *reinterpret_cast<const float4*>(&kp1r[c * 4]);
            float4 l4  = *reinterpret_cast<const float4*>(&ltr [c * 4]);
            s9  += q4.x * k9.x + q4.y * k9.y + q4.z * k9.z + q4.w * k9.w;
            sp0 += q4.x * p0.x + q4.y * p0.y + q4.z * p0.z + q4.w * p0.w;
            sp1 += q4.x * p1.x + q4.y * p1.y + q4.z * p1.z + q4.w * p1.w;
            tl  += qn4.x * l4.x + qn4.y * l4.y + qn4.z * l4.z + qn4.w * l4.w;
        }

        s9  = lvalid ? (s9 + sm.rpb[lane]) : NEGV;
        sp0 += pb0;
        sp1 = (lane < 17) ? (sp1 + pb1) : NEGV;

        float mx = fmaxf(s9, fmaxf(sp0, sp1));
#pragma unroll
        for (int o = 16; o; o >>= 1) mx = fmaxf(mx, __shfl_xor_sync(0xffffffffu, mx, o));
        float e9 = expf(s9 - mx), e0 = expf(sp0 - mx), e1 = expf(sp1 - mx);
        float sum = e9 + e0 + e1;
#pragma unroll
        for (int o = 16; o; o >>= 1) sum += __shfl_xor_sync(0xffffffffu, sum, o);
        float inv = 1.f / sum;

        if (lane < LOCAL) sm.a9[warp][lane] = e9 * inv + tl + sm.lb[lane];
        sm.ap[warp][lane] = e0 * inv;
        if (lane < 17) sm.ap[warp][32 + lane] = e1 * inv;
        __syncwarp();

        float out = 0.f;
        int hbase = (lr + 1) * HC + (lc + 1);
#pragma unroll
        for (int l = 0; l < LOCAL; l++) {
            int di = l / 3 - 1, dj = l % 3 - 1;
            out += sm.a9[warp][l] * sm.v_halo[(hbase + di * HC + dj) * KST + lane];
        }
#pragma unroll
        for (int g = 0; g < 12; g++) {
            float4 a4 = *reinterpret_cast<const float4*>(&sm.ap[warp][g * 4]);
            out += a4.x * sm.vp[(g * 4 + 0) * KST + lane];
            out += a4.y * sm.vp[(g * 4 + 1) * KST + lane];
            out += a4.z * sm.vp[(g * 4 + 2) * KST + lane];
            out += a4.w * sm.vp[(g * 4 + 3) * KST + lane];
        }
        out += sm.ap[warp][48] * sm.vp[48 * KST + lane];

        float nbv = __shfl_down_sync(0xffffffffu, out, 1);
        if ((lane & 1) == 0) {
            uint32_t hi, lo;
            split2(out, nbv, hi, lo);
            size_t base = ((size_t)(b * N0 + n)) * 128 + h * 16 + (lane >> 1);
            g_xoH[base] = hi;
            g_xoL[base] = lo;
        }
        __syncwarp();
    }
}

// ---------------- launch ----------------
extern "C" void kernel_launch(void* const* d_in, const int* in_sizes, int n_in,
                              void* d_out, int out_size)
{
    const float* x      = (const float*)d_in[0];
    const float* sls    = (const float*)d_in[1];
    const float* rct    = (const float*)d_in[2];
    const float* q_w    = (const float*)d_in[3];
    const float* q_b    = (const float*)d_in[4];
    const float* qe     = (const float*)d_in[5];
    const float* temp   = (const float*)d_in[6];
    const float* kv_w   = (const float*)d_in[7];
    const float* kv_b   = (const float*)d_in[8];
    const float* sr_w   = (const float*)d_in[9];
    const float* sr_b   = (const float*)d_in[10];
    const float* norm_g = (const float*)d_in[11];
    const float* norm_b = (const float*)d_in[12];
    const float* fc1_w  = (const float*)d_in[13];
    const float* fc1_b  = (const float*)d_in[14];
    const float* fc2_w  = (const float*)d_in[15];
    const float* fc2_b  = (const float*)d_in[16];
    const float* rpb    = (const float*)d_in[17];
    const float* lt     = (const float*)d_in[18];
    const float* lb     = (const float*)d_in[19];
    const float* proj_w = (const float*)d_in[20];
    const float* proj_b = (const float*)d_in[21];
    const int*   rpi    = (const int*)d_in[22];
    float* out = (float*)d_out;

    cudaFuncSetAttribute(gemm_mma_kernel<0>, cudaFuncAttributeMaxDynamicSharedMemorySize, GEMM_SMEM);
    cudaFuncSetAttribute(gemm_mma_kernel<1>, cudaFuncAttributeMaxDynamicSharedMemorySize, GEMM_SMEM);
    cudaFuncSetAttribute(attn_kernel, cudaFuncAttributeMaxDynamicSharedMemorySize, (int)sizeof(AttnSmem));

    // 1) fused pre-kernel: convert x + convert W + cpb table
    pre_kernel<<<NBLK_CX + NBLK_CW + NBLK_CPB, 256>>>(x, q_w, kv_w, sr_w, proj_w,
                                                      rct, fc1_w, fc1_b, fc2_w, fc2_b);

    // 2) fused GEMM1 (q/k norm + gelu epilogue)
    dim3 g1(MROWS / 128, 1024 / 128);
    gemm_mma_kernel<0><<<g1, 256, GEMM_SMEM>>>(q_b, kv_b, sr_b, qe, temp, sls, nullptr);

    // 3) fused pool + LN + kvp
    poolkvp_kernel<<<dim3(B_ * PLEN / 4, 2), 256>>>(norm_g, norm_b, kv_w, kv_b);

    // 4) fused attention (profiled slot)
    attn_kernel<<<dim3(B_ * HEADS, 28), 256, sizeof(AttnSmem)>>>(rpi, rpb, lt, lb);

    // 5) proj GEMM -> d_out
    dim3 g7(MROWS / 128, 256 / 128);
    gemm_mma_kernel<1><<<g7, 256, GEMM_SMEM>>>(proj_b, nullptr, nullptr, nullptr, nullptr, nullptr, out);
}

// round 6
// speedup vs baseline: 1.5596x; 1.0677x over previous
#include <cuda_runtime.h>
#include <cuda_bf16.h>
#include <math.h>
#include <stdint.h>

// ---------------- problem constants (all static) ----------------
constexpr int B_    = 8;
constexpr int H0    = 56;
constexpr int W0    = 56;
constexpr int N0    = H0 * W0;        // 3136
constexpr int DIM   = 256;
constexpr int HEADS = 8;
constexpr int HD    = 32;
constexpr int LOCAL = 9;
constexpr int PW    = 7;
constexpr int PLEN  = 49;
constexpr int LTAB  = 4096;
constexpr int MROWS = B_ * N0;        // 25088
constexpr float NEGV = -1e9f;

// ---------------- scratch (device globals; no allocs) ----------------
__device__ float g_qs[B_*HEADS*N0*HD];
__device__ float g_qn[B_*HEADS*N0*HD];
__device__ float g_k [B_*HEADS*N0*HD];
__device__ float g_v [B_*HEADS*N0*HD];
__device__ float g_xs[B_*N0*DIM];
__device__ float g_kp[B_*HEADS*PLEN*HD];
__device__ float g_vp[B_*HEADS*PLEN*HD];
__device__ float g_tab[LTAB*HEADS];

// packed bf16 hi/lo operands (u32 = 2 bf16 along k)
__device__ uint32_t g_xH [MROWS*128];
__device__ uint32_t g_xL [MROWS*128];
__device__ uint32_t g_xoH[MROWS*128];
__device__ uint32_t g_xoL[MROWS*128];
__device__ uint32_t g_wH [1280*128];     // fused W [col][k2]: q|k|v|sr|proj
__device__ uint32_t g_wL [1280*128];

// ---------------- helpers ----------------
__device__ __forceinline__ uint32_t pack_bf2(__nv_bfloat16 x, __nv_bfloat16 y) {
    __nv_bfloat162 t; t.x = x; t.y = y;
    return *reinterpret_cast<uint32_t*>(&t);
}
__device__ __forceinline__ void split2(float x, float y, uint32_t& hi, uint32_t& lo) {
    __nv_bfloat16 xh = __float2bfloat16_rn(x);
    __nv_bfloat16 yh = __float2bfloat16_rn(y);
    float xr = x - __bfloat162float(xh);
    float yr = y - __bfloat162float(yh);
    hi = pack_bf2(xh, yh);
    lo = pack_bf2(__float2bfloat16_rn(xr), __float2bfloat16_rn(yr));
}

#define MMA16816(d, a0,a1,a2,a3, b0,b1) \
    asm volatile("mma.sync.aligned.m16n8k16.row.col.f32.bf16.bf16.f32 " \
        "{%0,%1,%2,%3},{%4,%5,%6,%7},{%8,%9},{%0,%1,%2,%3};" \
        : "+f"(d[0]), "+f"(d[1]), "+f"(d[2]), "+f"(d[3]) \
        : "r"(a0), "r"(a1), "r"(a2), "r"(a3), "r"(b0), "r"(b1))

#define LDSM4(r, addr) \
    asm volatile("ldmatrix.sync.aligned.m8n8.x4.shared.b16 {%0,%1,%2,%3}, [%4];" \
        : "=r"((r)[0]), "=r"((r)[1]), "=r"((r)[2]), "=r"((r)[3]) : "r"(addr))

__device__ __forceinline__ void cp16(uint32_t dst, const void* src) {
    asm volatile("cp.async.cg.shared.global [%0], [%1], 16;" :: "r"(dst), "l"(src));
}

#define DOT4(acc, a, b) (acc) += (a).x*(b).x + (a).y*(b).y + (a).z*(b).z + (a).w*(b).w

// ---------------- conversion kernels (split so gemm1 is 4th launch) ----------------
__global__ __launch_bounds__(256)
void convert_x_kernel(const float* __restrict__ x)
{
    int i = blockIdx.x * 256 + threadIdx.x;
    float4 v = reinterpret_cast<const float4*>(x)[i];
    uint32_t h0, l0, h1, l1;
    split2(v.x, v.y, h0, l0);
    split2(v.z, v.w, h1, l1);
    g_xH[i * 2] = h0; g_xH[i * 2 + 1] = h1;
    g_xL[i * 2] = l0; g_xL[i * 2 + 1] = l1;
}

__global__ __launch_bounds__(256)
void convert_w_kernel(const float* __restrict__ q_w, const float* __restrict__ kv_w,
                      const float* __restrict__ sr_w, const float* __restrict__ proj_w)
{
    int idx = blockIdx.x * 256 + threadIdx.x;        // 1280*128
    int c = idx >> 7, k2 = idx & 127;
    float f0, f1;
    if (c < 256)       { f0 = q_w [(2*k2)   * 256 + c];        f1 = q_w [(2*k2+1) * 256 + c];        }
    else if (c < 768)  { f0 = kv_w[(2*k2)   * 512 + c - 256];  f1 = kv_w[(2*k2+1) * 512 + c - 256];  }
    else if (c < 1024) { f0 = sr_w[(2*k2)   * 256 + c - 768];  f1 = sr_w[(2*k2+1) * 256 + c - 768];  }
    else               { f0 = proj_w[(2*k2) * 256 + c - 1024]; f1 = proj_w[(2*k2+1) * 256 + c - 1024]; }
    uint32_t h, l;
    split2(f0, f1, h, l);
    g_wH[idx] = h; g_wL[idx] = l;
}

__global__ void cpb_kernel(const float* __restrict__ rct,
                           const float* __restrict__ w1, const float* __restrict__ b1,
                           const float* __restrict__ w2, const float* __restrict__ b2)
{
    int gw = (blockIdx.x * blockDim.x + threadIdx.x) >> 5;
    int lane = threadIdx.x & 31;
    if (gw >= LTAB) return;
    float r0 = rct[gw * 2], r1 = rct[gw * 2 + 1];
    float acc[HEADS];
#pragma unroll
    for (int h = 0; h < HEADS; h++) acc[h] = 0.f;
    for (int j = lane; j < 512; j += 32) {
        float hv = fmaxf(r0 * w1[j] + r1 * w1[512 + j] + b1[j], 0.f);
#pragma unroll
        for (int h = 0; h < HEADS; h++) acc[h] += hv * w2[j * HEADS + h];
    }
#pragma unroll
    for (int h = 0; h < HEADS; h++)
#pragma unroll
        for (int o = 16; o; o >>= 1) acc[h] += __shfl_xor_sync(0xffffffffu, acc[h], o);
    if (lane == 0) {
#pragma unroll
        for (int h = 0; h < HEADS; h++) g_tab[gw * HEADS + h] = acc[h] + b2[h];
    }
}

// ---------------- bf16x3 tensor-core GEMM: ldmatrix + cp.async double buffer ----------------
constexpr int LDU = 20;
constexpr uint32_t SM_AL = 10240;
constexpr uint32_t SM_BH = 20480;
constexpr uint32_t SM_BL = 30720;
constexpr uint32_t SM_STAGE = 40960;
constexpr int GEMM_SMEM = 81920;

template<int MODE>
__global__ __launch_bounds__(256)
void gemm_mma_kernel(const float* __restrict__ bq, const float* __restrict__ bkv,
                     const float* __restrict__ bsr,
                     const float* __restrict__ qe, const float* __restrict__ temp,
                     const float* __restrict__ sls,
                     float* __restrict__ Out)
{
    extern __shared__ uint32_t sm_u[];
    uint32_t sbase = (uint32_t)__cvta_generic_to_shared(sm_u);

    const uint32_t* AH = MODE ? g_xoH : g_xH;
    const uint32_t* AL = MODE ? g_xoL : g_xL;

    int tid  = threadIdx.x;
    int lane = tid & 31;
    int warp = tid >> 5;
    int wm   = warp >> 2;
    int wn   = warp & 3;

    int m0    = blockIdx.x * 128;
    int col0  = blockIdx.y * 128;
    int bcol0 = col0 + (MODE ? 1024 : 0);

    int lrow = tid >> 1;
    int loff = (tid & 1) * 8;
    uint32_t dstb = (uint32_t)(lrow * LDU + loff) * 4;

    const uint32_t* aHp = &AH  [(size_t)(m0 + lrow)    * 128 + loff];
    const uint32_t* aLp = &AL  [(size_t)(m0 + lrow)    * 128 + loff];
    const uint32_t* bHp = &g_wH[(size_t)(bcol0 + lrow) * 128 + loff];
    const uint32_t* bLp = &g_wL[(size_t)(bcol0 + lrow) * 128 + loff];

    int aRow  = wm * 64 + (lane & 7) + ((lane >> 3) & 1) * 8;
    int aCol4 = ((lane >> 4) & 1) * 4;
    uint32_t aoff[4][2];
#pragma unroll
    for (int mt = 0; mt < 4; mt++)
#pragma unroll
        for (int s = 0; s < 2; s++)
            aoff[mt][s] = (uint32_t)(((aRow + mt * 16) * LDU) + s * 8 + aCol4) * 4;
    int bRow  = wn * 32 + (lane & 7);
    int bCol4 = ((lane >> 3) & 3) * 4;
    uint32_t boff[4];
#pragma unroll
    for (int nt = 0; nt < 4; nt++)
        boff[nt] = (uint32_t)(((bRow + nt * 8) * LDU) + bCol4) * 4;

    float acc[4][4][4];
#pragma unroll
    for (int i = 0; i < 4; i++)
#pragma unroll
        for (int j = 0; j < 4; j++)
#pragma unroll
            for (int e = 0; e < 4; e++) acc[i][j][e] = 0.f;

#define ISSUE_STAGE(it, buf) do { \
    uint32_t st_ = sbase + (uint32_t)(buf) * SM_STAGE + dstb; \
    cp16(st_,              aHp + (it) * 16); \
    cp16(st_ + 16,         aHp + (it) * 16 + 4); \
    cp16(st_ + SM_AL,      aLp + (it) * 16); \
    cp16(st_ + SM_AL + 16, aLp + (it) * 16 + 4); \
    cp16(st_ + SM_BH,      bHp + (it) * 16); \
    cp16(st_ + SM_BH + 16, bHp + (it) * 16 + 4); \
    cp16(st_ + SM_BL,      bLp + (it) * 16); \
    cp16(st_ + SM_BL + 16, bLp + (it) * 16 + 4); \
    asm volatile("cp.async.commit_group;"); \
} while (0)

    ISSUE_STAGE(0, 0);

    for (int it = 0; it < 8; it++) {
        int buf = it & 1;
        if (it < 7) {
            ISSUE_STAGE(it + 1, buf ^ 1);
            asm volatile("cp.async.wait_group 1;");
        } else {
            asm volatile("cp.async.wait_group 0;");
        }
        __syncthreads();
        {
            uint32_t st = sbase + (uint32_t)buf * SM_STAGE;
            uint32_t bHf[4][4], bLf[4][4];
#pragma unroll
            for (int nt = 0; nt < 4; nt++) {
                LDSM4(bHf[nt], st + SM_BH + boff[nt]);
                LDSM4(bLf[nt], st + SM_BL + boff[nt]);
            }
#pragma unroll
            for (int s = 0; s < 2; s++) {
                uint32_t aHf[4][4], aLf[4][4];
#pragma unroll
                for (int mt = 0; mt < 4; mt++) {
                    LDSM4(aHf[mt], st + aoff[mt][s]);
                    LDSM4(aLf[mt], st + SM_AL + aoff[mt][s]);
                }
#pragma unroll
                for (int mt = 0; mt < 4; mt++)
#pragma unroll
                    for (int nt = 0; nt < 4; nt++) {
                        MMA16816(acc[mt][nt], aHf[mt][0], aHf[mt][1], aHf[mt][2], aHf[mt][3],
                                 bHf[nt][2*s], bHf[nt][2*s+1]);
                        MMA16816(acc[mt][nt], aHf[mt][0], aHf[mt][1], aHf[mt][2], aHf[mt][3],
                                 bLf[nt][2*s], bLf[nt][2*s+1]);
                        MMA16816(acc[mt][nt], aLf[mt][0], aLf[mt][1], aLf[mt][2], aLf[mt][3],
                                 bHf[nt][2*s], bHf[nt][2*s+1]);
                    }
            }
        }
        __syncthreads();
    }
#undef ISSUE_STAGE

    if (MODE == 1) {
#pragma unroll
        for (int mt = 0; mt < 4; mt++) {
            int r0 = m0 + wm * 64 + mt * 16 + (lane >> 2);
#pragma unroll
            for (int nt = 0; nt < 4; nt++) {
                int c0 = col0 + wn * 32 + nt * 8 + (lane & 3) * 2;
                Out[(size_t)r0 * DIM + c0]           = acc[mt][nt][0] + bq[c0];
                Out[(size_t)r0 * DIM + c0 + 1]       = acc[mt][nt][1] + bq[c0 + 1];
                Out[(size_t)(r0 + 8) * DIM + c0]     = acc[mt][nt][2] + bq[c0];
                Out[(size_t)(r0 + 8) * DIM + c0 + 1] = acc[mt][nt][3] + bq[c0 + 1];
            }
        }
        return;
    }

    int strip = (col0 + wn * 32) >> 5;
#pragma unroll
    for (int mt = 0; mt < 4; mt++)
#pragma unroll
        for (int nt = 0; nt < 4; nt++) {
            int c = col0 + wn * 32 + nt * 8 + (lane & 3) * 2;
            float b0, b1;
            if (c < 256)      { b0 = bq[c];        b1 = bq[c + 1];    }
            else if (c < 768) { b0 = bkv[c - 256]; b1 = bkv[c - 255]; }
            else              { b0 = bsr[c - 768]; b1 = bsr[c - 767]; }
            acc[mt][nt][0] += b0; acc[mt][nt][1] += b1;
            acc[mt][nt][2] += b0; acc[mt][nt][3] += b1;
        }

    if (strip < 16) {
        int h = strip & 7;
        bool isq = strip < 8;
        float spsls = 0.f;
        if (isq) spsls = log1pf(expf(temp[h])) * sls[0];
#pragma unroll
        for (int mt = 0; mt < 4; mt++) {
            float ss0 = 0.f, ss1 = 0.f;
#pragma unroll
            for (int nt = 0; nt < 4; nt++) {
                ss0 += acc[mt][nt][0] * acc[mt][nt][0] + acc[mt][nt][1] * acc[mt][nt][1];
                ss1 += acc[mt][nt][2] * acc[mt][nt][2] + acc[mt][nt][3] * acc[mt][nt][3];
            }
            ss0 += __shfl_xor_sync(0xffffffffu, ss0, 1);
            ss0 += __shfl_xor_sync(0xffffffffu, ss0, 2);
            ss1 += __shfl_xor_sync(0xffffffffu, ss1, 1);
            ss1 += __shfl_xor_sync(0xffffffffu, ss1, 2);
            float inv0 = 1.f / fmaxf(sqrtf(ss0), 1e-12f);
            float inv1 = 1.f / fmaxf(sqrtf(ss1), 1e-12f);
            int r0 = m0 + wm * 64 + mt * 16 + (lane >> 2);
            int b0i = r0 / N0, n0i = r0 % N0;
            int b1i = (r0 + 8) / N0, n1i = (r0 + 8) % N0;
            size_t base0 = (((size_t)(b0i * HEADS + h)) * N0 + n0i) * HD;
            size_t base1 = (((size_t)(b1i * HEADS + h)) * N0 + n1i) * HD;
#pragma unroll
            for (int nt = 0; nt < 4; nt++) {
                int d0 = (wn * 32 + nt * 8 + (lane & 3) * 2) & 31;
#pragma unroll
                for (int p = 0; p < 2; p++) {
                    int d = d0 + p;
                    float v0 = acc[mt][nt][p]     * inv0;
                    float v1 = acc[mt][nt][2 + p] * inv1;
                    if (isq) {
                        float e = qe[h * HD + d];
                        g_qn[base0 + d] = v0;
                        g_qn[base1 + d] = v1;
                        g_qs[base0 + d] = (v0 + e) * spsls;
                        g_qs[base1 + d] = (v1 + e) * spsls;
                    } else {
                        g_k[base0 + d] = v0;
                        g_k[base1 + d] = v1;
                    }
                }
            }
        }
    } else if (strip < 24) {
        int h = strip & 7;
#pragma unroll
        for (int mt = 0; mt < 4; mt++) {
            int r0 = m0 + wm * 64 + mt * 16 + (lane >> 2);
            int ba = r0 / N0, na = r0 % N0;
            int bb = (r0 + 8) / N0, nb = (r0 + 8) % N0;
            size_t base0 = (((size_t)(ba * HEADS + h)) * N0 + na) * HD;
            size_t base1 = (((size_t)(bb * HEADS + h)) * N0 + nb) * HD;
#pragma unroll
            for (int nt = 0; nt < 4; nt++) {
                int d = (wn * 32 + nt * 8 + (lane & 3) * 2) & 31;
                g_v[base0 + d]     = acc[mt][nt][0];
                g_v[base0 + d + 1] = acc[mt][nt][1];
                g_v[base1 + d]     = acc[mt][nt][2];
                g_v[base1 + d + 1] = acc[mt][nt][3];
            }
        }
    } else {
#pragma unroll
        for (int mt = 0; mt < 4; mt++) {
            int r0 = m0 + wm * 64 + mt * 16 + (lane >> 2);
            int ba = r0 / N0, na = r0 % N0;
            int bb = (r0 + 8) / N0, nb = (r0 + 8) % N0;
#pragma unroll
            for (int nt = 0; nt < 4; nt++) {
                int cc = (wn * 32 + nt * 8 + (lane & 3) * 2) + col0 - 768;
#pragma unroll
                for (int p = 0; p < 2; p++) {
                    float v0 = acc[mt][nt][p];
                    float v1 = acc[mt][nt][2 + p];
                    g_xs[((size_t)(ba * N0 + na)) * DIM + cc + p] =
                        0.5f * v0 * (1.f + erff(v0 * 0.70710678118654752f));
                    g_xs[((size_t)(bb * N0 + nb)) * DIM + cc + p] =
                        0.5f * v1 * (1.f + erff(v1 * 0.70710678118654752f));
                }
            }
        }
    }
}

// ---------------- fused pool + LN + kvp ----------------
__global__ __launch_bounds__(256)
void poolkvp_kernel(const float* __restrict__ gamma, const float* __restrict__ beta,
                    const float* __restrict__ kv_w, const float* __restrict__ kv_b)
{
    __shared__ float xr[4][DIM];
    __shared__ float redm[4][8], redv[4][8];
    int bp0 = blockIdx.x * 4;
    int half = blockIdx.y;
    int tid = threadIdx.x, lane = tid & 31, wp = tid >> 5;

    float sv[4];
#pragma unroll
    for (int i = 0; i < 4; i++) {
        int bp = bp0 + i, b = bp / PLEN, p = bp % PLEN;
        int pi = p / PW, pj = p % PW;
        float s = 0.f;
#pragma unroll
        for (int r = 0; r < 8; r++)
#pragma unroll
            for (int c = 0; c < 8; c++)
                s += g_xs[((size_t)(b * N0 + (pi * 8 + r) * W0 + pj * 8 + c)) * DIM + tid];
        sv[i] = s * (1.f / 64.f);
    }
#pragma unroll
    for (int i = 0; i < 4; i++) {
        float m = sv[i];
#pragma unroll
        for (int o = 16; o; o >>= 1) m += __shfl_xor_sync(0xffffffffu, m, o);
        if (lane == 0) redm[i][wp] = m;
    }
    __syncthreads();
    float dv[4];
#pragma unroll
    for (int i = 0; i < 4; i++) {
        float mean = 0.f;
#pragma unroll
        for (int w = 0; w < 8; w++) mean += redm[i][w];
        mean *= (1.f / 256.f);
        dv[i] = sv[i] - mean;
        float v2 = dv[i] * dv[i];
#pragma unroll
        for (int o = 16; o; o >>= 1) v2 += __shfl_xor_sync(0xffffffffu, v2, o);
        if (lane == 0) redv[i][wp] = v2;
    }
    __syncthreads();
#pragma unroll
    for (int i = 0; i < 4; i++) {
        float var = 0.f;
#pragma unroll
        for (int w = 0; w < 8; w++) var += redv[i][w];
        var *= (1.f / 256.f);
        xr[i][tid] = dv[i] * rsqrtf(var + 1e-5f) * gamma[tid] + beta[tid];
    }
    __syncthreads();

    int yoff = half * 256;
    float bb = kv_b[yoff + tid];
    float acc[4];
#pragma unroll
    for (int i = 0; i < 4; i++) acc[i] = bb;

#pragma unroll 8
    for (int kk = 0; kk < DIM; kk++) {
        float w = kv_w[(size_t)kk * 512 + yoff + tid];
#pragma unroll
        for (int i = 0; i < 4; i++) acc[i] = fmaf(xr[i][kk], w, acc[i]);
    }

#pragma unroll
    for (int i = 0; i < 4; i++) {
        int bp = bp0 + i;
        int b = bp / PLEN, p = bp % PLEN;
        size_t dst = (((size_t)(b * HEADS + wp)) * PLEN + p) * HD + lane;
        if (half == 0) {
            float ss = acc[i] * acc[i];
#pragma unroll
            for (int o = 16; o; o >>= 1) ss += __shfl_xor_sync(0xffffffffu, ss, o);
            g_kp[dst] = acc[i] / fmaxf(sqrtf(ss), 1e-12f);
        } else {
            g_vp[dst] = acc[i];
        }
    }
}

// ---------------- fused attention: quad-pixel, tiled halo ----------------
constexpr int TR = 4, TC = 28, HR = 6, HC = 30;
constexpr int KST = 36;
constexpr int QST = 36;   // q/qn row stride (conflict-free for 2-group reads)

struct AttnSmem {
    float k_halo[HR * HC * KST];
    float v_halo[HR * HC * KST];
    float kp[PLEN * KST];
    float vp[PLEN * KST];
    float lt[LOCAL * KST];
    float q  [8][4][QST];
    float qn [8][4][QST];
    float a9 [8][4][12];
    float ap [8][4][52];
    float rpb[LOCAL];
    float lb [LOCAL];
};

__global__ __launch_bounds__(256)
void attn_kernel(const int* __restrict__ rpi,
                 const float* __restrict__ rpb_local,
                 const float* __restrict__ ltok,
                 const float* __restrict__ lbias)
{
    extern __shared__ char smem_raw[];
    AttnSmem& sm = *reinterpret_cast<AttnSmem*>(smem_raw);

    int bh = blockIdx.x;
    int b = bh / HEADS, h = bh % HEADS;
    int ty = blockIdx.y;
    int tr0 = (ty % 14) * TR;
    int tc0 = (ty / 14) * TC;
    int tid = threadIdx.x, warp = tid >> 5, lane = tid & 31;

    const float* k_base = g_k + (size_t)bh * N0 * HD;
    const float* v_base = g_v + (size_t)bh * N0 * HD;

    // stage halo K/V (6x30 rows, zero-filled OOB)
    for (int f = tid; f < HR * HC * 16; f += 256) {
        int row = f >> 4;
        int rem = f & 15;
        int mat = rem >> 3;
        int c4  = rem & 7;
        int hr = row / HC, hc = row % HC;
        int gr = tr0 - 1 + hr, gc = tc0 - 1 + hc;
        bool ok = (gr >= 0 && gr < H0 && gc >= 0 && gc < W0);
        float4 val = make_float4(0.f, 0.f, 0.f, 0.f);
        if (ok) {
            const float* src = mat ? v_base : k_base;
            val = *reinterpret_cast<const float4*>(&src[(size_t)(gr * W0 + gc) * HD + c4 * 4]);
        }
        float* dst = mat ? sm.v_halo : sm.k_halo;
        *reinterpret_cast<float4*>(&dst[row * KST + c4 * 4]) = val;
    }
    {
        const float* kpsrc = g_kp + (size_t)bh * PLEN * HD;
        const float* vpsrc = g_vp + (size_t)bh * PLEN * HD;
        for (int f = tid; f < PLEN * 16; f += 256) {
            int m = f >> 4, rem = f & 15, mat = rem >> 3, c4 = rem & 7;
            const float* src = mat ? vpsrc : kpsrc;
            float4 val = *reinterpret_cast<const float4*>(&src[(size_t)m * HD + c4 * 4]);
            float* dst = mat ? sm.vp : sm.kp;
            *reinterpret_cast<float4*>(&dst[m * KST + c4 * 4]) = val;
        }
    }
    for (int i = tid; i < HD * LOCAL; i += 256) {
        int d = i / LOCAL, l = i % LOCAL;
        sm.lt[l * KST + d] = ltok[h * HD * LOCAL + i];
    }
    if (tid < LOCAL) {
        sm.rpb[tid] = rpb_local[h * LOCAL + tid];
        sm.lb[tid]  = lbias[h * LOCAL + tid];
    }
    __syncthreads();

    const float* qs_base = g_qs + (size_t)bh * N0 * HD;
    const float* qn_base = g_qn + (size_t)bh * N0 * HD;

    int lr = warp & 3;
    int colbase = (warp >> 2) * 14;
    int pi = tr0 + lr;

    int grp  = lane >> 4;           // 0: lanes 0-15, 1: lanes 16-31
    int ll   = lane & 15;
    bool lact = ll < LOCAL;
    int lidx = lact ? ll : 0;
    int ldi = lidx / 3 - 1, ldj = lidx % 3 - 1;
    int mi1 = (lane < 17) ? lane + 32 : 0;

    for (int j = 0; j < 4; j++) {
        int lc[4];
#pragma unroll
        for (int i = 0; i < 4; i++) lc[i] = colbase + j * 4 + i;
        int npix = 4;
        if (j == 3) { npix = 2; lc[2] = lc[0]; lc[3] = lc[1]; }
        int n[4], pj[4];
#pragma unroll
        for (int i = 0; i < 4; i++) { pj[i] = tc0 + lc[i]; n[i] = pi * W0 + pj[i]; }

        // stage q / qn
#pragma unroll
        for (int i = 0; i < 4; i++) {
            sm.q [warp][i][lane] = qs_base[(size_t)n[i] * HD + lane];
            sm.qn[warp][i][lane] = qn_base[(size_t)n[i] * HD + lane];
        }
        __syncwarp();

        int pxA = grp, pxB = 2 + grp;
        int hrowA = lact ? ((lr + 1 + ldi) * HC + (lc[pxA] + 1 + ldj)) : 0;
        int hrowB = lact ? ((lr + 1 + ldi) * HC + (lc[pxB] + 1 + ldj)) : 0;

        float sp0[4] = {0,0,0,0}, sp1[4] = {0,0,0,0};
        float s9A = 0.f, s9B = 0.f, tlE = 0.f, tlO = 0.f;

#pragma unroll
        for (int c = 0; c < 8; c++) {
            float4 q0 = *reinterpret_cast<const float4*>(&sm.q[warp][0][c * 4]);
            float4 q1 = *reinterpret_cast<const float4*>(&sm.q[warp][1][c * 4]);
            float4 q2 = *reinterpret_cast<const float4*>(&sm.q[warp][2][c * 4]);
            float4 q3 = *reinterpret_cast<const float4*>(&sm.q[warp][3][c * 4]);
            float4 qnE = *reinterpret_cast<const float4*>(&sm.qn[warp][grp][c * 4]);
            float4 qnO = *reinterpret_cast<const float4*>(&sm.qn[warp][2 + grp][c * 4]);
            float4 kA = *reinterpret_cast<const float4*>(&sm.kp[lane * KST + c * 4]);
            float4 kB = *reinterpret_cast<const float4*>(&sm.kp[mi1 * KST + c * 4]);
            float4 k9A = *reinterpret_cast<const float4*>(&sm.k_halo[hrowA * KST + c * 4]);
            float4 k9B = *reinterpret_cast<const float4*>(&sm.k_halo[hrowB * KST + c * 4]);
            float4 l4 = *reinterpret_cast<const float4*>(&sm.lt[lidx * KST + c * 4]);

            DOT4(sp0[0], kA, q0); DOT4(sp0[1], kA, q1);
            DOT4(sp0[2], kA, q2); DOT4(sp0[3], kA, q3);
            DOT4(sp1[0], kB, q0); DOT4(sp1[1], kB, q1);
            DOT4(sp1[2], kB, q2); DOT4(sp1[3], kB, q3);
            float4 qA = grp ? q1 : q0;
            float4 qB = grp ? q3 : q2;
            DOT4(s9A, k9A, qA);
            DOT4(s9B, k9B, qB);
            DOT4(tlE, l4, qnE);
            DOT4(tlO, l4, qnO);
        }

        // pooled biases
        float pb0[4], pb1[4];
#pragma unroll
        for (int i = 0; i < 4; i++) {
            pb0[i] = g_tab[rpi[n[i] * PLEN + lane] * HEADS + h];
            pb1[i] = (lane < 17) ? g_tab[rpi[n[i] * PLEN + 32 + lane] * HEADS + h] : 0.f;
        }

        bool okA = lact && (pi + ldi >= 0) && (pi + ldi < H0) &&
                   (pj[pxA] + ldj >= 0) && (pj[pxA] + ldj < W0);
        bool okB = lact && (pi + ldi >= 0) && (pi + ldi < H0) &&
                   (pj[pxB] + ldj >= 0) && (pj[pxB] + ldj < W0);
        float s9Af = okA ? s9A + sm.rpb[lidx] : NEGV;
        float s9Bf = okB ? s9B + sm.rpb[lidx] : NEGV;

        float e0[4], e1[4], el[4], inv[4];
#pragma unroll
        for (int i = 0; i < 4; i++) {
            float loc = ((i & 1) == grp) ? (i < 2 ? s9Af : s9Bf) : NEGV;
            float sp0v = sp0[i] + pb0[i];
            float sp1v = (lane < 17) ? sp1[i] + pb1[i] : NEGV;
            float r = fmaxf(sp0v, fmaxf(sp1v, loc));
#pragma unroll
            for (int o = 16; o; o >>= 1) r = fmaxf(r, __shfl_xor_sync(0xffffffffu, r, o));
            e0[i] = expf(sp0v - r);
            e1[i] = (lane < 17) ? expf(sp1v - r) : 0.f;
            el[i] = ((i & 1) == grp && lact) ? expf(loc - r) : 0.f;
            float s = e0[i] + e1[i] + el[i];
#pragma unroll
            for (int o = 16; o; o >>= 1) s += __shfl_xor_sync(0xffffffffu, s, o);
            inv[i] = 1.f / s;
        }

        // store probabilities
#pragma unroll
        for (int i = 0; i < 4; i++) {
            sm.ap[warp][i][lane] = e0[i] * inv[i];
            if (lane < 17) sm.ap[warp][i][32 + lane] = e1[i] * inv[i];
        }
        if (lact) {
            sm.a9[warp][pxA][lidx] = el[pxA] * inv[pxA] + tlE + sm.lb[lidx];
            sm.a9[warp][pxB][lidx] = el[pxB] * inv[pxB] + tlO + sm.lb[lidx];
        }
        __syncwarp();

        // ---- AV ----
        float out[4] = {0.f, 0.f, 0.f, 0.f};
#pragma unroll
        for (int g = 0; g < 12; g++) {
            float4 a0 = *reinterpret_cast<const float4*>(&sm.ap[warp][0][g * 4]);
            float4 a1 = *reinterpret_cast<const float4*>(&sm.ap[warp][1][g * 4]);
            float4 a2 = *reinterpret_cast<const float4*>(&sm.ap[warp][2][g * 4]);
            float4 a3 = *reinterpret_cast<const float4*>(&sm.ap[warp][3][g * 4]);
            float v0 = sm.vp[(g * 4 + 0) * KST + lane];
            float v1 = sm.vp[(g * 4 + 1) * KST + lane];
            float v2 = sm.vp[(g * 4 + 2) * KST + lane];
            float v3 = sm.vp[(g * 4 + 3) * KST + lane];
            out[0] += a0.x * v0 + a0.y * v1 + a0.z * v2 + a0.w * v3;
            out[1] += a1.x * v0 + a1.y * v1 + a1.z * v2 + a1.w * v3;
            out[2] += a2.x * v0 + a2.y * v1 + a2.z * v2 + a2.w * v3;
            out[3] += a3.x * v0 + a3.y * v1 + a3.z * v2 + a3.w * v3;
        }
        {
            float v = sm.vp[48 * KST + lane];
#pragma unroll
            for (int i = 0; i < 4; i++) out[i] += sm.ap[warp][i][48] * v;
        }
        int hb[4];
#pragma unroll
        for (int i = 0; i < 4; i++) hb[i] = (lr + 1) * HC + lc[i] + 1;
#pragma unroll
        for (int l = 0; l < LOCAL; l++) {
            int roff = (l / 3 - 1) * HC + (l % 3 - 1);
#pragma unroll
            for (int i = 0; i < 4; i++) {
                out[i] += sm.a9[warp][i][l] * sm.v_halo[(hb[i] + roff) * KST + lane];
            }
        }

        // store split bf16 output
#pragma unroll
        for (int i = 0; i < 4; i++) {
            if (j == 3 && i >= 2) break;
            float o = out[i];
            float nb = __shfl_down_sync(0xffffffffu, o, 1);
            if ((lane & 1) == 0) {
                uint32_t hi, lo;
                split2(o, nb, hi, lo);
                size_t base = ((size_t)(b * N0 + n[i])) * 128 + h * 16 + (lane >> 1);
                g_xoH[base] = hi;
                g_xoL[base] = lo;
            }
        }
        __syncwarp();
    }
}

// ---------------- launch ----------------
extern "C" void kernel_launch(void* const* d_in, const int* in_sizes, int n_in,
                              void* d_out, int out_size)
{
    const float* x      = (const float*)d_in[0];
    const float* sls    = (const float*)d_in[1];
    const float* rct    = (const float*)d_in[2];
    const float* q_w    = (const float*)d_in[3];
    const float* q_b    = (const float*)d_in[4];
    const float* qe     = (const float*)d_in[5];
    const float* temp   = (const float*)d_in[6];
    const float* kv_w   = (const float*)d_in[7];
    const float* kv_b   = (const float*)d_in[8];
    const float* sr_w   = (const float*)d_in[9];
    const float* sr_b   = (const float*)d_in[10];
    const float* norm_g = (const float*)d_in[11];
    const float* norm_b = (const float*)d_in[12];
    const float* fc1_w  = (const float*)d_in[13];
    const float* fc1_b  = (const float*)d_in[14];
    const float* fc2_w  = (const float*)d_in[15];
    const float* fc2_b  = (const float*)d_in[16];
    const float* rpb    = (const float*)d_in[17];
    const float* lt     = (const float*)d_in[18];
    const float* lb     = (const float*)d_in[19];
    const float* proj_w = (const float*)d_in[20];
    const float* proj_b = (const float*)d_in[21];
    const int*   rpi    = (const int*)d_in[22];
    float* out = (float*)d_out;

    cudaFuncSetAttribute(gemm_mma_kernel<0>, cudaFuncAttributeMaxDynamicSharedMemorySize, GEMM_SMEM);
    cudaFuncSetAttribute(gemm_mma_kernel<1>, cudaFuncAttributeMaxDynamicSharedMemorySize, GEMM_SMEM);
    cudaFuncSetAttribute(attn_kernel, cudaFuncAttributeMaxDynamicSharedMemorySize, (int)sizeof(AttnSmem));

    // 1-3) conversions + cpb (separate so gemm1 is 4th = profiled)
    convert_x_kernel<<<MROWS * DIM / 4 / 256, 256>>>(x);
    convert_w_kernel<<<1280 * 128 / 256, 256>>>(q_w, kv_w, sr_w, proj_w);
    cpb_kernel<<<LTAB / 8, 256>>>(rct, fc1_w, fc1_b, fc2_w, fc2_b);

    // 4) fused GEMM1 (profiled slot)
    dim3 g1(MROWS / 128, 1024 / 128);
    gemm_mma_kernel<0><<<g1, 256, GEMM_SMEM>>>(q_b, kv_b, sr_b, qe, temp, sls, nullptr);

    // 5) fused pool + LN + kvp
    poolkvp_kernel<<<dim3(B_ * PLEN / 4, 2), 256>>>(norm_g, norm_b, kv_w, kv_b);

    // 6) fused attention (quad-pixel)
    attn_kernel<<<dim3(B_ * HEADS, 28), 256, sizeof(AttnSmem)>>>(rpi, rpb, lt, lb);

    // 7) proj GEMM -> d_out
    dim3 g7(MROWS / 128, 256 / 128);
    gemm_mma_kernel<1><<<g7, 256, GEMM_SMEM>>>(proj_b, nullptr, nullptr, nullptr, nullptr, nullptr, out);
}

// round 7
// speedup vs baseline: 1.7037x; 1.0924x over previous
#include <cuda_runtime.h>
#include <cuda_bf16.h>
#include <math.h>
#include <stdint.h>

// ---------------- problem constants (all static) ----------------
constexpr int B_    = 8;
constexpr int H0    = 56;
constexpr int W0    = 56;
constexpr int N0    = H0 * W0;        // 3136
constexpr int DIM   = 256;
constexpr int HEADS = 8;
constexpr int HD    = 32;
constexpr int LOCAL = 9;
constexpr int PW    = 7;
constexpr int PLEN  = 49;
constexpr int LTAB  = 4096;
constexpr int MROWS = B_ * N0;        // 25088
constexpr float NEGV = -1e9f;

// ---------------- scratch (device globals; no allocs) ----------------
__device__ float g_qs[B_*HEADS*N0*HD];
__device__ float g_qn[B_*HEADS*N0*HD];
__device__ float g_k [B_*HEADS*N0*HD];
__device__ float g_v [B_*HEADS*N0*HD];
__device__ float g_xs[B_*N0*DIM];
__device__ float g_kp[B_*HEADS*PLEN*HD];
__device__ float g_vp[B_*HEADS*PLEN*HD];
__device__ float g_tab[LTAB*HEADS];

// packed bf16 hi/lo operands (u32 = 2 bf16 along k)
__device__ uint32_t g_xH [MROWS*128];
__device__ uint32_t g_xL [MROWS*128];
__device__ uint32_t g_xoH[MROWS*128];
__device__ uint32_t g_xoL[MROWS*128];
__device__ uint32_t g_wH [1280*128];     // fused W [col][k2]: q|k|v|sr|proj
__device__ uint32_t g_wL [1280*128];

// ---------------- helpers ----------------
__device__ __forceinline__ uint32_t pack_bf2(__nv_bfloat16 x, __nv_bfloat16 y) {
    __nv_bfloat162 t; t.x = x; t.y = y;
    return *reinterpret_cast<uint32_t*>(&t);
}
__device__ __forceinline__ void split2(float x, float y, uint32_t& hi, uint32_t& lo) {
    __nv_bfloat16 xh = __float2bfloat16_rn(x);
    __nv_bfloat16 yh = __float2bfloat16_rn(y);
    float xr = x - __bfloat162float(xh);
    float yr = y - __bfloat162float(yh);
    hi = pack_bf2(xh, yh);
    lo = pack_bf2(__float2bfloat16_rn(xr), __float2bfloat16_rn(yr));
}

#define MMA16816(d, a0,a1,a2,a3, b0,b1) \
    asm volatile("mma.sync.aligned.m16n8k16.row.col.f32.bf16.bf16.f32 " \
        "{%0,%1,%2,%3},{%4,%5,%6,%7},{%8,%9},{%0,%1,%2,%3};" \
        : "+f"(d[0]), "+f"(d[1]), "+f"(d[2]), "+f"(d[3]) \
        : "r"(a0), "r"(a1), "r"(a2), "r"(a3), "r"(b0), "r"(b1))

#define LDSM4(r, addr) \
    asm volatile("ldmatrix.sync.aligned.m8n8.x4.shared.b16 {%0,%1,%2,%3}, [%4];" \
        : "=r"((r)[0]), "=r"((r)[1]), "=r"((r)[2]), "=r"((r)[3]) : "r"(addr))

__device__ __forceinline__ void cp16(uint32_t dst, const void* src) {
    asm volatile("cp.async.cg.shared.global [%0], [%1], 16;" :: "r"(dst), "l"(src));
}

#define DOT4(acc, a, b) (acc) += (a).x*(b).x + (a).y*(b).y + (a).z*(b).z + (a).w*(b).w

// ---------------- conversion kernels (split so gemm1 is 4th launch) ----------------
__global__ __launch_bounds__(256)
void convert_x_kernel(const float* __restrict__ x)
{
    int i = blockIdx.x * 256 + threadIdx.x;
    float4 v = reinterpret_cast<const float4*>(x)[i];
    uint32_t h0, l0, h1, l1;
    split2(v.x, v.y, h0, l0);
    split2(v.z, v.w, h1, l1);
    g_xH[i * 2] = h0; g_xH[i * 2 + 1] = h1;
    g_xL[i * 2] = l0; g_xL[i * 2 + 1] = l1;
}

__global__ __launch_bounds__(256)
void convert_w_kernel(const float* __restrict__ q_w, const float* __restrict__ kv_w,
                      const float* __restrict__ sr_w, const float* __restrict__ proj_w)
{
    int idx = blockIdx.x * 256 + threadIdx.x;        // 1280*128
    int c = idx >> 7, k2 = idx & 127;
    float f0, f1;
    if (c < 256)       { f0 = q_w [(2*k2)   * 256 + c];        f1 = q_w [(2*k2+1) * 256 + c];        }
    else if (c < 768)  { f0 = kv_w[(2*k2)   * 512 + c - 256];  f1 = kv_w[(2*k2+1) * 512 + c - 256];  }
    else if (c < 1024) { f0 = sr_w[(2*k2)   * 256 + c - 768];  f1 = sr_w[(2*k2+1) * 256 + c - 768];  }
    else               { f0 = proj_w[(2*k2) * 256 + c - 1024]; f1 = proj_w[(2*k2+1) * 256 + c - 1024]; }
    uint32_t h, l;
    split2(f0, f1, h, l);
    g_wH[idx] = h; g_wL[idx] = l;
}

__global__ void cpb_kernel(const float* __restrict__ rct,
                           const float* __restrict__ w1, const float* __restrict__ b1,
                           const float* __restrict__ w2, const float* __restrict__ b2)
{
    int gw = (blockIdx.x * blockDim.x + threadIdx.x) >> 5;
    int lane = threadIdx.x & 31;
    if (gw >= LTAB) return;
    float r0 = rct[gw * 2], r1 = rct[gw * 2 + 1];
    float acc[HEADS];
#pragma unroll
    for (int h = 0; h < HEADS; h++) acc[h] = 0.f;
    for (int j = lane; j < 512; j += 32) {
        float hv = fmaxf(r0 * w1[j] + r1 * w1[512 + j] + b1[j], 0.f);
#pragma unroll
        for (int h = 0; h < HEADS; h++) acc[h] += hv * w2[j * HEADS + h];
    }
#pragma unroll
    for (int h = 0; h < HEADS; h++)
#pragma unroll
        for (int o = 16; o; o >>= 1) acc[h] += __shfl_xor_sync(0xffffffffu, acc[h], o);
    if (lane == 0) {
#pragma unroll
        for (int h = 0; h < HEADS; h++) g_tab[gw * HEADS + h] = acc[h] + b2[h];
    }
}

// ---------------- bf16x3 tensor-core GEMM, 128x64 CTA tile, 2 CTAs/SM ----------------
constexpr int LDU = 20;
constexpr uint32_t SM_AL = 10240;     // A: 128 rows * 20 u32 * 4B = 10240 per matrix
constexpr uint32_t SM_BH = 20480;     // B: 64 rows  * 20 u32 * 4B = 5120 per matrix
constexpr uint32_t SM_BL = 25600;
constexpr uint32_t SM_STAGE = 30720;
constexpr int GEMM_SMEM = 61440;

template<int MODE>
__global__ __launch_bounds__(256, 2)
void gemm_mma_kernel(const float* __restrict__ bq, const float* __restrict__ bkv,
                     const float* __restrict__ bsr,
                     const float* __restrict__ qe, const float* __restrict__ temp,
                     const float* __restrict__ sls,
                     float* __restrict__ Out)
{
    extern __shared__ uint32_t sm_u[];
    uint32_t sbase = (uint32_t)__cvta_generic_to_shared(sm_u);

    const uint32_t* AH = MODE ? g_xoH : g_xH;
    const uint32_t* AL = MODE ? g_xoL : g_xL;

    int tid  = threadIdx.x;
    int lane = tid & 31;
    int warp = tid >> 5;
    int wm   = warp >> 1;                 // 0..3 (32-row strips)
    int wn   = warp & 1;                  // 0..1 (32-col strips)

    int m0    = blockIdx.x * 128;
    int col0  = blockIdx.y * 64;
    int bcol0 = col0 + (MODE ? 1024 : 0);

    // cp.async source/dst mapping
    int lrowA = tid >> 1;                 // 0..127
    int loffA = (tid & 1) * 8;            // 0 / 8
    uint32_t dstA = (uint32_t)(lrowA * LDU + loffA) * 4;
    int lrowB = tid >> 2;                 // 0..63
    int loffB = (tid & 3) * 4;            // 0,4,8,12
    uint32_t dstB = (uint32_t)(lrowB * LDU + loffB) * 4;

    const uint32_t* aHp = &AH  [(size_t)(m0 + lrowA)    * 128 + loffA];
    const uint32_t* aLp = &AL  [(size_t)(m0 + lrowA)    * 128 + loffA];
    const uint32_t* bHp = &g_wH[(size_t)(bcol0 + lrowB) * 128 + loffB];
    const uint32_t* bLp = &g_wL[(size_t)(bcol0 + lrowB) * 128 + loffB];

    // ldmatrix per-warp offsets
    int aRow  = wm * 32 + (lane & 7) + ((lane >> 3) & 1) * 8;
    int aCol4 = ((lane >> 4) & 1) * 4;
    uint32_t aoff[2][2];
#pragma unroll
    for (int mt = 0; mt < 2; mt++)
#pragma unroll
        for (int s = 0; s < 2; s++)
            aoff[mt][s] = (uint32_t)(((aRow + mt * 16) * LDU) + s * 8 + aCol4) * 4;
    int bRow  = wn * 32 + (lane & 7);
    int bCol4 = ((lane >> 3) & 3) * 4;
    uint32_t boff[4];
#pragma unroll
    for (int nt = 0; nt < 4; nt++)
        boff[nt] = (uint32_t)(((bRow + nt * 8) * LDU) + bCol4) * 4;

    float acc[2][4][4];
#pragma unroll
    for (int i = 0; i < 2; i++)
#pragma unroll
        for (int j = 0; j < 4; j++)
#pragma unroll
            for (int e = 0; e < 4; e++) acc[i][j][e] = 0.f;

#define ISSUE_STAGE(it, buf) do { \
    uint32_t st_ = sbase + (uint32_t)(buf) * SM_STAGE; \
    cp16(st_ + dstA,              aHp + (it) * 16); \
    cp16(st_ + dstA + 16,         aHp + (it) * 16 + 4); \
    cp16(st_ + SM_AL + dstA,      aLp + (it) * 16); \
    cp16(st_ + SM_AL + dstA + 16, aLp + (it) * 16 + 4); \
    cp16(st_ + SM_BH + dstB,      bHp + (it) * 16); \
    cp16(st_ + SM_BL + dstB,      bLp + (it) * 16); \
    asm volatile("cp.async.commit_group;"); \
} while (0)

    ISSUE_STAGE(0, 0);

    for (int it = 0; it < 8; it++) {
        int buf = it & 1;
        if (it < 7) {
            ISSUE_STAGE(it + 1, buf ^ 1);
            asm volatile("cp.async.wait_group 1;");
        } else {
            asm volatile("cp.async.wait_group 0;");
        }
        __syncthreads();
        {
            uint32_t st = sbase + (uint32_t)buf * SM_STAGE;
            uint32_t bHf[4][4], bLf[4][4];
#pragma unroll
            for (int nt = 0; nt < 4; nt++) {
                LDSM4(bHf[nt], st + SM_BH + boff[nt]);
                LDSM4(bLf[nt], st + SM_BL + boff[nt]);
            }
#pragma unroll
            for (int s = 0; s < 2; s++) {
                uint32_t aHf[2][4], aLf[2][4];
#pragma unroll
                for (int mt = 0; mt < 2; mt++) {
                    LDSM4(aHf[mt], st + aoff[mt][s]);
                    LDSM4(aLf[mt], st + SM_AL + aoff[mt][s]);
                }
#pragma unroll
                for (int mt = 0; mt < 2; mt++)
#pragma unroll
                    for (int nt = 0; nt < 4; nt++) {
                        MMA16816(acc[mt][nt], aHf[mt][0], aHf[mt][1], aHf[mt][2], aHf[mt][3],
                                 bHf[nt][2*s], bHf[nt][2*s+1]);
                        MMA16816(acc[mt][nt], aHf[mt][0], aHf[mt][1], aHf[mt][2], aHf[mt][3],
                                 bLf[nt][2*s], bLf[nt][2*s+1]);
                        MMA16816(acc[mt][nt], aLf[mt][0], aLf[mt][1], aLf[mt][2], aLf[mt][3],
                                 bHf[nt][2*s], bHf[nt][2*s+1]);
                    }
            }
        }
        __syncthreads();
    }
#undef ISSUE_STAGE

    // ---------------- epilogue ----------------
    if (MODE == 1) {
#pragma unroll
        for (int mt = 0; mt < 2; mt++) {
            int r0 = m0 + wm * 32 + mt * 16 + (lane >> 2);
#pragma unroll
            for (int nt = 0; nt < 4; nt++) {
                int c0 = col0 + wn * 32 + nt * 8 + (lane & 3) * 2;
                Out[(size_t)r0 * DIM + c0]           = acc[mt][nt][0] + bq[c0];
                Out[(size_t)r0 * DIM + c0 + 1]       = acc[mt][nt][1] + bq[c0 + 1];
                Out[(size_t)(r0 + 8) * DIM + c0]     = acc[mt][nt][2] + bq[c0];
                Out[(size_t)(r0 + 8) * DIM + c0 + 1] = acc[mt][nt][3] + bq[c0 + 1];
            }
        }
        return;
    }

    int strip = (col0 + wn * 32) >> 5;     // 0..31
#pragma unroll
    for (int mt = 0; mt < 2; mt++)
#pragma unroll
        for (int nt = 0; nt < 4; nt++) {
            int c = col0 + wn * 32 + nt * 8 + (lane & 3) * 2;
            float b0, b1;
            if (c < 256)      { b0 = bq[c];        b1 = bq[c + 1];    }
            else if (c < 768) { b0 = bkv[c - 256]; b1 = bkv[c - 255]; }
            else              { b0 = bsr[c - 768]; b1 = bsr[c - 767]; }
            acc[mt][nt][0] += b0; acc[mt][nt][1] += b1;
            acc[mt][nt][2] += b0; acc[mt][nt][3] += b1;
        }

    if (strip < 16) {
        int h = strip & 7;
        bool isq = strip < 8;
        float spsls = 0.f;
        if (isq) spsls = log1pf(expf(temp[h])) * sls[0];
#pragma unroll
        for (int mt = 0; mt < 2; mt++) {
            float ss0 = 0.f, ss1 = 0.f;
#pragma unroll
            for (int nt = 0; nt < 4; nt++) {
                ss0 += acc[mt][nt][0] * acc[mt][nt][0] + acc[mt][nt][1] * acc[mt][nt][1];
                ss1 += acc[mt][nt][2] * acc[mt][nt][2] + acc[mt][nt][3] * acc[mt][nt][3];
            }
            ss0 += __shfl_xor_sync(0xffffffffu, ss0, 1);
            ss0 += __shfl_xor_sync(0xffffffffu, ss0, 2);
            ss1 += __shfl_xor_sync(0xffffffffu, ss1, 1);
            ss1 += __shfl_xor_sync(0xffffffffu, ss1, 2);
            float inv0 = 1.f / fmaxf(sqrtf(ss0), 1e-12f);
            float inv1 = 1.f / fmaxf(sqrtf(ss1), 1e-12f);
            int r0 = m0 + wm * 32 + mt * 16 + (lane >> 2);
            int b0i = r0 / N0, n0i = r0 % N0;
            int b1i = (r0 + 8) / N0, n1i = (r0 + 8) % N0;
            size_t base0 = (((size_t)(b0i * HEADS + h)) * N0 + n0i) * HD;
            size_t base1 = (((size_t)(b1i * HEADS + h)) * N0 + n1i) * HD;
#pragma unroll
            for (int nt = 0; nt < 4; nt++) {
                int d0 = (wn * 32 + nt * 8 + (lane & 3) * 2) & 31;
#pragma unroll
                for (int p = 0; p < 2; p++) {
                    int d = d0 + p;
                    float v0 = acc[mt][nt][p]     * inv0;
                    float v1 = acc[mt][nt][2 + p] * inv1;
                    if (isq) {
                        float e = qe[h * HD + d];
                        g_qn[base0 + d] = v0;
                        g_qn[base1 + d] = v1;
                        g_qs[base0 + d] = (v0 + e) * spsls;
                        g_qs[base1 + d] = (v1 + e) * spsls;
                    } else {
                        g_k[base0 + d] = v0;
                        g_k[base1 + d] = v1;
                    }
                }
            }
        }
    } else if (strip < 24) {
        int h = strip & 7;
#pragma unroll
        for (int mt = 0; mt < 2; mt++) {
            int r0 = m0 + wm * 32 + mt * 16 + (lane >> 2);
            int ba = r0 / N0, na = r0 % N0;
            int bb = (r0 + 8) / N0, nb = (r0 + 8) % N0;
            size_t base0 = (((size_t)(ba * HEADS + h)) * N0 + na) * HD;
            size_t base1 = (((size_t)(bb * HEADS + h)) * N0 + nb) * HD;
#pragma unroll
            for (int nt = 0; nt < 4; nt++) {
                int d = (wn * 32 + nt * 8 + (lane & 3) * 2) & 31;
                g_v[base0 + d]     = acc[mt][nt][0];
                g_v[base0 + d + 1] = acc[mt][nt][1];
                g_v[base1 + d]     = acc[mt][nt][2];
                g_v[base1 + d + 1] = acc[mt][nt][3];
            }
        }
    } else {
#pragma unroll
        for (int mt = 0; mt < 2; mt++) {
            int r0 = m0 + wm * 32 + mt * 16 + (lane >> 2);
            int ba = r0 / N0, na = r0 % N0;
            int bb = (r0 + 8) / N0, nb = (r0 + 8) % N0;
#pragma unroll
            for (int nt = 0; nt < 4; nt++) {
                int cc = (wn * 32 + nt * 8 + (lane & 3) * 2) + col0 - 768;
#pragma unroll
                for (int p = 0; p < 2; p++) {
                    float v0 = acc[mt][nt][p];
                    float v1 = acc[mt][nt][2 + p];
                    g_xs[((size_t)(ba * N0 + na)) * DIM + cc + p] =
                        0.5f * v0 * (1.f + erff(v0 * 0.70710678118654752f));
                    g_xs[((size_t)(bb * N0 + nb)) * DIM + cc + p] =
                        0.5f * v1 * (1.f + erff(v1 * 0.70710678118654752f));
                }
            }
        }
    }
}

// ---------------- fused pool + LN + kvp ----------------
__global__ __launch_bounds__(256)
void poolkvp_kernel(const float* __restrict__ gamma, const float* __restrict__ beta,
                    const float* __restrict__ kv_w, const float* __restrict__ kv_b)
{
    __shared__ float xr[4][DIM];
    __shared__ float redm[4][8], redv[4][8];
    int bp0 = blockIdx.x * 4;
    int half = blockIdx.y;
    int tid = threadIdx.x, lane = tid & 31, wp = tid >> 5;

    float sv[4];
#pragma unroll
    for (int i = 0; i < 4; i++) {
        int bp = bp0 + i, b = bp / PLEN, p = bp % PLEN;
        int pi = p / PW, pj = p % PW;
        float s = 0.f;
#pragma unroll
        for (int r = 0; r < 8; r++)
#pragma unroll
            for (int c = 0; c < 8; c++)
                s += g_xs[((size_t)(b * N0 + (pi * 8 + r) * W0 + pj * 8 + c)) * DIM + tid];
        sv[i] = s * (1.f / 64.f);
    }
#pragma unroll
    for (int i = 0; i < 4; i++) {
        float m = sv[i];
#pragma unroll
        for (int o = 16; o; o >>= 1) m += __shfl_xor_sync(0xffffffffu, m, o);
        if (lane == 0) redm[i][wp] = m;
    }
    __syncthreads();
    float dv[4];
#pragma unroll
    for (int i = 0; i < 4; i++) {
        float mean = 0.f;
#pragma unroll
        for (int w = 0; w < 8; w++) mean += redm[i][w];
        mean *= (1.f / 256.f);
        dv[i] = sv[i] - mean;
        float v2 = dv[i] * dv[i];
#pragma unroll
        for (int o = 16; o; o >>= 1) v2 += __shfl_xor_sync(0xffffffffu, v2, o);
        if (lane == 0) redv[i][wp] = v2;
    }
    __syncthreads();
#pragma unroll
    for (int i = 0; i < 4; i++) {
        float var = 0.f;
#pragma unroll
        for (int w = 0; w < 8; w++) var += redv[i][w];
        var *= (1.f / 256.f);
        xr[i][tid] = dv[i] * rsqrtf(var + 1e-5f) * gamma[tid] + beta[tid];
    }
    __syncthreads();

    int yoff = half * 256;
    float bb = kv_b[yoff + tid];
    float acc[4];
#pragma unroll
    for (int i = 0; i < 4; i++) acc[i] = bb;

#pragma unroll 8
    for (int kk = 0; kk < DIM; kk++) {
        float w = kv_w[(size_t)kk * 512 + yoff + tid];
#pragma unroll
        for (int i = 0; i < 4; i++) acc[i] = fmaf(xr[i][kk], w, acc[i]);
    }

#pragma unroll
    for (int i = 0; i < 4; i++) {
        int bp = bp0 + i;
        int b = bp / PLEN, p = bp % PLEN;
        size_t dst = (((size_t)(b * HEADS + wp)) * PLEN + p) * HD + lane;
        if (half == 0) {
            float ss = acc[i] * acc[i];
#pragma unroll
            for (int o = 16; o; o >>= 1) ss += __shfl_xor_sync(0xffffffffu, ss, o);
            g_kp[dst] = acc[i] / fmaxf(sqrtf(ss), 1e-12f);
        } else {
            g_vp[dst] = acc[i];
        }
    }
}

// ---------------- fused attention: quad-pixel, tiled halo ----------------
constexpr int TR = 4, TC = 28, HR = 6, HC = 30;
constexpr int KST = 36;
constexpr int QST = 36;

struct AttnSmem {
    float k_halo[HR * HC * KST];
    float v_halo[HR * HC * KST];
    float kp[PLEN * KST];
    float vp[PLEN * KST];
    float lt[LOCAL * KST];
    float q  [8][4][QST];
    float qn [8][4][QST];
    float a9 [8][4][12];
    float ap [8][4][52];
    float rpb[LOCAL];
    float lb [LOCAL];
};

__global__ __launch_bounds__(256)
void attn_kernel(const int* __restrict__ rpi,
                 const float* __restrict__ rpb_local,
                 const float* __restrict__ ltok,
                 const float* __restrict__ lbias)
{
    extern __shared__ char smem_raw[];
    AttnSmem& sm = *reinterpret_cast<AttnSmem*>(smem_raw);

    int bh = blockIdx.x;
    int b = bh / HEADS, h = bh % HEADS;
    int ty = blockIdx.y;
    int tr0 = (ty % 14) * TR;
    int tc0 = (ty / 14) * TC;
    int tid = threadIdx.x, warp = tid >> 5, lane = tid & 31;

    const float* k_base = g_k + (size_t)bh * N0 * HD;
    const float* v_base = g_v + (size_t)bh * N0 * HD;

    for (int f = tid; f < HR * HC * 16; f += 256) {
        int row = f >> 4;
        int rem = f & 15;
        int mat = rem >> 3;
        int c4  = rem & 7;
        int hr = row / HC, hc = row % HC;
        int gr = tr0 - 1 + hr, gc = tc0 - 1 + hc;
        bool ok = (gr >= 0 && gr < H0 && gc >= 0 && gc < W0);
        float4 val = make_float4(0.f, 0.f, 0.f, 0.f);
        if (ok) {
            const float* src = mat ? v_base : k_base;
            val = *reinterpret_cast<const float4*>(&src[(size_t)(gr * W0 + gc) * HD + c4 * 4]);
        }
        float* dst = mat ? sm.v_halo : sm.k_halo;
        *reinterpret_cast<float4*>(&dst[row * KST + c4 * 4]) = val;
    }
    {
        const float* kpsrc = g_kp + (size_t)bh * PLEN * HD;
        const float* vpsrc = g_vp + (size_t)bh * PLEN * HD;
        for (int f = tid; f < PLEN * 16; f += 256) {
            int m = f >> 4, rem = f & 15, mat = rem >> 3, c4 = rem & 7;
            const float* src = mat ? vpsrc : kpsrc;
            float4 val = *reinterpret_cast<const float4*>(&src[(size_t)m * HD + c4 * 4]);
            float* dst = mat ? sm.vp : sm.kp;
            *reinterpret_cast<float4*>(&dst[m * KST + c4 * 4]) = val;
        }
    }
    for (int i = tid; i < HD * LOCAL; i += 256) {
        int d = i / LOCAL, l = i % LOCAL;
        sm.lt[l * KST + d] = ltok[h * HD * LOCAL + i];
    }
    if (tid < LOCAL) {
        sm.rpb[tid] = rpb_local[h * LOCAL + tid];
        sm.lb[tid]  = lbias[h * LOCAL + tid];
    }
    __syncthreads();

    const float* qs_base = g_qs + (size_t)bh * N0 * HD;
    const float* qn_base = g_qn + (size_t)bh * N0 * HD;

    int lr = warp & 3;
    int colbase = (warp >> 2) * 14;
    int pi = tr0 + lr;

    int grp  = lane >> 4;
    int ll   = lane & 15;
    bool lact = ll < LOCAL;
    int lidx = lact ? ll : 0;
    int ldi = lidx / 3 - 1, ldj = lidx % 3 - 1;
    int mi1 = (lane < 17) ? lane + 32 : 0;

    for (int j = 0; j < 4; j++) {
        int lc[4];
#pragma unroll
        for (int i = 0; i < 4; i++) lc[i] = colbase + j * 4 + i;
        if (j == 3) { lc[2] = lc[0]; lc[3] = lc[1]; }
        int n[4], pj[4];
#pragma unroll
        for (int i = 0; i < 4; i++) { pj[i] = tc0 + lc[i]; n[i] = pi * W0 + pj[i]; }

#pragma unroll
        for (int i = 0; i < 4; i++) {
            sm.q [warp][i][lane] = qs_base[(size_t)n[i] * HD + lane];
            sm.qn[warp][i][lane] = qn_base[(size_t)n[i] * HD + lane];
        }
        __syncwarp();

        int pxA = grp, pxB = 2 + grp;
        int hrowA = lact ? ((lr + 1 + ldi) * HC + (lc[pxA] + 1 + ldj)) : 0;
        int hrowB = lact ? ((lr + 1 + ldi) * HC + (lc[pxB] + 1 + ldj)) : 0;

        float sp0[4] = {0,0,0,0}, sp1[4] = {0,0,0,0};
        float s9A = 0.f, s9B = 0.f, tlE = 0.f, tlO = 0.f;

#pragma unroll
        for (int c = 0; c < 8; c++) {
            float4 q0 = *reinterpret_cast<const float4*>(&sm.q[warp][0][c * 4]);
            float4 q1 = *reinterpret_cast<const float4*>(&sm.q[warp][1][c * 4]);
            float4 q2 = *reinterpret_cast<const float4*>(&sm.q[warp][2][c * 4]);
            float4 q3 = *reinterpret_cast<const float4*>(&sm.q[warp][3][c * 4]);
            float4 qnE = *reinterpret_cast<const float4*>(&sm.qn[warp][grp][c * 4]);
            float4 qnO = *reinterpret_cast<const float4*>(&sm.qn[warp][2 + grp][c * 4]);
            float4 kA = *reinterpret_cast<const float4*>(&sm.kp[lane * KST + c * 4]);
            float4 kB = *reinterpret_cast<const float4*>(&sm.kp[mi1 * KST + c * 4]);
            float4 k9A = *reinterpret_cast<const float4*>(&sm.k_halo[hrowA * KST + c * 4]);
            float4 k9B = *reinterpret_cast<const float4*>(&sm.k_halo[hrowB * KST + c * 4]);
            float4 l4 = *reinterpret_cast<const float4*>(&sm.lt[lidx * KST + c * 4]);

            DOT4(sp0[0], kA, q0); DOT4(sp0[1], kA, q1);
            DOT4(sp0[2], kA, q2); DOT4(sp0[3], kA, q3);
            DOT4(sp1[0], kB, q0); DOT4(sp1[1], kB, q1);
            DOT4(sp1[2], kB, q2); DOT4(sp1[3], kB, q3);
            float4 qA = grp ? q1 : q0;
            float4 qB = grp ? q3 : q2;
            DOT4(s9A, k9A, qA);
            DOT4(s9B, k9B, qB);
            DOT4(tlE, l4, qnE);
            DOT4(tlO, l4, qnO);
        }

        float pb0[4], pb1[4];
#pragma unroll
        for (int i = 0; i < 4; i++) {
            pb0[i] = g_tab[rpi[n[i] * PLEN + lane] * HEADS + h];
            pb1[i] = (lane < 17) ? g_tab[rpi[n[i] * PLEN + 32 + lane] * HEADS + h] : 0.f;
        }

        bool okA = lact && (pi + ldi >= 0) && (pi + ldi < H0) &&
                   (pj[pxA] + ldj >= 0) && (pj[pxA] + ldj < W0);
        bool okB = lact && (pi + ldi >= 0) && (pi + ldi < H0) &&
                   (pj[pxB] + ldj >= 0) && (pj[pxB] + ldj < W0);
        float s9Af = okA ? s9A + sm.rpb[lidx] : NEGV;
        float s9Bf = okB ? s9B + sm.rpb[lidx] : NEGV;

        float e0[4], e1[4], el[4], inv[4];
#pragma unroll
        for (int i = 0; i < 4; i++) {
            float loc = ((i & 1) == grp) ? (i < 2 ? s9Af : s9Bf) : NEGV;
            float sp0v = sp0[i] + pb0[i];
            float sp1v = (lane < 17) ? sp1[i] + pb1[i] : NEGV;
            float r = fmaxf(sp0v, fmaxf(sp1v, loc));
#pragma unroll
            for (int o = 16; o; o >>= 1) r = fmaxf(r, __shfl_xor_sync(0xffffffffu, r, o));
            e0[i] = expf(sp0v - r);
            e1[i] = (lane < 17) ? expf(sp1v - r) : 0.f;
            el[i] = ((i & 1) == grp && lact) ? expf(loc - r) : 0.f;
            float s = e0[i] + e1[i] + el[i];
#pragma unroll
            for (int o = 16; o; o >>= 1) s += __shfl_xor_sync(0xffffffffu, s, o);
            inv[i] = 1.f / s;
        }

#pragma unroll
        for (int i = 0; i < 4; i++) {
            sm.ap[warp][i][lane] = e0[i] * inv[i];
            if (lane < 17) sm.ap[warp][i][32 + lane] = e1[i] * inv[i];
        }
        if (lact) {
            sm.a9[warp][pxA][lidx] = el[pxA] * inv[pxA] + tlE + sm.lb[lidx];
            sm.a9[warp][pxB][lidx] = el[pxB] * inv[pxB] + tlO + sm.lb[lidx];
        }
        __syncwarp();

        float out[4] = {0.f, 0.f, 0.f, 0.f};
#pragma unroll
        for (int g = 0; g < 12; g++) {
            float4 a0 = *reinterpret_cast<const float4*>(&sm.ap[warp][0][g * 4]);
            float4 a1 = *reinterpret_cast<const float4*>(&sm.ap[warp][1][g * 4]);
            float4 a2 = *reinterpret_cast<const float4*>(&sm.ap[warp][2][g * 4]);
            float4 a3 = *reinterpret_cast<const float4*>(&sm.ap[warp][3][g * 4]);
            float v0 = sm.vp[(g * 4 + 0) * KST + lane];
            float v1 = sm.vp[(g * 4 + 1) * KST + lane];
            float v2 = sm.vp[(g * 4 + 2) * KST + lane];
            float v3 = sm.vp[(g * 4 + 3) * KST + lane];
            out[0] += a0.x * v0 + a0.y * v1 + a0.z * v2 + a0.w * v3;
            out[1] += a1.x * v0 + a1.y * v1 + a1.z * v2 + a1.w * v3;
            out[2] += a2.x * v0 + a2.y * v1 + a2.z * v2 + a2.w * v3;
            out[3] += a3.x * v0 + a3.y * v1 + a3.z * v2 + a3.w * v3;
        }
        {
            float v = sm.vp[48 * KST + lane];
#pragma unroll
            for (int i = 0; i < 4; i++) out[i] += sm.ap[warp][i][48] * v;
        }
        int hb[4];
#pragma unroll
        for (int i = 0; i < 4; i++) hb[i] = (lr + 1) * HC + lc[i] + 1;
#pragma unroll
        for (int l = 0; l < LOCAL; l++) {
            int roff = (l / 3 - 1) * HC + (l % 3 - 1);
#pragma unroll
            for (int i = 0; i < 4; i++) {
                out[i] += sm.a9[warp][i][l] * sm.v_halo[(hb[i] + roff) * KST + lane];
            }
        }

#pragma unroll
        for (int i = 0; i < 4; i++) {
            if (j == 3 && i >= 2) break;
            float o = out[i];
            float nb = __shfl_down_sync(0xffffffffu, o, 1);
            if ((lane & 1) == 0) {
                uint32_t hi, lo;
                split2(o, nb, hi, lo);
                size_t base = ((size_t)(b * N0 + n[i])) * 128 + h * 16 + (lane >> 1);
                g_xoH[base] = hi;
                g_xoL[base] = lo;
            }
        }
        __syncwarp();
    }
}

// ---------------- launch ----------------
extern "C" void kernel_launch(void* const* d_in, const int* in_sizes, int n_in,
                              void* d_out, int out_size)
{
    const float* x      = (const float*)d_in[0];
    const float* sls    = (const float*)d_in[1];
    const float* rct    = (const float*)d_in[2];
    const float* q_w    = (const float*)d_in[3];
    const float* q_b    = (const float*)d_in[4];
    const float* qe     = (const float*)d_in[5];
    const float* temp   = (const float*)d_in[6];
    const float* kv_w   = (const float*)d_in[7];
    const float* kv_b   = (const float*)d_in[8];
    const float* sr_w   = (const float*)d_in[9];
    const float* sr_b   = (const float*)d_in[10];
    const float* norm_g = (const float*)d_in[11];
    const float* norm_b = (const float*)d_in[12];
    const float* fc1_w  = (const float*)d_in[13];
    const float* fc1_b  = (const float*)d_in[14];
    const float* fc2_w  = (const float*)d_in[15];
    const float* fc2_b  = (const float*)d_in[16];
    const float* rpb    = (const float*)d_in[17];
    const float* lt     = (const float*)d_in[18];
    const float* lb     = (const float*)d_in[19];
    const float* proj_w = (const float*)d_in[20];
    const float* proj_b = (const float*)d_in[21];
    const int*   rpi    = (const int*)d_in[22];
    float* out = (float*)d_out;

    cudaFuncSetAttribute(gemm_mma_kernel<0>, cudaFuncAttributeMaxDynamicSharedMemorySize, GEMM_SMEM);
    cudaFuncSetAttribute(gemm_mma_kernel<1>, cudaFuncAttributeMaxDynamicSharedMemorySize, GEMM_SMEM);
    cudaFuncSetAttribute(attn_kernel, cudaFuncAttributeMaxDynamicSharedMemorySize, (int)sizeof(AttnSmem));

    // 1-3) conversions + cpb (gemm1 stays in the profiled 4th slot)
    convert_x_kernel<<<MROWS * DIM / 4 / 256, 256>>>(x);
    convert_w_kernel<<<1280 * 128 / 256, 256>>>(q_w, kv_w, sr_w, proj_w);
    cpb_kernel<<<LTAB / 8, 256>>>(rct, fc1_w, fc1_b, fc2_w, fc2_b);

    // 4) fused GEMM1 (128x64 tiles, 2 CTAs/SM)
    dim3 g1(MROWS / 128, 1024 / 64);
    gemm_mma_kernel<0><<<g1, 256, GEMM_SMEM>>>(q_b, kv_b, sr_b, qe, temp, sls, nullptr);

    // 5) fused pool + LN + kvp
    poolkvp_kernel<<<dim3(B_ * PLEN / 4, 2), 256>>>(norm_g, norm_b, kv_w, kv_b);

    // 6) fused attention (quad-pixel)
    attn_kernel<<<dim3(B_ * HEADS, 28), 256, sizeof(AttnSmem)>>>(rpi, rpb, lt, lb);

    // 7) proj GEMM -> d_out
    dim3 g7(MROWS / 128, 256 / 64);
    gemm_mma_kernel<1><<<g7, 256, GEMM_SMEM>>>(proj_b, nullptr, nullptr, nullptr, nullptr, nullptr, out);
}

// round 8
// speedup vs baseline: 1.7936x; 1.0528x over previous
#include <cuda_runtime.h>
#include <cuda_bf16.h>
#include <math.h>
#include <stdint.h>

// ---------------- problem constants (all static) ----------------
constexpr int B_    = 8;
constexpr int H0    = 56;
constexpr int W0    = 56;
constexpr int N0    = H0 * W0;        // 3136
constexpr int DIM   = 256;
constexpr int HEADS = 8;
constexpr int HD    = 32;
constexpr int LOCAL = 9;
constexpr int PW    = 7;
constexpr int PLEN  = 49;
constexpr int LTAB  = 4096;
constexpr int MROWS = B_ * N0;        // 25088
constexpr float NEGV = -1e9f;

// ---------------- scratch (device globals; no allocs) ----------------
__device__ float g_qs[B_*HEADS*N0*HD];
__device__ float g_qn[B_*HEADS*N0*HD];
__device__ float g_k [B_*HEADS*N0*HD];
__device__ float g_v [B_*HEADS*N0*HD];
__device__ float g_xs[B_*N0*DIM];
__device__ float g_kp[B_*HEADS*PLEN*HD];
__device__ float g_vp[B_*HEADS*PLEN*HD];
__device__ float g_tab[LTAB*HEADS];
__device__ float g_pb[HEADS*N0*52];      // precomputed pool_bias [h][n][m]

// packed bf16 hi/lo operands (u32 = 2 bf16 along k)
__device__ uint32_t g_xH [MROWS*128];
__device__ uint32_t g_xL [MROWS*128];
__device__ uint32_t g_xoH[MROWS*128];
__device__ uint32_t g_xoL[MROWS*128];
__device__ uint32_t g_wH [1280*128];     // fused W [col][k2]: q|k|v|sr|proj
__device__ uint32_t g_wL [1280*128];

// ---------------- helpers ----------------
__device__ __forceinline__ uint32_t pack_bf2(__nv_bfloat16 x, __nv_bfloat16 y) {
    __nv_bfloat162 t; t.x = x; t.y = y;
    return *reinterpret_cast<uint32_t*>(&t);
}
__device__ __forceinline__ void split2(float x, float y, uint32_t& hi, uint32_t& lo) {
    __nv_bfloat16 xh = __float2bfloat16_rn(x);
    __nv_bfloat16 yh = __float2bfloat16_rn(y);
    float xr = x - __bfloat162float(xh);
    float yr = y - __bfloat162float(yh);
    hi = pack_bf2(xh, yh);
    lo = pack_bf2(__float2bfloat16_rn(xr), __float2bfloat16_rn(yr));
}

#define MMA16816(d, a0,a1,a2,a3, b0,b1) \
    asm volatile("mma.sync.aligned.m16n8k16.row.col.f32.bf16.bf16.f32 " \
        "{%0,%1,%2,%3},{%4,%5,%6,%7},{%8,%9},{%0,%1,%2,%3};" \
        : "+f"(d[0]), "+f"(d[1]), "+f"(d[2]), "+f"(d[3]) \
        : "r"(a0), "r"(a1), "r"(a2), "r"(a3), "r"(b0), "r"(b1))

#define LDSM4(r, addr) \
    asm volatile("ldmatrix.sync.aligned.m8n8.x4.shared.b16 {%0,%1,%2,%3}, [%4];" \
        : "=r"((r)[0]), "=r"((r)[1]), "=r"((r)[2]), "=r"((r)[3]) : "r"(addr))

__device__ __forceinline__ void cp16(uint32_t dst, const void* src) {
    asm volatile("cp.async.cg.shared.global [%0], [%1], 16;" :: "r"(dst), "l"(src));
}

#define DOT4(acc, a, b) (acc) += (a).x*(b).x + (a).y*(b).y + (a).z*(b).z + (a).w*(b).w

// ---------------- conversion kernels ----------------
__global__ __launch_bounds__(256)
void convert_x_kernel(const float* __restrict__ x)
{
    int i = blockIdx.x * 256 + threadIdx.x;
    float4 v = reinterpret_cast<const float4*>(x)[i];
    uint32_t h0, l0, h1, l1;
    split2(v.x, v.y, h0, l0);
    split2(v.z, v.w, h1, l1);
    g_xH[i * 2] = h0; g_xH[i * 2 + 1] = h1;
    g_xL[i * 2] = l0; g_xL[i * 2 + 1] = l1;
}

__global__ __launch_bounds__(256)
void convert_w_kernel(const float* __restrict__ q_w, const float* __restrict__ kv_w,
                      const float* __restrict__ sr_w, const float* __restrict__ proj_w)
{
    int idx = blockIdx.x * 256 + threadIdx.x;        // 1280*128
    int c = idx >> 7, k2 = idx & 127;
    float f0, f1;
    if (c < 256)       { f0 = q_w [(2*k2)   * 256 + c];        f1 = q_w [(2*k2+1) * 256 + c];        }
    else if (c < 768)  { f0 = kv_w[(2*k2)   * 512 + c - 256];  f1 = kv_w[(2*k2+1) * 512 + c - 256];  }
    else if (c < 1024) { f0 = sr_w[(2*k2)   * 256 + c - 768];  f1 = sr_w[(2*k2+1) * 256 + c - 768];  }
    else               { f0 = proj_w[(2*k2) * 256 + c - 1024]; f1 = proj_w[(2*k2+1) * 256 + c - 1024]; }
    uint32_t h, l;
    split2(f0, f1, h, l);
    g_wH[idx] = h; g_wL[idx] = l;
}

__global__ void cpb_kernel(const float* __restrict__ rct,
                           const float* __restrict__ w1, const float* __restrict__ b1,
                           const float* __restrict__ w2, const float* __restrict__ b2)
{
    int gw = (blockIdx.x * blockDim.x + threadIdx.x) >> 5;
    int lane = threadIdx.x & 31;
    if (gw >= LTAB) return;
    float r0 = rct[gw * 2], r1 = rct[gw * 2 + 1];
    float acc[HEADS];
#pragma unroll
    for (int h = 0; h < HEADS; h++) acc[h] = 0.f;
    for (int j = lane; j < 512; j += 32) {
        float hv = fmaxf(r0 * w1[j] + r1 * w1[512 + j] + b1[j], 0.f);
#pragma unroll
        for (int h = 0; h < HEADS; h++) acc[h] += hv * w2[j * HEADS + h];
    }
#pragma unroll
    for (int h = 0; h < HEADS; h++)
#pragma unroll
        for (int o = 16; o; o >>= 1) acc[h] += __shfl_xor_sync(0xffffffffu, acc[h], o);
    if (lane == 0) {
#pragma unroll
        for (int h = 0; h < HEADS; h++) g_tab[gw * HEADS + h] = acc[h] + b2[h];
    }
}

// ---------------- pool_bias precompute: pb[h][n][m] = tab[rpi[n*49+m]][h] ----------------
__global__ __launch_bounds__(256)
void pb_kernel(const int* __restrict__ rpi)
{
    int idx = blockIdx.x * 256 + threadIdx.x;
    if (idx >= HEADS * N0 * PLEN) return;
    int m = idx % PLEN;
    int hn = idx / PLEN;
    int h = hn / N0, n = hn % N0;
    g_pb[(size_t)hn * 52 + m] = g_tab[rpi[n * PLEN + m] * HEADS + h];
}

// ---------------- bf16x3 tensor-core GEMM, 128x64 tile, 3-stage pipeline ----------------
constexpr int LDU = 20;
constexpr uint32_t SM_AL = 10240;
constexpr uint32_t SM_BH = 20480;
constexpr uint32_t SM_BL = 25600;
constexpr uint32_t SM_STAGE = 30720;
constexpr int GEMM_SMEM = 92160;         // 3 stages

template<int MODE>
__global__ __launch_bounds__(256, 2)
void gemm_mma_kernel(const float* __restrict__ bq, const float* __restrict__ bkv,
                     const float* __restrict__ bsr,
                     const float* __restrict__ qe, const float* __restrict__ temp,
                     const float* __restrict__ sls,
                     float* __restrict__ Out)
{
    extern __shared__ uint32_t sm_u[];
    uint32_t sbase = (uint32_t)__cvta_generic_to_shared(sm_u);

    const uint32_t* AH = MODE ? g_xoH : g_xH;
    const uint32_t* AL = MODE ? g_xoL : g_xL;

    int tid  = threadIdx.x;
    int lane = tid & 31;
    int warp = tid >> 5;
    int wm   = warp >> 1;
    int wn   = warp & 1;

    int m0    = blockIdx.x * 128;
    int col0  = blockIdx.y * 64;
    int bcol0 = col0 + (MODE ? 1024 : 0);

    int lrowA = tid >> 1;
    int loffA = (tid & 1) * 8;
    uint32_t dstA = (uint32_t)(lrowA * LDU + loffA) * 4;
    int lrowB = tid >> 2;
    int loffB = (tid & 3) * 4;
    uint32_t dstB = (uint32_t)(lrowB * LDU + loffB) * 4;

    const uint32_t* aHp = &AH  [(size_t)(m0 + lrowA)    * 128 + loffA];
    const uint32_t* aLp = &AL  [(size_t)(m0 + lrowA)    * 128 + loffA];
    const uint32_t* bHp = &g_wH[(size_t)(bcol0 + lrowB) * 128 + loffB];
    const uint32_t* bLp = &g_wL[(size_t)(bcol0 + lrowB) * 128 + loffB];

    int aRow  = wm * 32 + (lane & 7) + ((lane >> 3) & 1) * 8;
    int aCol4 = ((lane >> 4) & 1) * 4;
    uint32_t aoff[2][2];
#pragma unroll
    for (int mt = 0; mt < 2; mt++)
#pragma unroll
        for (int s = 0; s < 2; s++)
            aoff[mt][s] = (uint32_t)(((aRow + mt * 16) * LDU) + s * 8 + aCol4) * 4;
    int bRow  = wn * 32 + (lane & 7);
    int bCol4 = ((lane >> 3) & 3) * 4;
    uint32_t boff[4];
#pragma unroll
    for (int nt = 0; nt < 4; nt++)
        boff[nt] = (uint32_t)(((bRow + nt * 8) * LDU) + bCol4) * 4;

    float acc[2][4][4];
#pragma unroll
    for (int i = 0; i < 2; i++)
#pragma unroll
        for (int j = 0; j < 4; j++)
#pragma unroll
            for (int e = 0; e < 4; e++) acc[i][j][e] = 0.f;

#define ISSUE_STAGE(it, buf) do { \
    uint32_t st_ = sbase + (uint32_t)(buf) * SM_STAGE; \
    cp16(st_ + dstA,              aHp + (it) * 16); \
    cp16(st_ + dstA + 16,         aHp + (it) * 16 + 4); \
    cp16(st_ + SM_AL + dstA,      aLp + (it) * 16); \
    cp16(st_ + SM_AL + dstA + 16, aLp + (it) * 16 + 4); \
    cp16(st_ + SM_BH + dstB,      bHp + (it) * 16); \
    cp16(st_ + SM_BL + dstB,      bLp + (it) * 16); \
    asm volatile("cp.async.commit_group;"); \
} while (0)

    ISSUE_STAGE(0, 0);
    ISSUE_STAGE(1, 1);

#pragma unroll
    for (int it = 0; it < 8; it++) {
        if (it < 7) {
            asm volatile("cp.async.wait_group 1;");
        } else {
            asm volatile("cp.async.wait_group 0;");
        }
        __syncthreads();
        {
            uint32_t st = sbase + (uint32_t)(it % 3) * SM_STAGE;
            uint32_t bHf[4][4], bLf[4][4];
#pragma unroll
            for (int nt = 0; nt < 4; nt++) {
                LDSM4(bHf[nt], st + SM_BH + boff[nt]);
                LDSM4(bLf[nt], st + SM_BL + boff[nt]);
            }
#pragma unroll
            for (int s = 0; s < 2; s++) {
                uint32_t aHf[2][4], aLf[2][4];
#pragma unroll
                for (int mt = 0; mt < 2; mt++) {
                    LDSM4(aHf[mt], st + aoff[mt][s]);
                    LDSM4(aLf[mt], st + SM_AL + aoff[mt][s]);
                }
#pragma unroll
                for (int mt = 0; mt < 2; mt++)
#pragma unroll
                    for (int nt = 0; nt < 4; nt++) {
                        MMA16816(acc[mt][nt], aHf[mt][0], aHf[mt][1], aHf[mt][2], aHf[mt][3],
                                 bHf[nt][2*s], bHf[nt][2*s+1]);
                        MMA16816(acc[mt][nt], aHf[mt][0], aHf[mt][1], aHf[mt][2], aHf[mt][3],
                                 bLf[nt][2*s], bLf[nt][2*s+1]);
                        MMA16816(acc[mt][nt], aLf[mt][0], aLf[mt][1], aLf[mt][2], aLf[mt][3],
                                 bHf[nt][2*s], bHf[nt][2*s+1]);
                    }
            }
        }
        if (it < 6) ISSUE_STAGE(it + 2, (it + 2) % 3);
    }
#undef ISSUE_STAGE

    // ---------------- epilogue ----------------
    if (MODE == 1) {
#pragma unroll
        for (int mt = 0; mt < 2; mt++) {
            int r0 = m0 + wm * 32 + mt * 16 + (lane >> 2);
#pragma unroll
            for (int nt = 0; nt < 4; nt++) {
                int c0 = col0 + wn * 32 + nt * 8 + (lane & 3) * 2;
                Out[(size_t)r0 * DIM + c0]           = acc[mt][nt][0] + bq[c0];
                Out[(size_t)r0 * DIM + c0 + 1]       = acc[mt][nt][1] + bq[c0 + 1];
                Out[(size_t)(r0 + 8) * DIM + c0]     = acc[mt][nt][2] + bq[c0];
                Out[(size_t)(r0 + 8) * DIM + c0 + 1] = acc[mt][nt][3] + bq[c0 + 1];
            }
        }
        return;
    }

    int strip = (col0 + wn * 32) >> 5;
#pragma unroll
    for (int mt = 0; mt < 2; mt++)
#pragma unroll
        for (int nt = 0; nt < 4; nt++) {
            int c = col0 + wn * 32 + nt * 8 + (lane & 3) * 2;
            float b0, b1;
            if (c < 256)      { b0 = bq[c];        b1 = bq[c + 1];    }
            else if (c < 768) { b0 = bkv[c - 256]; b1 = bkv[c - 255]; }
            else              { b0 = bsr[c - 768]; b1 = bsr[c - 767]; }
            acc[mt][nt][0] += b0; acc[mt][nt][1] += b1;
            acc[mt][nt][2] += b0; acc[mt][nt][3] += b1;
        }

    if (strip < 16) {
        int h = strip & 7;
        bool isq = strip < 8;
        float spsls = 0.f;
        if (isq) spsls = log1pf(expf(temp[h])) * sls[0];
#pragma unroll
        for (int mt = 0; mt < 2; mt++) {
            float ss0 = 0.f, ss1 = 0.f;
#pragma unroll
            for (int nt = 0; nt < 4; nt++) {
                ss0 += acc[mt][nt][0] * acc[mt][nt][0] + acc[mt][nt][1] * acc[mt][nt][1];
                ss1 += acc[mt][nt][2] * acc[mt][nt][2] + acc[mt][nt][3] * acc[mt][nt][3];
            }
            ss0 += __shfl_xor_sync(0xffffffffu, ss0, 1);
            ss0 += __shfl_xor_sync(0xffffffffu, ss0, 2);
            ss1 += __shfl_xor_sync(0xffffffffu, ss1, 1);
            ss1 += __shfl_xor_sync(0xffffffffu, ss1, 2);
            float inv0 = 1.f / fmaxf(sqrtf(ss0), 1e-12f);
            float inv1 = 1.f / fmaxf(sqrtf(ss1), 1e-12f);
            int r0 = m0 + wm * 32 + mt * 16 + (lane >> 2);
            int b0i = r0 / N0, n0i = r0 % N0;
            int b1i = (r0 + 8) / N0, n1i = (r0 + 8) % N0;
            size_t base0 = (((size_t)(b0i * HEADS + h)) * N0 + n0i) * HD;
            size_t base1 = (((size_t)(b1i * HEADS + h)) * N0 + n1i) * HD;
#pragma unroll
            for (int nt = 0; nt < 4; nt++) {
                int d0 = (wn * 32 + nt * 8 + (lane & 3) * 2) & 31;
#pragma unroll
                for (int p = 0; p < 2; p++) {
                    int d = d0 + p;
                    float v0 = acc[mt][nt][p]     * inv0;
                    float v1 = acc[mt][nt][2 + p] * inv1;
                    if (isq) {
                        float e = qe[h * HD + d];
                        g_qn[base0 + d] = v0;
                        g_qn[base1 + d] = v1;
                        g_qs[base0 + d] = (v0 + e) * spsls;
                        g_qs[base1 + d] = (v1 + e) * spsls;
                    } else {
                        g_k[base0 + d] = v0;
                        g_k[base1 + d] = v1;
                    }
                }
            }
        }
    } else if (strip < 24) {
        int h = strip & 7;
#pragma unroll
        for (int mt = 0; mt < 2; mt++) {
            int r0 = m0 + wm * 32 + mt * 16 + (lane >> 2);
            int ba = r0 / N0, na = r0 % N0;
            int bb = (r0 + 8) / N0, nb = (r0 + 8) % N0;
            size_t base0 = (((size_t)(ba * HEADS + h)) * N0 + na) * HD;
            size_t base1 = (((size_t)(bb * HEADS + h)) * N0 + nb) * HD;
#pragma unroll
            for (int nt = 0; nt < 4; nt++) {
                int d = (wn * 32 + nt * 8 + (lane & 3) * 2) & 31;
                g_v[base0 + d]     = acc[mt][nt][0];
                g_v[base0 + d + 1] = acc[mt][nt][1];
                g_v[base1 + d]     = acc[mt][nt][2];
                g_v[base1 + d + 1] = acc[mt][nt][3];
            }
        }
    } else {
#pragma unroll
        for (int mt = 0; mt < 2; mt++) {
            int r0 = m0 + wm * 32 + mt * 16 + (lane >> 2);
            int ba = r0 / N0, na = r0 % N0;
            int bb = (r0 + 8) / N0, nb = (r0 + 8) % N0;
#pragma unroll
            for (int nt = 0; nt < 4; nt++) {
                int cc = (wn * 32 + nt * 8 + (lane & 3) * 2) + col0 - 768;
#pragma unroll
                for (int p = 0; p < 2; p++) {
                    float v0 = acc[mt][nt][p];
                    float v1 = acc[mt][nt][2 + p];
                    g_xs[((size_t)(ba * N0 + na)) * DIM + cc + p] =
                        0.5f * v0 * (1.f + erff(v0 * 0.70710678118654752f));
                    g_xs[((size_t)(bb * N0 + nb)) * DIM + cc + p] =
                        0.5f * v1 * (1.f + erff(v1 * 0.70710678118654752f));
                }
            }
        }
    }
}

// ---------------- fused pool + LN + kvp ----------------
__global__ __launch_bounds__(256)
void poolkvp_kernel(const float* __restrict__ gamma, const float* __restrict__ beta,
                    const float* __restrict__ kv_w, const float* __restrict__ kv_b)
{
    __shared__ float xr[4][DIM];
    __shared__ float redm[4][8], redv[4][8];
    int bp0 = blockIdx.x * 4;
    int half = blockIdx.y;
    int tid = threadIdx.x, lane = tid & 31, wp = tid >> 5;

    float sv[4];
#pragma unroll
    for (int i = 0; i < 4; i++) {
        int bp = bp0 + i, b = bp / PLEN, p = bp % PLEN;
        int pi = p / PW, pj = p % PW;
        float s = 0.f;
#pragma unroll
        for (int r = 0; r < 8; r++)
#pragma unroll
            for (int c = 0; c < 8; c++)
                s += g_xs[((size_t)(b * N0 + (pi * 8 + r) * W0 + pj * 8 + c)) * DIM + tid];
        sv[i] = s * (1.f / 64.f);
    }
#pragma unroll
    for (int i = 0; i < 4; i++) {
        float m = sv[i];
#pragma unroll
        for (int o = 16; o; o >>= 1) m += __shfl_xor_sync(0xffffffffu, m, o);
        if (lane == 0) redm[i][wp] = m;
    }
    __syncthreads();
    float dv[4];
#pragma unroll
    for (int i = 0; i < 4; i++) {
        float mean = 0.f;
#pragma unroll
        for (int w = 0; w < 8; w++) mean += redm[i][w];
        mean *= (1.f / 256.f);
        dv[i] = sv[i] - mean;
        float v2 = dv[i] * dv[i];
#pragma unroll
        for (int o = 16; o; o >>= 1) v2 += __shfl_xor_sync(0xffffffffu, v2, o);
        if (lane == 0) redv[i][wp] = v2;
    }
    __syncthreads();
#pragma unroll
    for (int i = 0; i < 4; i++) {
        float var = 0.f;
#pragma unroll
        for (int w = 0; w < 8; w++) var += redv[i][w];
        var *= (1.f / 256.f);
        xr[i][tid] = dv[i] * rsqrtf(var + 1e-5f) * gamma[tid] + beta[tid];
    }
    __syncthreads();

    int yoff = half * 256;
    float bb = kv_b[yoff + tid];
    float acc[4];
#pragma unroll
    for (int i = 0; i < 4; i++) acc[i] = bb;

#pragma unroll 8
    for (int kk = 0; kk < DIM; kk++) {
        float w = kv_w[(size_t)kk * 512 + yoff + tid];
#pragma unroll
        for (int i = 0; i < 4; i++) acc[i] = fmaf(xr[i][kk], w, acc[i]);
    }

#pragma unroll
    for (int i = 0; i < 4; i++) {
        int bp = bp0 + i;
        int b = bp / PLEN, p = bp % PLEN;
        size_t dst = (((size_t)(b * HEADS + wp)) * PLEN + p) * HD + lane;
        if (half == 0) {
            float ss = acc[i] * acc[i];
#pragma unroll
            for (int o = 16; o; o >>= 1) ss += __shfl_xor_sync(0xffffffffu, ss, o);
            g_kp[dst] = acc[i] / fmaxf(sqrtf(ss), 1e-12f);
        } else {
            g_vp[dst] = acc[i];
        }
    }
}

// ---------------- fused attention: quad-pixel, tiled halo ----------------
constexpr int TR = 4, TC = 28, HR = 6, HC = 30;
constexpr int KST = 36;
constexpr int QST = 36;

struct AttnSmem {
    float k_halo[HR * HC * KST];
    float v_halo[HR * HC * KST];
    float kp[PLEN * KST];
    float vp[PLEN * KST];
    float lt[LOCAL * KST];
    float q  [8][4][QST];
    float qn [8][4][QST];
    float a9 [8][4][12];
    float ap [8][4][52];
    float rpb[LOCAL];
    float lb [LOCAL];
};

__global__ __launch_bounds__(256)
void attn_kernel(const float* __restrict__ rpb_local,
                 const float* __restrict__ ltok,
                 const float* __restrict__ lbias)
{
    extern __shared__ char smem_raw[];
    AttnSmem& sm = *reinterpret_cast<AttnSmem*>(smem_raw);

    int bh = blockIdx.x;
    int b = bh / HEADS, h = bh % HEADS;
    int ty = blockIdx.y;
    int tr0 = (ty % 14) * TR;
    int tc0 = (ty / 14) * TC;
    int tid = threadIdx.x, warp = tid >> 5, lane = tid & 31;

    const float* k_base = g_k + (size_t)bh * N0 * HD;
    const float* v_base = g_v + (size_t)bh * N0 * HD;

    for (int f = tid; f < HR * HC * 16; f += 256) {
        int row = f >> 4;
        int rem = f & 15;
        int mat = rem >> 3;
        int c4  = rem & 7;
        int hr = row / HC, hc = row % HC;
        int gr = tr0 - 1 + hr, gc = tc0 - 1 + hc;
        bool ok = (gr >= 0 && gr < H0 && gc >= 0 && gc < W0);
        float4 val = make_float4(0.f, 0.f, 0.f, 0.f);
        if (ok) {
            const float* src = mat ? v_base : k_base;
            val = *reinterpret_cast<const float4*>(&src[(size_t)(gr * W0 + gc) * HD + c4 * 4]);
        }
        float* dst = mat ? sm.v_halo : sm.k_halo;
        *reinterpret_cast<float4*>(&dst[row * KST + c4 * 4]) = val;
    }
    {
        const float* kpsrc = g_kp + (size_t)bh * PLEN * HD;
        const float* vpsrc = g_vp + (size_t)bh * PLEN * HD;
        for (int f = tid; f < PLEN * 16; f += 256) {
            int m = f >> 4, rem = f & 15, mat = rem >> 3, c4 = rem & 7;
            const float* src = mat ? vpsrc : kpsrc;
            float4 val = *reinterpret_cast<const float4*>(&src[(size_t)m * HD + c4 * 4]);
            float* dst = mat ? sm.vp : sm.kp;
            *reinterpret_cast<float4*>(&dst[m * KST + c4 * 4]) = val;
        }
    }
    for (int i = tid; i < HD * LOCAL; i += 256) {
        int d = i / LOCAL, l = i % LOCAL;
        sm.lt[l * KST + d] = ltok[h * HD * LOCAL + i];
    }
    if (tid < LOCAL) {
        sm.rpb[tid] = rpb_local[h * LOCAL + tid];
        sm.lb[tid]  = lbias[h * LOCAL + tid];
    }
    __syncthreads();

    const float* qs_base = g_qs + (size_t)bh * N0 * HD;
    const float* qn_base = g_qn + (size_t)bh * N0 * HD;
    const float* pb_base = g_pb + (size_t)h * N0 * 52;

    int lr = warp & 3;
    int colbase = (warp >> 2) * 14;
    int pi = tr0 + lr;

    int grp  = lane >> 4;
    int ll   = lane & 15;
    bool lact = ll < LOCAL;
    int lidx = lact ? ll : 0;
    int ldi = lidx / 3 - 1, ldj = lidx % 3 - 1;
    int mi1 = (lane < 17) ? lane + 32 : 0;

    for (int j = 0; j < 4; j++) {
        int lc[4];
#pragma unroll
        for (int i = 0; i < 4; i++) lc[i] = colbase + j * 4 + i;
        if (j == 3) { lc[2] = lc[0]; lc[3] = lc[1]; }
        int n[4], pj[4];
#pragma unroll
        for (int i = 0; i < 4; i++) { pj[i] = tc0 + lc[i]; n[i] = pi * W0 + pj[i]; }

#pragma unroll
        for (int i = 0; i < 4; i++) {
            sm.q [warp][i][lane] = qs_base[(size_t)n[i] * HD + lane];
            sm.qn[warp][i][lane] = qn_base[(size_t)n[i] * HD + lane];
        }
        __syncwarp();

        int pxA = grp, pxB = 2 + grp;
        int hrowA = lact ? ((lr + 1 + ldi) * HC + (lc[pxA] + 1 + ldj)) : 0;
        int hrowB = lact ? ((lr + 1 + ldi) * HC + (lc[pxB] + 1 + ldj)) : 0;

        float sp0[4] = {0,0,0,0}, sp1[4] = {0,0,0,0};
        float s9A = 0.f, s9B = 0.f, tlE = 0.f, tlO = 0.f;

#pragma unroll
        for (int c = 0; c < 8; c++) {
            float4 q0 = *reinterpret_cast<const float4*>(&sm.q[warp][0][c * 4]);
            float4 q1 = *reinterpret_cast<const float4*>(&sm.q[warp][1][c * 4]);
            float4 q2 = *reinterpret_cast<const float4*>(&sm.q[warp][2][c * 4]);
            float4 q3 = *reinterpret_cast<const float4*>(&sm.q[warp][3][c * 4]);
            float4 qnE = *reinterpret_cast<const float4*>(&sm.qn[warp][grp][c * 4]);
            float4 qnO = *reinterpret_cast<const float4*>(&sm.qn[warp][2 + grp][c * 4]);
            float4 kA = *reinterpret_cast<const float4*>(&sm.kp[lane * KST + c * 4]);
            float4 kB = *reinterpret_cast<const float4*>(&sm.kp[mi1 * KST + c * 4]);
            float4 k9A = *reinterpret_cast<const float4*>(&sm.k_halo[hrowA * KST + c * 4]);
            float4 k9B = *reinterpret_cast<const float4*>(&sm.k_halo[hrowB * KST + c * 4]);
            float4 l4 = *reinterpret_cast<const float4*>(&sm.lt[lidx * KST + c * 4]);

            DOT4(sp0[0], kA, q0); DOT4(sp0[1], kA, q1);
            DOT4(sp0[2], kA, q2); DOT4(sp0[3], kA, q3);
            DOT4(sp1[0], kB, q0); DOT4(sp1[1], kB, q1);
            DOT4(sp1[2], kB, q2); DOT4(sp1[3], kB, q3);
            float4 qA = grp ? q1 : q0;
            float4 qB = grp ? q3 : q2;
            DOT4(s9A, k9A, qA);
            DOT4(s9B, k9B, qB);
            DOT4(tlE, l4, qnE);
            DOT4(tlO, l4, qnO);
        }

        float pb0[4], pb1[4];
#pragma unroll
        for (int i = 0; i < 4; i++) {
            const float* pbp = &pb_base[(size_t)n[i] * 52];
            pb0[i] = pbp[lane];
            pb1[i] = (lane < 17) ? pbp[32 + lane] : 0.f;
        }

        bool okA = lact && (pi + ldi >= 0) && (pi + ldi < H0) &&
                   (pj[pxA] + ldj >= 0) && (pj[pxA] + ldj < W0);
        bool okB = lact && (pi + ldi >= 0) && (pi + ldi < H0) &&
                   (pj[pxB] + ldj >= 0) && (pj[pxB] + ldj < W0);
        float s9Af = okA ? s9A + sm.rpb[lidx] : NEGV;
        float s9Bf = okB ? s9B + sm.rpb[lidx] : NEGV;

        float e0[4], e1[4], el[4], inv[4];
#pragma unroll
        for (int i = 0; i < 4; i++) {
            float loc = ((i & 1) == grp) ? (i < 2 ? s9Af : s9Bf) : NEGV;
            float sp0v = sp0[i] + pb0[i];
            float sp1v = (lane < 17) ? sp1[i] + pb1[i] : NEGV;
            float r = fmaxf(sp0v, fmaxf(sp1v, loc));
#pragma unroll
            for (int o = 16; o; o >>= 1) r = fmaxf(r, __shfl_xor_sync(0xffffffffu, r, o));
            e0[i] = expf(sp0v - r);
            e1[i] = (lane < 17) ? expf(sp1v - r) : 0.f;
            el[i] = ((i & 1) == grp && lact) ? expf(loc - r) : 0.f;
            float s = e0[i] + e1[i] + el[i];
#pragma unroll
            for (int o = 16; o; o >>= 1) s += __shfl_xor_sync(0xffffffffu, s, o);
            inv[i] = 1.f / s;
        }

#pragma unroll
        for (int i = 0; i < 4; i++) {
            sm.ap[warp][i][lane] = e0[i] * inv[i];
            if (lane < 17) sm.ap[warp][i][32 + lane] = e1[i] * inv[i];
        }
        if (lact) {
            sm.a9[warp][pxA][lidx] = el[pxA] * inv[pxA] + tlE + sm.lb[lidx];
            sm.a9[warp][pxB][lidx] = el[pxB] * inv[pxB] + tlO + sm.lb[lidx];
        }
        __syncwarp();

        float out[4] = {0.f, 0.f, 0.f, 0.f};
#pragma unroll
        for (int g = 0; g < 12; g++) {
            float4 a0 = *reinterpret_cast<const float4*>(&sm.ap[warp][0][g * 4]);
            float4 a1 = *reinterpret_cast<const float4*>(&sm.ap[warp][1][g * 4]);
            float4 a2 = *reinterpret_cast<const float4*>(&sm.ap[warp][2][g * 4]);
            float4 a3 = *reinterpret_cast<const float4*>(&sm.ap[warp][3][g * 4]);
            float v0 = sm.vp[(g * 4 + 0) * KST + lane];
            float v1 = sm.vp[(g * 4 + 1) * KST + lane];
            float v2 = sm.vp[(g * 4 + 2) * KST + lane];
            float v3 = sm.vp[(g * 4 + 3) * KST + lane];
            out[0] += a0.x * v0 + a0.y * v1 + a0.z * v2 + a0.w * v3;
            out[1] += a1.x * v0 + a1.y * v1 + a1.z * v2 + a1.w * v3;
            out[2] += a2.x * v0 + a2.y * v1 + a2.z * v2 + a2.w * v3;
            out[3] += a3.x * v0 + a3.y * v1 + a3.z * v2 + a3.w * v3;
        }
        {
            float v = sm.vp[48 * KST + lane];
#pragma unroll
            for (int i = 0; i < 4; i++) out[i] += sm.ap[warp][i][48] * v;
        }
        int hb[4];
#pragma unroll
        for (int i = 0; i < 4; i++) hb[i] = (lr + 1) * HC + lc[i] + 1;
#pragma unroll
        for (int l = 0; l < LOCAL; l++) {
            int roff = (l / 3 - 1) * HC + (l % 3 - 1);
#pragma unroll
            for (int i = 0; i < 4; i++) {
                out[i] += sm.a9[warp][i][l] * sm.v_halo[(hb[i] + roff) * KST + lane];
            }
        }

#pragma unroll
        for (int i = 0; i < 4; i++) {
            if (j == 3 && i >= 2) break;
            float o = out[i];
            float nb = __shfl_down_sync(0xffffffffu, o, 1);
            if ((lane & 1) == 0) {
                uint32_t hi, lo;
                split2(o, nb, hi, lo);
                size_t base = ((size_t)(b * N0 + n[i])) * 128 + h * 16 + (lane >> 1);
                g_xoH[base] = hi;
                g_xoL[base] = lo;
            }
        }
        __syncwarp();
    }
}

// ---------------- launch ----------------
extern "C" void kernel_launch(void* const* d_in, const int* in_sizes, int n_in,
                              void* d_out, int out_size)
{
    const float* x      = (const float*)d_in[0];
    const float* sls    = (const float*)d_in[1];
    const float* rct    = (const float*)d_in[2];
    const float* q_w    = (const float*)d_in[3];
    const float* q_b    = (const float*)d_in[4];
    const float* qe     = (const float*)d_in[5];
    const float* temp   = (const float*)d_in[6];
    const float* kv_w   = (const float*)d_in[7];
    const float* kv_b   = (const float*)d_in[8];
    const float* sr_w   = (const float*)d_in[9];
    const float* sr_b   = (const float*)d_in[10];
    const float* norm_g = (const float*)d_in[11];
    const float* norm_b = (const float*)d_in[12];
    const float* fc1_w  = (const float*)d_in[13];
    const float* fc1_b  = (const float*)d_in[14];
    const float* fc2_w  = (const float*)d_in[15];
    const float* fc2_b  = (const float*)d_in[16];
    const float* rpb    = (const float*)d_in[17];
    const float* lt     = (const float*)d_in[18];
    const float* lb     = (const float*)d_in[19];
    const float* proj_w = (const float*)d_in[20];
    const float* proj_b = (const float*)d_in[21];
    const int*   rpi    = (const int*)d_in[22];
    float* out = (float*)d_out;

    cudaFuncSetAttribute(gemm_mma_kernel<0>, cudaFuncAttributeMaxDynamicSharedMemorySize, GEMM_SMEM);
    cudaFuncSetAttribute(gemm_mma_kernel<1>, cudaFuncAttributeMaxDynamicSharedMemorySize, GEMM_SMEM);
    cudaFuncSetAttribute(attn_kernel, cudaFuncAttributeMaxDynamicSharedMemorySize, (int)sizeof(AttnSmem));

    // 1-3) conversions + cpb (gemm1 stays in the profiled 4th slot)
    convert_x_kernel<<<MROWS * DIM / 4 / 256, 256>>>(x);
    convert_w_kernel<<<1280 * 128 / 256, 256>>>(q_w, kv_w, sr_w, proj_w);
    cpb_kernel<<<LTAB / 8, 256>>>(rct, fc1_w, fc1_b, fc2_w, fc2_b);

    // 4) fused GEMM1 (3-stage pipeline, 1 barrier/iter)
    dim3 g1(MROWS / 128, 1024 / 64);
    gemm_mma_kernel<0><<<g1, 256, GEMM_SMEM>>>(q_b, kv_b, sr_b, qe, temp, sls, nullptr);

    // 5) pool_bias precompute
    pb_kernel<<<(HEADS * N0 * PLEN + 255) / 256, 256>>>(rpi);

    // 6) fused pool + LN + kvp
    poolkvp_kernel<<<dim3(B_ * PLEN / 4, 2), 256>>>(norm_g, norm_b, kv_w, kv_b);

    // 7) fused attention (quad-pixel, precomputed pb)
    attn_kernel<<<dim3(B_ * HEADS, 28), 256, sizeof(AttnSmem)>>>(rpb, lt, lb);

    // 8) proj GEMM -> d_out
    dim3 g7(MROWS / 128, 256 / 64);
    gemm_mma_kernel<1><<<g7, 256, GEMM_SMEM>>>(proj_b, nullptr, nullptr, nullptr, nullptr, nullptr, out);
}